// round 1
// baseline (speedup 1.0000x reference)
#include <cuda_runtime.h>
#include <math.h>

// Problem constants
#define BQ 32          // query batch
#define NSUP 25        // support images
#define KCLS 5         // classes
#define CIN 512        // input channels
#define PPIX 196       // 14*14 pixels
#define DDIM 128       // dk = dv
#define KEYS 980       // keys per class (5 supports * 196)
#define OUT1 (BQ * KCLS * DDIM * PPIX)   // prototypes size = 4,014,080

// Scratch (device globals — no allocation allowed)
__device__ float g_q[BQ * DDIM * PPIX];     // [b][d][p]
__device__ float g_k[NSUP * DDIM * PPIX];   // [n][d][p]
__device__ float g_v[NSUP * PPIX * DDIM];   // [key][d]  (key = n*196+pix)

// ---------------------------------------------------------------------------
// Projection kernel: per image, q[d,p] = sum_c W_qk[d,c] x[c,p]; same for v.
// block = 128 threads (one per d). grid = (7 pixel-tiles of 28, nimg).
// mode 1 (query): q -> g_q [img][d][p], v -> out region2 [img][d][p]
// mode 0 (supp):  q -> g_k [img][d][p], v -> g_v [key][d]
// ---------------------------------------------------------------------------
__global__ __launch_bounds__(128) void proj_kernel(
    const float* __restrict__ x, const float* __restrict__ Wq,
    const float* __restrict__ Wv, float* __restrict__ outv_ext, int mode)
{
    __shared__ float Wqs[32][129];
    __shared__ float Wvs[32][129];
    __shared__ float xs[32][28];

    const int tid = threadIdx.x;        // = d
    const int img = blockIdx.y;
    const int p0 = blockIdx.x * 28;

    float accq[28], accv[28];
#pragma unroll
    for (int i = 0; i < 28; i++) { accq[i] = 0.f; accv[i] = 0.f; }

    for (int c0 = 0; c0 < CIN; c0 += 32) {
        __syncthreads();
        // stage W chunks transposed: Ws[c][d]
        for (int idx = tid; idx < 32 * 128; idx += 128) {
            int d = idx >> 5, c = idx & 31;
            Wqs[c][d] = Wq[d * CIN + c0 + c];
            Wvs[c][d] = Wv[d * CIN + c0 + c];
        }
        // stage x chunk: xs[c][i]
        for (int idx = tid; idx < 32 * 28; idx += 128) {
            int c = idx / 28, i = idx - c * 28;
            xs[c][i] = x[img * (CIN * PPIX) + (c0 + c) * PPIX + p0 + i];
        }
        __syncthreads();
#pragma unroll 4
        for (int c = 0; c < 32; c++) {
            float wq = Wqs[c][tid];
            float wv = Wvs[c][tid];
#pragma unroll
            for (int i = 0; i < 28; i++) {
                float xi = xs[c][i];
                accq[i] = fmaf(xi, wq, accq[i]);
                accv[i] = fmaf(xi, wv, accv[i]);
            }
        }
    }

    if (mode == 1) {
        float* oq = g_q + img * (DDIM * PPIX) + tid * PPIX + p0;
        float* ov = outv_ext + img * (DDIM * PPIX) + tid * PPIX + p0;
#pragma unroll
        for (int i = 0; i < 28; i++) { oq[i] = accq[i]; ov[i] = accv[i]; }
    } else {
        float* oq = g_k + img * (DDIM * PPIX) + tid * PPIX + p0;
#pragma unroll
        for (int i = 0; i < 28; i++) oq[i] = accq[i];
#pragma unroll
        for (int i = 0; i < 28; i++)
            g_v[(img * PPIX + p0 + i) * DDIM + tid] = accv[i];
    }
}

// ---------------------------------------------------------------------------
// Fused attention kernel.
// grid = (2 m-tiles of 98, 5 classes, 32 batch). block = 256.
// For each of 20 chunks of 49 keys:
//   S[98x49] = Q . K^T  (register-tiled 8x4, operands transposed in smem)
//   E = exp(S)  (no max subtraction: |s| <~ 15, fp32-safe; mathematically
//                identical to reference softmax)
//   denom[m] += row sums;  U[m,d] += E . V  (V in registers, E broadcast LDS)
// Final: out = U / denom, written to prototypes [b][k][d*196+m].
// ---------------------------------------------------------------------------
#define MT 98
#define MTP 104
#define NC 49
#define NCP 52
#define ATT_SMEM_FLOATS (128 * MTP + 128 * NCP + MTP * NCP + MTP)

__global__ __launch_bounds__(256, 2) void attn_kernel(float* __restrict__ out)
{
    extern __shared__ float sm[];
    float* Qs = sm;                         // [128][104]  Qs[d][mi]
    float* Ks = Qs + 128 * MTP;             // [128][52]   Ks[d][j]
    float* Es = Ks + 128 * NCP;             // [104][52]   Es[m][j]
    float* dsum = Es + MTP * NCP;           // [104]

    const int tid = threadIdx.x;
    const int mt = blockIdx.x, kc = blockIdx.y, b = blockIdx.z;
    const int m_base = mt * MT;

    // load Q tile transposed, zero-pad m >= 98
    {
        const float* qimg = g_q + b * (DDIM * PPIX);
        for (int idx = tid; idx < 128 * MTP; idx += 256) {
            int d = idx / MTP, mi = idx - d * MTP;
            Qs[idx] = (mi < MT) ? qimg[d * PPIX + m_base + mi] : 0.f;
        }
    }
    if (tid < MTP) dsum[tid] = 0.f;

    float U[49];
#pragma unroll
    for (int i = 0; i < 49; i++) U[i] = 0.f;

    const int dcol = tid & 127;
    const int mh = tid >> 7;                // 0: rows 0..48, 1: rows 49..97
    const float* vclass = g_v + (kc * KEYS) * DDIM + dcol;

    const int ty = tid / 13;                // S-phase thread grid 13x13 (tid<169)
    const int tx = tid - ty * 13;
    const int m0 = ty * 8;
    const int j0 = tx * 4;

    __syncthreads();

    for (int ch = 0; ch < 20; ch++) {
        const int key0 = kc * KEYS + ch * NC;
        // stage K chunk transposed, zero-pad j >= 49
        for (int idx = tid; idx < 128 * NCP; idx += 256) {
            int d = idx / NCP, j = idx - d * NCP;
            float val = 0.f;
            if (j < NC) {
                int kg = key0 + j;
                int n = kg / PPIX, pix = kg - n * PPIX;
                val = g_k[n * (DDIM * PPIX) + d * PPIX + pix];
            }
            Ks[idx] = val;
        }
        __syncthreads();

        // S = Q.K^T (8m x 4j per thread) -> E = exp(S)
        if (tid < 169) {
            float acc[8][4];
#pragma unroll
            for (int i = 0; i < 8; i++)
#pragma unroll
                for (int jj = 0; jj < 4; jj++) acc[i][jj] = 0.f;

            for (int d = 0; d < 128; d++) {
                const float4 a0 = *(const float4*)(Qs + d * MTP + m0);
                const float4 a1 = *(const float4*)(Qs + d * MTP + m0 + 4);
                const float4 b0 = *(const float4*)(Ks + d * NCP + j0);
                float am[8] = {a0.x, a0.y, a0.z, a0.w, a1.x, a1.y, a1.z, a1.w};
                float bn[4] = {b0.x, b0.y, b0.z, b0.w};
#pragma unroll
                for (int i = 0; i < 8; i++)
#pragma unroll
                    for (int jj = 0; jj < 4; jj++)
                        acc[i][jj] = fmaf(am[i], bn[jj], acc[i][jj]);
            }
#pragma unroll
            for (int i = 0; i < 8; i++)
#pragma unroll
                for (int jj = 0; jj < 4; jj++)
                    Es[(m0 + i) * NCP + j0 + jj] = __expf(acc[i][jj]);
        }
        __syncthreads();

        // per-row denominators
        if (tid < MT) {
            float s = 0.f;
            for (int j = 0; j < NC; j++) s += Es[tid * NCP + j];
            dsum[tid] += s;
        }

        // U[m, dcol] += sum_j E[m,j] * V[j, dcol]
        {
            const float* vb = vclass + ch * NC * DDIM;
            const float* erow = Es + (mh * 49) * NCP;
            for (int js = 0; js < 48; js += 8) {
                float vr[8];
#pragma unroll
                for (int jj = 0; jj < 8; jj++) vr[jj] = vb[(js + jj) * DDIM];
#pragma unroll
                for (int mm = 0; mm < 49; mm++) {
                    const float* e = erow + mm * NCP + js;
                    const float4 e0 = *(const float4*)e;
                    const float4 e1 = *(const float4*)(e + 4);
                    float u = U[mm];
                    u = fmaf(e0.x, vr[0], u);
                    u = fmaf(e0.y, vr[1], u);
                    u = fmaf(e0.z, vr[2], u);
                    u = fmaf(e0.w, vr[3], u);
                    u = fmaf(e1.x, vr[4], u);
                    u = fmaf(e1.y, vr[5], u);
                    u = fmaf(e1.z, vr[6], u);
                    u = fmaf(e1.w, vr[7], u);
                    U[mm] = u;
                }
            }
            float v48 = vb[48 * DDIM];
#pragma unroll
            for (int mm = 0; mm < 49; mm++)
                U[mm] = fmaf(erow[mm * NCP + 48], v48, U[mm]);
        }
        __syncthreads();
    }

    // normalize + write prototypes: out[b][k][dcol*196 + m_base + m]
    float* orow = out + ((b * KCLS + kc) * DDIM + dcol) * PPIX + m_base + mh * 49;
#pragma unroll
    for (int mm = 0; mm < 49; mm++)
        orow[mm] = U[mm] / dsum[mh * 49 + mm];
}

// ---------------------------------------------------------------------------
// kernel_launch
// inputs: 0 support_features [25,512,14,14], 1 query_features [32,512,14,14],
//         2 support_labels (sorted repeat pattern — unused), 3 W_qk [128,512],
//         4 W_v [128,512]
// output: prototypes [32,5,25088] then query_v [32,1,25088]
// ---------------------------------------------------------------------------
extern "C" void kernel_launch(void* const* d_in, const int* in_sizes, int n_in,
                              void* d_out, int out_size)
{
    const float* supp = (const float*)d_in[0];
    const float* qry  = (const float*)d_in[1];
    const float* Wqk  = (const float*)d_in[3];
    const float* Wv   = (const float*)d_in[4];
    float* out = (float*)d_out;

    const int att_smem = ATT_SMEM_FLOATS * (int)sizeof(float);
    cudaFuncSetAttribute(attn_kernel,
                         cudaFuncAttributeMaxDynamicSharedMemorySize, att_smem);

    // support projections: k -> g_k, v -> g_v
    proj_kernel<<<dim3(7, NSUP), 128>>>(supp, Wqk, Wv, nullptr, 0);
    // query projections: q -> g_q, v -> out region 2 directly
    proj_kernel<<<dim3(7, BQ), 128>>>(qry, Wqk, Wv, out + OUT1, 1);
    // fused attention -> prototypes
    attn_kernel<<<dim3(2, KCLS, BQ), 256, att_smem>>>(out);
}

// round 2
// speedup vs baseline: 1.0958x; 1.0958x over previous
#include <cuda_runtime.h>
#include <math.h>

// Problem constants
#define BQ 32          // query batch
#define NSUP 25        // support images
#define KCLS 5         // classes
#define CIN 512        // input channels
#define PPIX 196       // 14*14 pixels
#define DDIM 128       // dk = dv
#define KEYS 980       // keys per class (5 supports * 196)
#define OUT1 (BQ * KCLS * DDIM * PPIX)   // prototypes size = 4,014,080

// Scratch (device globals — no allocation allowed)
__device__ float g_q[BQ * DDIM * PPIX];     // [b][d][p]
__device__ float g_k[NSUP * DDIM * PPIX];   // [n][d][p]
__device__ float g_v[NSUP * PPIX * DDIM];   // [key][d]  (key = n*196+pix)

// ---------------------------------------------------------------------------
// Projection kernel (merged supports+queries).
// grid = (7 pixel-tiles of 28, 57 images). block = 256 = 128 d x 2 halves.
// Each thread: one d, 14 pixels, both q and v accumulators.
// img < 25: support (q->g_k, v->g_v transposed); else query (q->g_q, v->out).
// ---------------------------------------------------------------------------
__global__ __launch_bounds__(256) void proj_kernel(
    const float* __restrict__ supp, const float* __restrict__ qry,
    const float* __restrict__ Wq, const float* __restrict__ Wv,
    float* __restrict__ outv_ext)
{
    __shared__ float Wqs[32][129];
    __shared__ float Wvs[32][129];
    __shared__ float xs[32][28];

    const int tid = threadIdx.x;
    const int d = tid & 127;
    const int half = tid >> 7;
    const int img = blockIdx.y;
    const bool is_supp = img < NSUP;
    const float* x = is_supp ? supp + img * (CIN * PPIX)
                             : qry + (img - NSUP) * (CIN * PPIX);
    const int p0 = blockIdx.x * 28;
    const int pp = p0 + half * 14;

    float accq[14], accv[14];
#pragma unroll
    for (int i = 0; i < 14; i++) { accq[i] = 0.f; accv[i] = 0.f; }

    for (int c0 = 0; c0 < CIN; c0 += 32) {
        __syncthreads();
        for (int idx = tid; idx < 32 * 128; idx += 256) {
            int dd = idx >> 5, c = idx & 31;
            Wqs[c][dd] = Wq[dd * CIN + c0 + c];
            Wvs[c][dd] = Wv[dd * CIN + c0 + c];
        }
        for (int idx = tid; idx < 32 * 28; idx += 256) {
            int c = idx / 28, i = idx - c * 28;
            xs[c][i] = x[(c0 + c) * PPIX + p0 + i];
        }
        __syncthreads();
#pragma unroll 8
        for (int c = 0; c < 32; c++) {
            float wq = Wqs[c][d];
            float wv = Wvs[c][d];
#pragma unroll
            for (int i = 0; i < 14; i++) {
                float xi = xs[c][half * 14 + i];
                accq[i] = fmaf(xi, wq, accq[i]);
                accv[i] = fmaf(xi, wv, accv[i]);
            }
        }
    }

    if (is_supp) {
        float* oq = g_k + img * (DDIM * PPIX) + d * PPIX + pp;
#pragma unroll
        for (int i = 0; i < 14; i++) oq[i] = accq[i];
#pragma unroll
        for (int i = 0; i < 14; i++)
            g_v[(img * PPIX + pp + i) * DDIM + d] = accv[i];
    } else {
        int qi = img - NSUP;
        float* oq = g_q + qi * (DDIM * PPIX) + d * PPIX + pp;
        float* ov = outv_ext + qi * (DDIM * PPIX) + d * PPIX + pp;
#pragma unroll
        for (int i = 0; i < 14; i++) { oq[i] = accq[i]; ov[i] = accv[i]; }
    }
}

// ---------------------------------------------------------------------------
// Fused attention kernel.
// grid = (2 m-tiles of 98, 5 classes, 32 batch). block = 256, 2 CTA/SM.
// Per chunk of 49 keys:
//   S[98x49] = Q.K^T   8x4 register tiles (169 threads), exp -> EsT[j][m]
//   dsum[m] += row sums (coalesced reads of EsT rows)
//   U[8x8] += E.V      8x8 register tiles (208 threads = 13 m x 16 d groups),
//                      E from smem (transposed), V straight from L1/L2.
// U persists in registers across all 20 chunks; final out = U/dsum.
// ---------------------------------------------------------------------------
#define MT 98
#define MTP 104
#define NC 49
#define NCP 52
#define ATT_SMEM_FLOATS (128 * MTP + 128 * NCP + NCP * MTP + MTP)

__global__ __launch_bounds__(256, 2) void attn_kernel(float* __restrict__ out)
{
    extern __shared__ float sm[];
    float* Qs = sm;                         // [128][104]  Qs[d][mi]
    float* Ks = Qs + 128 * MTP;             // [128][52]   Ks[d][j]
    float* EsT = Ks + 128 * NCP;            // [52][104]   EsT[j][m]
    float* dsum = EsT + NCP * MTP;          // [104]

    const int tid = threadIdx.x;
    const int mt = blockIdx.x, kc = blockIdx.y, b = blockIdx.z;
    const int m_base = mt * MT;

    // load Q tile transposed, zero-pad m >= 98
    {
        const float* qimg = g_q + b * (DDIM * PPIX);
        for (int idx = tid; idx < 128 * MTP; idx += 256) {
            int d = idx / MTP, mi = idx - d * MTP;
            Qs[idx] = (mi < MT) ? qimg[d * PPIX + m_base + mi] : 0.f;
        }
    }
    if (tid < MTP) dsum[tid] = 0.f;

    // S-phase thread mapping: 13x13 grid of 8x4 tiles (tid < 169)
    const int s_ty = tid / 13;
    const int s_tx = tid - s_ty * 13;
    const int s_m0 = s_ty * 8;
    const int s_j0 = s_tx * 4;

    // PV-phase thread mapping: 13 m-groups x 16 d-groups (tid < 208)
    const int p_ty = tid / 16;              // m-group
    const int p_tx = tid - p_ty * 16;       // d-group
    const int p_m0 = p_ty * 8;
    const int p_d0 = p_tx * 8;

    float U[64];
#pragma unroll
    for (int i = 0; i < 64; i++) U[i] = 0.f;

    const float* vclass = g_v + (kc * KEYS) * DDIM;

    for (int ch = 0; ch < 20; ch++) {
        __syncthreads();   // protects EsT (prev PV done) and Ks (prev S done)
        const int key0 = kc * KEYS + ch * NC;
        // stage K chunk transposed, zero-pad j >= 49
        for (int idx = tid; idx < 128 * NCP; idx += 256) {
            int d = idx / NCP, j = idx - d * NCP;
            float val = 0.f;
            if (j < NC) {
                int kg = key0 + j;
                int n = kg / PPIX, pix = kg - n * PPIX;
                val = g_k[n * (DDIM * PPIX) + d * PPIX + pix];
            }
            Ks[idx] = val;
        }
        __syncthreads();

        // S = Q.K^T (8m x 4j per thread) -> EsT[j][m] = exp(S)
        if (tid < 169) {
            float acc[8][4];
#pragma unroll
            for (int i = 0; i < 8; i++)
#pragma unroll
                for (int jj = 0; jj < 4; jj++) acc[i][jj] = 0.f;

#pragma unroll 4
            for (int d = 0; d < 128; d++) {
                const float4 a0 = *(const float4*)(Qs + d * MTP + s_m0);
                const float4 a1 = *(const float4*)(Qs + d * MTP + s_m0 + 4);
                const float4 b0 = *(const float4*)(Ks + d * NCP + s_j0);
                float am[8] = {a0.x, a0.y, a0.z, a0.w, a1.x, a1.y, a1.z, a1.w};
                float bn[4] = {b0.x, b0.y, b0.z, b0.w};
#pragma unroll
                for (int i = 0; i < 8; i++)
#pragma unroll
                    for (int jj = 0; jj < 4; jj++)
                        acc[i][jj] = fmaf(am[i], bn[jj], acc[i][jj]);
            }
#pragma unroll
            for (int jj = 0; jj < 4; jj++)
#pragma unroll
                for (int i = 0; i < 8; i++)
                    EsT[(s_j0 + jj) * MTP + s_m0 + i] = __expf(acc[i][jj]);
        }
        __syncthreads();

        // per-row denominators (coalesced: consecutive m per j-row)
        if (tid < MTP) {
            float s = 0.f;
#pragma unroll 7
            for (int j = 0; j < NC; j++) s += EsT[j * MTP + tid];
            dsum[tid] += s;
        }

        // U[m0..+8, d0..+8] += E.V  (8x8 tile, 208 threads)
        if (tid < 208) {
            const float* vb = vclass + (ch * NC) * DDIM + p_d0;
            const float* eb = EsT + p_m0;
#pragma unroll 7
            for (int j = 0; j < NC; j++) {
                const float4 e0 = *(const float4*)(eb + j * MTP);
                const float4 e1 = *(const float4*)(eb + j * MTP + 4);
                const float4 v0 = *(const float4*)(vb + j * DDIM);
                const float4 v1 = *(const float4*)(vb + j * DDIM + 4);
                float ev[8] = {e0.x, e0.y, e0.z, e0.w, e1.x, e1.y, e1.z, e1.w};
                float vv[8] = {v0.x, v0.y, v0.z, v0.w, v1.x, v1.y, v1.z, v1.w};
#pragma unroll
                for (int i = 0; i < 8; i++)
#pragma unroll
                    for (int dd = 0; dd < 8; dd++)
                        U[i * 8 + dd] = fmaf(ev[i], vv[dd], U[i * 8 + dd]);
            }
        }
    }
    __syncthreads();

    // normalize + write: out[b][k][(p_d0+dd)*196 + m_base + p_m0 + i]
    if (tid < 208) {
        float ds[8];
#pragma unroll
        for (int i = 0; i < 8; i++) ds[i] = 1.f / dsum[p_m0 + i];
        float* ob = out + ((b * KCLS + kc) * DDIM + p_d0) * PPIX + m_base + p_m0;
#pragma unroll
        for (int dd = 0; dd < 8; dd++) {
#pragma unroll
            for (int i = 0; i < 8; i++) {
                if (p_m0 + i < MT)
                    ob[dd * PPIX + i] = U[i * 8 + dd] * ds[i];
            }
        }
    }
}

// ---------------------------------------------------------------------------
// kernel_launch
// inputs: 0 support_features [25,512,14,14], 1 query_features [32,512,14,14],
//         2 support_labels (sorted repeat pattern — unused), 3 W_qk [128,512],
//         4 W_v [128,512]
// output: prototypes [32,5,25088] then query_v [32,1,25088]
// ---------------------------------------------------------------------------
extern "C" void kernel_launch(void* const* d_in, const int* in_sizes, int n_in,
                              void* d_out, int out_size)
{
    const float* supp = (const float*)d_in[0];
    const float* qry  = (const float*)d_in[1];
    const float* Wqk  = (const float*)d_in[3];
    const float* Wv   = (const float*)d_in[4];
    float* out = (float*)d_out;

    const int att_smem = ATT_SMEM_FLOATS * (int)sizeof(float);
    cudaFuncSetAttribute(attn_kernel,
                         cudaFuncAttributeMaxDynamicSharedMemorySize, att_smem);

    // all projections in one launch (supports + queries)
    proj_kernel<<<dim3(7, NSUP + BQ), 256>>>(supp, qry, Wqk, Wv, out + OUT1);
    // fused attention -> prototypes
    attn_kernel<<<dim3(2, KCLS, BQ), 256, att_smem>>>(out);
}

// round 3
// speedup vs baseline: 1.0967x; 1.0009x over previous
#include <cuda_runtime.h>
#include <math.h>

// Problem constants
#define BQ 32          // query batch
#define NSUP 25        // support images
#define KCLS 5         // classes
#define CIN 512        // input channels
#define PPIX 196       // 14*14 pixels
#define DDIM 128       // dk = dv
#define KEYS 980       // keys per class (5 supports * 196)
#define OUT1 (BQ * KCLS * DDIM * PPIX)   // prototypes size = 4,014,080

// Scratch (device globals — no allocation allowed)
__device__ float g_q[BQ * DDIM * PPIX];     // [b][d][p]
__device__ float g_k[NSUP * DDIM * PPIX];   // [n][d][p]
__device__ float g_v[NSUP * PPIX * DDIM];   // [key][d]  (key = n*196+pix)

// ---------------------------------------------------------------------------
// Projection kernel (merged supports+queries).
// grid = (7 pixel-tiles of 28, 57 images). block = 256 = 128 d x 2 halves.
// Each thread: one d, 14 pixels, both q and v accumulators.
// img < 25: support (q->g_k, v->g_v transposed); else query (q->g_q, v->out).
// ---------------------------------------------------------------------------
__global__ __launch_bounds__(256) void proj_kernel(
    const float* __restrict__ supp, const float* __restrict__ qry,
    const float* __restrict__ Wq, const float* __restrict__ Wv,
    float* __restrict__ outv_ext)
{
    __shared__ float Wqs[32][129];
    __shared__ float Wvs[32][129];
    __shared__ float xs[32][28];

    const int tid = threadIdx.x;
    const int d = tid & 127;
    const int half = tid >> 7;
    const int img = blockIdx.y;
    const bool is_supp = img < NSUP;
    const float* x = is_supp ? supp + img * (CIN * PPIX)
                             : qry + (img - NSUP) * (CIN * PPIX);
    const int p0 = blockIdx.x * 28;
    const int pp = p0 + half * 14;

    float accq[14], accv[14];
#pragma unroll
    for (int i = 0; i < 14; i++) { accq[i] = 0.f; accv[i] = 0.f; }

    for (int c0 = 0; c0 < CIN; c0 += 32) {
        __syncthreads();
        for (int idx = tid; idx < 32 * 128; idx += 256) {
            int dd = idx >> 5, c = idx & 31;
            Wqs[c][dd] = Wq[dd * CIN + c0 + c];
            Wvs[c][dd] = Wv[dd * CIN + c0 + c];
        }
        for (int idx = tid; idx < 32 * 28; idx += 256) {
            int c = idx / 28, i = idx - c * 28;
            xs[c][i] = x[(c0 + c) * PPIX + p0 + i];
        }
        __syncthreads();
#pragma unroll 8
        for (int c = 0; c < 32; c++) {
            float wq = Wqs[c][d];
            float wv = Wvs[c][d];
#pragma unroll
            for (int i = 0; i < 14; i++) {
                float xi = xs[c][half * 14 + i];
                accq[i] = fmaf(xi, wq, accq[i]);
                accv[i] = fmaf(xi, wv, accv[i]);
            }
        }
    }

    if (is_supp) {
        float* oq = g_k + img * (DDIM * PPIX) + d * PPIX + pp;
#pragma unroll
        for (int i = 0; i < 14; i++) oq[i] = accq[i];
#pragma unroll
        for (int i = 0; i < 14; i++)
            g_v[(img * PPIX + pp + i) * DDIM + d] = accv[i];
    } else {
        int qi = img - NSUP;
        float* oq = g_q + qi * (DDIM * PPIX) + d * PPIX + pp;
        float* ov = outv_ext + qi * (DDIM * PPIX) + d * PPIX + pp;
#pragma unroll
        for (int i = 0; i < 14; i++) { oq[i] = accq[i]; ov[i] = accv[i]; }
    }
}

// ---------------------------------------------------------------------------
// Fused attention kernel.
// grid = (2 m-tiles of 98, 5 classes, 32 batch). block = 256, 2 CTA/SM.
// Per chunk of 49 keys:
//   S[98x49] = Q.K^T   8x4 register tiles (169 threads), exp -> EsT[j][m]
//   dsum[m] += row sums (coalesced reads of EsT rows)
//   U[8x8] += E.V      8x8 register tiles (208 threads = 13 m x 16 d groups),
//                      E from smem (transposed), V straight from L1/L2.
// U persists in registers across all 20 chunks; final out = U/dsum.
// ---------------------------------------------------------------------------
#define MT 98
#define MTP 104
#define NC 49
#define NCP 52
#define ATT_SMEM_FLOATS (128 * MTP + 128 * NCP + NCP * MTP + MTP)

__global__ __launch_bounds__(256, 2) void attn_kernel(float* __restrict__ out)
{
    extern __shared__ float sm[];
    float* Qs = sm;                         // [128][104]  Qs[d][mi]
    float* Ks = Qs + 128 * MTP;             // [128][52]   Ks[d][j]
    float* EsT = Ks + 128 * NCP;            // [52][104]   EsT[j][m]
    float* dsum = EsT + NCP * MTP;          // [104]

    const int tid = threadIdx.x;
    const int mt = blockIdx.x, kc = blockIdx.y, b = blockIdx.z;
    const int m_base = mt * MT;

    // load Q tile transposed, zero-pad m >= 98
    {
        const float* qimg = g_q + b * (DDIM * PPIX);
        for (int idx = tid; idx < 128 * MTP; idx += 256) {
            int d = idx / MTP, mi = idx - d * MTP;
            Qs[idx] = (mi < MT) ? qimg[d * PPIX + m_base + mi] : 0.f;
        }
    }
    if (tid < MTP) dsum[tid] = 0.f;

    // S-phase thread mapping: 13x13 grid of 8x4 tiles (tid < 169)
    const int s_ty = tid / 13;
    const int s_tx = tid - s_ty * 13;
    const int s_m0 = s_ty * 8;
    const int s_j0 = s_tx * 4;

    // PV-phase thread mapping: 13 m-groups x 16 d-groups (tid < 208)
    const int p_ty = tid / 16;              // m-group
    const int p_tx = tid - p_ty * 16;       // d-group
    const int p_m0 = p_ty * 8;
    const int p_d0 = p_tx * 8;

    float U[64];
#pragma unroll
    for (int i = 0; i < 64; i++) U[i] = 0.f;

    const float* vclass = g_v + (kc * KEYS) * DDIM;

    for (int ch = 0; ch < 20; ch++) {
        __syncthreads();   // protects EsT (prev PV done) and Ks (prev S done)
        const int key0 = kc * KEYS + ch * NC;
        // stage K chunk transposed, zero-pad j >= 49
        for (int idx = tid; idx < 128 * NCP; idx += 256) {
            int d = idx / NCP, j = idx - d * NCP;
            float val = 0.f;
            if (j < NC) {
                int kg = key0 + j;
                int n = kg / PPIX, pix = kg - n * PPIX;
                val = g_k[n * (DDIM * PPIX) + d * PPIX + pix];
            }
            Ks[idx] = val;
        }
        __syncthreads();

        // S = Q.K^T (8m x 4j per thread) -> EsT[j][m] = exp(S)
        if (tid < 169) {
            float acc[8][4];
#pragma unroll
            for (int i = 0; i < 8; i++)
#pragma unroll
                for (int jj = 0; jj < 4; jj++) acc[i][jj] = 0.f;

#pragma unroll 4
            for (int d = 0; d < 128; d++) {
                const float4 a0 = *(const float4*)(Qs + d * MTP + s_m0);
                const float4 a1 = *(const float4*)(Qs + d * MTP + s_m0 + 4);
                const float4 b0 = *(const float4*)(Ks + d * NCP + s_j0);
                float am[8] = {a0.x, a0.y, a0.z, a0.w, a1.x, a1.y, a1.z, a1.w};
                float bn[4] = {b0.x, b0.y, b0.z, b0.w};
#pragma unroll
                for (int i = 0; i < 8; i++)
#pragma unroll
                    for (int jj = 0; jj < 4; jj++)
                        acc[i][jj] = fmaf(am[i], bn[jj], acc[i][jj]);
            }
#pragma unroll
            for (int jj = 0; jj < 4; jj++)
#pragma unroll
                for (int i = 0; i < 8; i++)
                    EsT[(s_j0 + jj) * MTP + s_m0 + i] = __expf(acc[i][jj]);
        }
        __syncthreads();

        // per-row denominators (coalesced: consecutive m per j-row)
        if (tid < MTP) {
            float s = 0.f;
#pragma unroll 7
            for (int j = 0; j < NC; j++) s += EsT[j * MTP + tid];
            dsum[tid] += s;
        }

        // U[m0..+8, d0..+8] += E.V  (8x8 tile, 208 threads)
        if (tid < 208) {
            const float* vb = vclass + (ch * NC) * DDIM + p_d0;
            const float* eb = EsT + p_m0;
#pragma unroll 7
            for (int j = 0; j < NC; j++) {
                const float4 e0 = *(const float4*)(eb + j * MTP);
                const float4 e1 = *(const float4*)(eb + j * MTP + 4);
                const float4 v0 = *(const float4*)(vb + j * DDIM);
                const float4 v1 = *(const float4*)(vb + j * DDIM + 4);
                float ev[8] = {e0.x, e0.y, e0.z, e0.w, e1.x, e1.y, e1.z, e1.w};
                float vv[8] = {v0.x, v0.y, v0.z, v0.w, v1.x, v1.y, v1.z, v1.w};
#pragma unroll
                for (int i = 0; i < 8; i++)
#pragma unroll
                    for (int dd = 0; dd < 8; dd++)
                        U[i * 8 + dd] = fmaf(ev[i], vv[dd], U[i * 8 + dd]);
            }
        }
    }
    __syncthreads();

    // normalize + write: out[b][k][(p_d0+dd)*196 + m_base + p_m0 + i]
    if (tid < 208) {
        float ds[8];
#pragma unroll
        for (int i = 0; i < 8; i++) ds[i] = 1.f / dsum[p_m0 + i];
        float* ob = out + ((b * KCLS + kc) * DDIM + p_d0) * PPIX + m_base + p_m0;
#pragma unroll
        for (int dd = 0; dd < 8; dd++) {
#pragma unroll
            for (int i = 0; i < 8; i++) {
                if (p_m0 + i < MT)
                    ob[dd * PPIX + i] = U[i * 8 + dd] * ds[i];
            }
        }
    }
}

// ---------------------------------------------------------------------------
// kernel_launch
// inputs: 0 support_features [25,512,14,14], 1 query_features [32,512,14,14],
//         2 support_labels (sorted repeat pattern — unused), 3 W_qk [128,512],
//         4 W_v [128,512]
// output: prototypes [32,5,25088] then query_v [32,1,25088]
// ---------------------------------------------------------------------------
extern "C" void kernel_launch(void* const* d_in, const int* in_sizes, int n_in,
                              void* d_out, int out_size)
{
    const float* supp = (const float*)d_in[0];
    const float* qry  = (const float*)d_in[1];
    const float* Wqk  = (const float*)d_in[3];
    const float* Wv   = (const float*)d_in[4];
    float* out = (float*)d_out;

    const int att_smem = ATT_SMEM_FLOATS * (int)sizeof(float);
    cudaFuncSetAttribute(attn_kernel,
                         cudaFuncAttributeMaxDynamicSharedMemorySize, att_smem);

    // all projections in one launch (supports + queries)
    proj_kernel<<<dim3(7, NSUP + BQ), 256>>>(supp, qry, Wqk, Wv, out + OUT1);
    // fused attention -> prototypes
    attn_kernel<<<dim3(2, KCLS, BQ), 256, att_smem>>>(out);
}

// round 5
// speedup vs baseline: 2.3565x; 2.1487x over previous
#include <cuda_runtime.h>
#include <cuda_bf16.h>
#include <cstdint>
#include <math.h>

// ---------------------------------------------------------------------------
// Problem constants
// ---------------------------------------------------------------------------
#define BQ 32
#define NSUP 25
#define KCLS 5
#define CIN 512
#define PPIX 196
#define DDIM 128
#define KEYS 980
#define OUT1 (BQ * KCLS * DDIM * PPIX)

// bf16 hi/lo split scratch (device globals — no allocation allowed)
__device__ __align__(16) __nv_bfloat16 g_qh[BQ * PPIX * DDIM];    // [b][p][d]
__device__ __align__(16) __nv_bfloat16 g_ql[BQ * PPIX * DDIM];
__device__ __align__(16) __nv_bfloat16 g_kh[NSUP * PPIX * DDIM];  // [gkey][d]
__device__ __align__(16) __nv_bfloat16 g_kl[NSUP * PPIX * DDIM];
__device__ __align__(16) __nv_bfloat16 g_vh[NSUP * DDIM * PPIX];  // [n][d][pix]
__device__ __align__(16) __nv_bfloat16 g_vl[NSUP * DDIM * PPIX];

// ---------------------------------------------------------------------------
// mma.sync / ldmatrix helpers (baseline PTX, legal on plain sm_103)
// ---------------------------------------------------------------------------
__device__ __forceinline__ void ldsm4(uint32_t addr, uint32_t r[4]) {
    asm volatile("ldmatrix.sync.aligned.m8n8.x4.shared.b16 {%0,%1,%2,%3}, [%4];"
                 : "=r"(r[0]), "=r"(r[1]), "=r"(r[2]), "=r"(r[3]) : "r"(addr));
}
__device__ __forceinline__ void mma16816(float c[4], const uint32_t a[4],
                                         uint32_t b0, uint32_t b1) {
    asm volatile("mma.sync.aligned.m16n8k16.row.col.f32.bf16.bf16.f32 "
                 "{%0,%1,%2,%3}, {%4,%5,%6,%7}, {%8,%9}, {%0,%1,%2,%3};"
                 : "+f"(c[0]), "+f"(c[1]), "+f"(c[2]), "+f"(c[3])
                 : "r"(a[0]), "r"(a[1]), "r"(a[2]), "r"(a[3]), "r"(b0), "r"(b1));
}
__device__ __forceinline__ uint32_t smem_u32(const void* p) {
    uint32_t a;
    asm("{ .reg .u64 t; cvta.to.shared.u64 t, %1; cvt.u32.u64 %0, t; }"
        : "=r"(a) : "l"(p));
    return a;
}
// pack two f32 -> bf16x2, lower half = first arg
__device__ __forceinline__ uint32_t packbf(float e0, float e1) {
    uint32_t r;
    asm("cvt.rn.bf16x2.f32 %0, %1, %2;" : "=r"(r) : "f"(e1), "f"(e0));
    return r;
}

// ---------------------------------------------------------------------------
// Projection: channel-mixing GEMM + bf16 hi/lo split emission.
// grid = (7 pixel-tiles of 28, 57 images). block = 256 = 128 d x 2 halves.
// ---------------------------------------------------------------------------
__global__ __launch_bounds__(256) void proj_kernel(
    const float* __restrict__ supp, const float* __restrict__ qry,
    const float* __restrict__ Wq, const float* __restrict__ Wv,
    float* __restrict__ outv_ext)
{
    __shared__ float Wqs[32][129];
    __shared__ float Wvs[32][129];
    __shared__ float xs[32][28];

    const int tid = threadIdx.x;
    const int d = tid & 127;
    const int half = tid >> 7;
    const int img = blockIdx.y;
    const bool is_supp = img < NSUP;
    const float* x = is_supp ? supp + img * (CIN * PPIX)
                             : qry + (img - NSUP) * (CIN * PPIX);
    const int p0 = blockIdx.x * 28;
    const int pp = p0 + half * 14;

    float accq[14], accv[14];
#pragma unroll
    for (int i = 0; i < 14; i++) { accq[i] = 0.f; accv[i] = 0.f; }

    for (int c0 = 0; c0 < CIN; c0 += 32) {
        __syncthreads();
        for (int idx = tid; idx < 32 * 128; idx += 256) {
            int dd = idx >> 5, c = idx & 31;
            Wqs[c][dd] = Wq[dd * CIN + c0 + c];
            Wvs[c][dd] = Wv[dd * CIN + c0 + c];
        }
        for (int idx = tid; idx < 32 * 28; idx += 256) {
            int c = idx / 28, i = idx - c * 28;
            xs[c][i] = x[(c0 + c) * PPIX + p0 + i];
        }
        __syncthreads();
#pragma unroll 8
        for (int c = 0; c < 32; c++) {
            float wq = Wqs[c][d];
            float wv = Wvs[c][d];
#pragma unroll
            for (int i = 0; i < 14; i++) {
                float xi = xs[c][half * 14 + i];
                accq[i] = fmaf(xi, wq, accq[i]);
                accv[i] = fmaf(xi, wv, accv[i]);
            }
        }
    }

    if (is_supp) {
#pragma unroll
        for (int i = 0; i < 14; i++) {
            float q = accq[i];
            __nv_bfloat16 qh = __float2bfloat16(q);
            int kidx = (img * PPIX + pp + i) * DDIM + d;
            g_kh[kidx] = qh;
            g_kl[kidx] = __float2bfloat16(q - __bfloat162float(qh));
            float v = accv[i];
            __nv_bfloat16 vh = __float2bfloat16(v);
            int vidx = (img * DDIM + d) * PPIX + pp + i;
            g_vh[vidx] = vh;
            g_vl[vidx] = __float2bfloat16(v - __bfloat162float(vh));
        }
    } else {
        int qi = img - NSUP;
        float* ov = outv_ext + qi * (DDIM * PPIX) + d * PPIX + pp;
#pragma unroll
        for (int i = 0; i < 14; i++) {
            float q = accq[i];
            __nv_bfloat16 qh = __float2bfloat16(q);
            int qidx = (qi * PPIX + pp + i) * DDIM + d;
            g_qh[qidx] = qh;
            g_ql[qidx] = __float2bfloat16(q - __bfloat162float(qh));
            ov[i] = accv[i];
        }
    }
}

// ---------------------------------------------------------------------------
// mma.sync attention. grid = (2, 5, 32), block = 256 (8 warps), 1 CTA/SM.
// M-tile 128 rows (98 valid). 16 chunks x 64 keys (980 valid, pads masked).
// S warps: 4m x 2j (32x32).  PV warps: 4m x 2d (32x64), O in regs.
// ---------------------------------------------------------------------------
// smem byte offsets (rows padded +16B for conflict-free ldmatrix)
#define QROW 272            // 128 bf16 + 8 pad
#define EROW 144            // 64 bf16 + 8 pad
#define OFF_QH 0
#define OFF_QL 34816
#define OFF_KH 69632
#define OFF_KL 87040
#define OFF_VH 104448
#define OFF_VL 122880
#define OFF_EH 141312
#define OFF_EL 159744
#define OFF_DS 178176
#define ATT_SMEM (OFF_DS + 512)

__global__ __launch_bounds__(256, 1) void attn_kernel(float* __restrict__ out)
{
    extern __shared__ char smem[];
    const uint32_t sb = smem_u32(smem);
    float* dsumf = (float*)(smem + OFF_DS);

    const int tid = threadIdx.x;
    const int lane = tid & 31;
    const int warp = tid >> 5;
    const int mt = blockIdx.x, kc = blockIdx.y, b = blockIdx.z;

    const int sm0 = (warp & 3) * 32;     // warp m base (S and PV)
    const int sj0 = (warp >> 2) * 32;    // warp j base (S)
    const int pd0 = (warp >> 2) * 64;    // warp d base (PV)

    // ldmatrix lane addressing
    const int a_row = lane & 15;
    const int a_off = (lane >> 4) << 4;
    const int b_row = (lane & 7) | ((lane >> 4) << 3);
    const int b_off = ((lane >> 3) & 1) << 4;

    const uint32_t* qh32 = (const uint32_t*)g_qh;
    const uint32_t* ql32 = (const uint32_t*)g_ql;
    const uint32_t* kh32 = (const uint32_t*)g_kh;
    const uint32_t* kl32 = (const uint32_t*)g_kl;
    const uint32_t* vh32 = (const uint32_t*)g_vh;
    const uint32_t* vl32 = (const uint32_t*)g_vl;

    // ---- stage Q (hi/lo), zero-pad rows 98..127; zero dsum ----
    for (int idx = tid; idx < 128 * 64; idx += 256) {
        int r = idx >> 6, w = idx & 63;
        uint32_t vh = 0, vl = 0;
        if (r < 98) {
            int gi = (b * PPIX + mt * 98 + r) * 64 + w;
            vh = qh32[gi];
            vl = ql32[gi];
        }
        *(uint32_t*)(smem + OFF_QH + r * QROW + w * 4) = vh;
        *(uint32_t*)(smem + OFF_QL + r * QROW + w * 4) = vl;
    }
    if (tid < 128) dsumf[tid] = 0.f;

    // PV accumulators, persist across chunks: O[32m x 64d] per warp
    float oc[2][8][4];
#pragma unroll
    for (int mi = 0; mi < 2; mi++)
#pragma unroll
        for (int n = 0; n < 8; n++)
#pragma unroll
            for (int q = 0; q < 4; q++) oc[mi][n][q] = 0.f;

    for (int ch = 0; ch < 16; ch++) {
        __syncthreads();   // prior S/PV reads of K/V/E done before restage

        // ---- stage K chunk (rows j, hi/lo) and V^T chunk (rows d) ----
        for (int idx = tid; idx < 64 * 64; idx += 256) {
            int j = idx >> 6, w = idx & 63;
            int loc = ch * 64 + j;
            uint32_t vh = 0, vl = 0;
            if (loc < KEYS) {
                int gi = (kc * KEYS + loc) * 64 + w;
                vh = kh32[gi];
                vl = kl32[gi];
            }
            *(uint32_t*)(smem + OFF_KH + j * QROW + w * 4) = vh;
            *(uint32_t*)(smem + OFF_KL + j * QROW + w * 4) = vl;
        }
        for (int idx = tid; idx < 128 * 32; idx += 256) {
            int d = idx >> 5, w = idx & 31;
            int loc = ch * 64 + 2 * w;     // even -> pixel pair in same image
            uint32_t vh = 0, vl = 0;
            if (loc < KEYS) {
                int g = kc * KEYS + loc;
                int n = g / PPIX, pix = g - n * PPIX;
                int gi = (n * DDIM + d) * 98 + (pix >> 1);
                vh = vh32[gi];
                vl = vl32[gi];
            }
            *(uint32_t*)(smem + OFF_VH + d * EROW + w * 4) = vh;
            *(uint32_t*)(smem + OFF_VL + d * EROW + w * 4) = vl;
        }
        __syncthreads();

        // ---- S = Qh.Kh^T + Qh.Kl^T + Ql.Kh^T  (32m x 32j per warp) ----
        float sc[2][4][4];
#pragma unroll
        for (int mi = 0; mi < 2; mi++)
#pragma unroll
            for (int n = 0; n < 4; n++)
#pragma unroll
                for (int q = 0; q < 4; q++) sc[mi][n][q] = 0.f;

#pragma unroll
        for (int k = 0; k < 8; k++) {
            const int kb = k * 32;
            uint32_t ah[2][4], al[2][4], bh[2][4], bl[2][4];
#pragma unroll
            for (int mi = 0; mi < 2; mi++) {
                uint32_t ra = sb + OFF_QH + (sm0 + mi * 16 + a_row) * QROW + kb + a_off;
                ldsm4(ra, ah[mi]);
                ldsm4(ra + (OFF_QL - OFF_QH), al[mi]);
            }
#pragma unroll
            for (int nj = 0; nj < 2; nj++) {
                uint32_t rb = sb + OFF_KH + (sj0 + nj * 16 + b_row) * QROW + kb + b_off;
                ldsm4(rb, bh[nj]);
                ldsm4(rb + (OFF_KL - OFF_KH), bl[nj]);
            }
#pragma unroll
            for (int mi = 0; mi < 2; mi++)
#pragma unroll
                for (int n = 0; n < 4; n++) {
                    uint32_t bh0 = bh[n >> 1][(n & 1) * 2], bh1 = bh[n >> 1][(n & 1) * 2 + 1];
                    uint32_t bl0 = bl[n >> 1][(n & 1) * 2], bl1 = bl[n >> 1][(n & 1) * 2 + 1];
                    mma16816(sc[mi][n], ah[mi], bh0, bh1);
                    mma16816(sc[mi][n], ah[mi], bl0, bl1);
                    mma16816(sc[mi][n], al[mi], bh0, bh1);
                }
        }

        // ---- exp + mask pads; write E hi/lo to smem; row-sum partials ----
        float rs[4] = {0.f, 0.f, 0.f, 0.f};
#pragma unroll
        for (int mi = 0; mi < 2; mi++)
#pragma unroll
            for (int n = 0; n < 4; n++) {
                int jl = sj0 + n * 8 + 2 * (lane & 3);
                int jg = ch * 64 + jl;
                float e0 = (jg     < KEYS) ? __expf(sc[mi][n][0]) : 0.f;
                float e1 = (jg + 1 < KEYS) ? __expf(sc[mi][n][1]) : 0.f;
                float e2 = (jg     < KEYS) ? __expf(sc[mi][n][2]) : 0.f;
                float e3 = (jg + 1 < KEYS) ? __expf(sc[mi][n][3]) : 0.f;
                rs[mi * 2]     += e0 + e1;
                rs[mi * 2 + 1] += e2 + e3;
                int r = sm0 + mi * 16 + (lane >> 2);
                float h0 = __bfloat162float(__float2bfloat16(e0));
                float h1 = __bfloat162float(__float2bfloat16(e1));
                float h2 = __bfloat162float(__float2bfloat16(e2));
                float h3 = __bfloat162float(__float2bfloat16(e3));
                *(uint32_t*)(smem + OFF_EH + r * EROW + jl * 2)       = packbf(h0, h1);
                *(uint32_t*)(smem + OFF_EH + (r + 8) * EROW + jl * 2) = packbf(h2, h3);
                *(uint32_t*)(smem + OFF_EL + r * EROW + jl * 2)       = packbf(e0 - h0, e1 - h1);
                *(uint32_t*)(smem + OFF_EL + (r + 8) * EROW + jl * 2) = packbf(e2 - h2, e3 - h3);
            }
        // quad reduce -> one atomicAdd per (row, warp)
#pragma unroll
        for (int s = 0; s < 4; s++) {
            rs[s] += __shfl_xor_sync(0xFFFFFFFFu, rs[s], 1);
            rs[s] += __shfl_xor_sync(0xFFFFFFFFu, rs[s], 2);
        }
        if ((lane & 3) == 0) {
#pragma unroll
            for (int mi = 0; mi < 2; mi++) {
                int r = sm0 + mi * 16 + (lane >> 2);
                atomicAdd(&dsumf[r], rs[mi * 2]);
                atomicAdd(&dsumf[r + 8], rs[mi * 2 + 1]);
            }
        }
        __syncthreads();   // E visible to all warps

        // ---- O += Eh.Vh + Eh.Vl + El.Vh  (32m x 64d per warp) ----
#pragma unroll
        for (int kj = 0; kj < 4; kj++) {
            const int kb = kj * 32;
            uint32_t eh[2][4], el[2][4], vvh[4][4], vvl[4][4];
#pragma unroll
            for (int mi = 0; mi < 2; mi++) {
                uint32_t ra = sb + OFF_EH + (sm0 + mi * 16 + a_row) * EROW + kb + a_off;
                ldsm4(ra, eh[mi]);
                ldsm4(ra + (OFF_EL - OFF_EH), el[mi]);
            }
#pragma unroll
            for (int nd = 0; nd < 4; nd++) {
                uint32_t rb = sb + OFF_VH + (pd0 + nd * 16 + b_row) * EROW + kb + b_off;
                ldsm4(rb, vvh[nd]);
                ldsm4(rb + (OFF_VL - OFF_VH), vvl[nd]);
            }
#pragma unroll
            for (int mi = 0; mi < 2; mi++)
#pragma unroll
                for (int n = 0; n < 8; n++) {
                    uint32_t vh0 = vvh[n >> 1][(n & 1) * 2], vh1 = vvh[n >> 1][(n & 1) * 2 + 1];
                    uint32_t vl0 = vvl[n >> 1][(n & 1) * 2], vl1 = vvl[n >> 1][(n & 1) * 2 + 1];
                    mma16816(oc[mi][n], eh[mi], vh0, vh1);
                    mma16816(oc[mi][n], eh[mi], vl0, vl1);
                    mma16816(oc[mi][n], el[mi], vh0, vh1);
                }
        }
    }

    // ---- epilogue: O frags -> smem (transpose, pad 133) -> normalized out ----
    __syncthreads();
    float* Osm = (float*)smem;   // [128][133] f32, reuses Q region
#pragma unroll
    for (int mi = 0; mi < 2; mi++)
#pragma unroll
        for (int n = 0; n < 8; n++) {
            int r = sm0 + mi * 16 + (lane >> 2);
            int d = pd0 + n * 8 + 2 * (lane & 3);
            Osm[r * 133 + d]           = oc[mi][n][0];
            Osm[r * 133 + d + 1]       = oc[mi][n][1];
            Osm[(r + 8) * 133 + d]     = oc[mi][n][2];
            Osm[(r + 8) * 133 + d + 1] = oc[mi][n][3];
        }
    __syncthreads();

    float* ob = out + ((b * KCLS + kc) * DDIM) * PPIX + mt * 98;
    for (int idx = tid; idx < 128 * 98; idx += 256) {
        int d = idx / 98, m = idx - d * 98;
        ob[d * PPIX + m] = Osm[m * 133 + d] / dsumf[m];
    }
}

// ---------------------------------------------------------------------------
// kernel_launch
// ---------------------------------------------------------------------------
extern "C" void kernel_launch(void* const* d_in, const int* in_sizes, int n_in,
                              void* d_out, int out_size)
{
    const float* supp = (const float*)d_in[0];
    const float* qry  = (const float*)d_in[1];
    const float* Wqk  = (const float*)d_in[3];
    const float* Wv   = (const float*)d_in[4];
    float* out = (float*)d_out;

    cudaFuncSetAttribute(attn_kernel,
                         cudaFuncAttributeMaxDynamicSharedMemorySize, ATT_SMEM);

    proj_kernel<<<dim3(7, NSUP + BQ), 256>>>(supp, qry, Wqk, Wv, out + OUT1);
    attn_kernel<<<dim3(2, KCLS, BQ), 256, ATT_SMEM>>>(out);
}

// round 6
// speedup vs baseline: 2.4092x; 1.0223x over previous
#include <cuda_runtime.h>
#include <cuda_bf16.h>
#include <cstdint>
#include <math.h>

// ---------------------------------------------------------------------------
// Problem constants
// ---------------------------------------------------------------------------
#define BQ 32
#define NSUP 25
#define KCLS 5
#define CIN 512
#define PPIX 196
#define DDIM 128
#define KEYS 980
#define OUT1 (BQ * KCLS * DDIM * PPIX)

// bf16 hi/lo split scratch (device globals — no allocation allowed)
__device__ __align__(16) __nv_bfloat16 g_qh[BQ * PPIX * DDIM];    // [b][p][d]
__device__ __align__(16) __nv_bfloat16 g_ql[BQ * PPIX * DDIM];
__device__ __align__(16) __nv_bfloat16 g_kh[NSUP * PPIX * DDIM];  // [gkey][d]
__device__ __align__(16) __nv_bfloat16 g_kl[NSUP * PPIX * DDIM];
__device__ __align__(16) __nv_bfloat16 g_vh[NSUP * DDIM * PPIX];  // [n][d][pix]
__device__ __align__(16) __nv_bfloat16 g_vl[NSUP * DDIM * PPIX];

// ---------------------------------------------------------------------------
// mma.sync / ldmatrix helpers (baseline PTX, legal on plain sm_103)
// ---------------------------------------------------------------------------
__device__ __forceinline__ void ldsm4(uint32_t addr, uint32_t r[4]) {
    asm volatile("ldmatrix.sync.aligned.m8n8.x4.shared.b16 {%0,%1,%2,%3}, [%4];"
                 : "=r"(r[0]), "=r"(r[1]), "=r"(r[2]), "=r"(r[3]) : "r"(addr));
}
__device__ __forceinline__ void mma16816(float c[4], const uint32_t a[4],
                                         uint32_t b0, uint32_t b1) {
    asm volatile("mma.sync.aligned.m16n8k16.row.col.f32.bf16.bf16.f32 "
                 "{%0,%1,%2,%3}, {%4,%5,%6,%7}, {%8,%9}, {%0,%1,%2,%3};"
                 : "+f"(c[0]), "+f"(c[1]), "+f"(c[2]), "+f"(c[3])
                 : "r"(a[0]), "r"(a[1]), "r"(a[2]), "r"(a[3]), "r"(b0), "r"(b1));
}
__device__ __forceinline__ uint32_t smem_u32(const void* p) {
    uint32_t a;
    asm("{ .reg .u64 t; cvta.to.shared.u64 t, %1; cvt.u32.u64 %0, t; }"
        : "=r"(a) : "l"(p));
    return a;
}
__device__ __forceinline__ uint32_t packbf(float e0, float e1) {
    uint32_t r;   // lower half = e0
    asm("cvt.rn.bf16x2.f32 %0, %1, %2;" : "=r"(r) : "f"(e1), "f"(e0));
    return r;
}

// ---------------------------------------------------------------------------
// Projection: channel-mixing GEMM + bf16 hi/lo split emission.
// grid = (7 pixel-tiles of 28, 57 images). block = 256 = 128 d x 2 halves.
// ---------------------------------------------------------------------------
__global__ __launch_bounds__(256) void proj_kernel(
    const float* __restrict__ supp, const float* __restrict__ qry,
    const float* __restrict__ Wq, const float* __restrict__ Wv,
    float* __restrict__ outv_ext)
{
    __shared__ float Wqs[32][129];
    __shared__ float Wvs[32][129];
    __shared__ float xs[32][28];

    const int tid = threadIdx.x;
    const int d = tid & 127;
    const int half = tid >> 7;
    const int img = blockIdx.y;
    const bool is_supp = img < NSUP;
    const float* x = is_supp ? supp + img * (CIN * PPIX)
                             : qry + (img - NSUP) * (CIN * PPIX);
    const int p0 = blockIdx.x * 28;
    const int pp = p0 + half * 14;

    float accq[14], accv[14];
#pragma unroll
    for (int i = 0; i < 14; i++) { accq[i] = 0.f; accv[i] = 0.f; }

    for (int c0 = 0; c0 < CIN; c0 += 32) {
        __syncthreads();
        for (int idx = tid; idx < 32 * 128; idx += 256) {
            int dd = idx >> 5, c = idx & 31;
            Wqs[c][dd] = Wq[dd * CIN + c0 + c];
            Wvs[c][dd] = Wv[dd * CIN + c0 + c];
        }
        for (int idx = tid; idx < 32 * 28; idx += 256) {
            int c = idx / 28, i = idx - c * 28;
            xs[c][i] = x[(c0 + c) * PPIX + p0 + i];
        }
        __syncthreads();
#pragma unroll 8
        for (int c = 0; c < 32; c++) {
            float wq = Wqs[c][d];
            float wv = Wvs[c][d];
#pragma unroll
            for (int i = 0; i < 14; i++) {
                float xi = xs[c][half * 14 + i];
                accq[i] = fmaf(xi, wq, accq[i]);
                accv[i] = fmaf(xi, wv, accv[i]);
            }
        }
    }

    if (is_supp) {
#pragma unroll
        for (int i = 0; i < 14; i++) {
            float q = accq[i];
            __nv_bfloat16 qh = __float2bfloat16(q);
            int kidx = (img * PPIX + pp + i) * DDIM + d;
            g_kh[kidx] = qh;
            g_kl[kidx] = __float2bfloat16(q - __bfloat162float(qh));
            float v = accv[i];
            __nv_bfloat16 vh = __float2bfloat16(v);
            int vidx = (img * DDIM + d) * PPIX + pp + i;
            g_vh[vidx] = vh;
            g_vl[vidx] = __float2bfloat16(v - __bfloat162float(vh));
        }
    } else {
        int qi = img - NSUP;
        float* ov = outv_ext + qi * (DDIM * PPIX) + d * PPIX + pp;
#pragma unroll
        for (int i = 0; i < 14; i++) {
            float q = accq[i];
            __nv_bfloat16 qh = __float2bfloat16(q);
            int qidx = (qi * PPIX + pp + i) * DDIM + d;
            g_qh[qidx] = qh;
            g_ql[qidx] = __float2bfloat16(q - __bfloat162float(qh));
            ov[i] = accv[i];
        }
    }
}

// ---------------------------------------------------------------------------
// mma.sync attention. grid = (4 m-tiles of 49, 5, 32) = 640 CTAs.
// block = 256 (8 warps), 2 CTAs/SM (smem 83 KB). M=64 rows (49 valid).
// 32 chunks x 32 keys (980 valid, pads masked exactly).
// S warps: 4m(16) x 2j(16).  PV warps: 4m(16) x 2d(64), O held in regs.
// ---------------------------------------------------------------------------
#define QROW 272            // 128 bf16 + 16B pad (conflict-free ldmatrix)
#define EROW 80             // 32 bf16 + 16B pad
#define OFF_QH 0
#define OFF_QL 17408
#define OFF_KH 34816
#define OFF_KL 43520
#define OFF_VH 52224
#define OFF_VL 62464
#define OFF_EH 72704
#define OFF_EL 77824
#define OFF_DS 82944
#define ATT_SMEM (OFF_DS + 256)

__global__ __launch_bounds__(256, 2) void attn_kernel(float* __restrict__ out)
{
    extern __shared__ char smem[];
    const uint32_t sb = smem_u32(smem);
    float* dsumf = (float*)(smem + OFF_DS);

    const int tid = threadIdx.x;
    const int lane = tid & 31;
    const int warp = tid >> 5;
    const int mt = blockIdx.x, kc = blockIdx.y, b = blockIdx.z;

    const int m0 = (warp & 3) * 16;      // warp m base (S and PV)
    const int j0 = (warp >> 2) * 16;     // warp j base (S)
    const int d0 = (warp >> 2) * 64;     // warp d base (PV)

    // ldmatrix lane addressing
    const int a_row = lane & 15;
    const int a_off = (lane >> 4) << 4;
    const int b_row = (lane & 7) | ((lane >> 4) << 3);
    const int b_off = ((lane >> 3) & 1) << 4;

    const uint32_t* qh32 = (const uint32_t*)g_qh;
    const uint32_t* ql32 = (const uint32_t*)g_ql;
    const uint32_t* kh32 = (const uint32_t*)g_kh;
    const uint32_t* kl32 = (const uint32_t*)g_kl;
    const uint32_t* vh32 = (const uint32_t*)g_vh;
    const uint32_t* vl32 = (const uint32_t*)g_vl;

    // ---- stage Q (hi/lo), rows mt*49 .. +48, zero-pad rows 49..63 ----
    for (int idx = tid; idx < 64 * 64; idx += 256) {
        int r = idx >> 6, w = idx & 63;
        uint32_t vh = 0, vl = 0;
        if (r < 49) {
            int gi = (b * PPIX + mt * 49 + r) * 64 + w;
            vh = qh32[gi];
            vl = ql32[gi];
        }
        *(uint32_t*)(smem + OFF_QH + r * QROW + w * 4) = vh;
        *(uint32_t*)(smem + OFF_QL + r * QROW + w * 4) = vl;
    }
    if (tid < 64) dsumf[tid] = 0.f;

    // PV accumulators (persist across chunks): O[16m x 64d] per warp
    float oc[8][4];
#pragma unroll
    for (int n = 0; n < 8; n++)
#pragma unroll
        for (int q = 0; q < 4; q++) oc[n][q] = 0.f;

    for (int ch = 0; ch < 32; ch++) {
        __syncthreads();   // prior chunk's reads of K/V/E done before restage

        // ---- stage K chunk (32 key-rows, hi/lo) ----
        for (int idx = tid; idx < 32 * 64; idx += 256) {
            int j = idx >> 6, w = idx & 63;
            int loc = ch * 32 + j;
            uint32_t vh = 0, vl = 0;
            if (loc < KEYS) {
                int gi = (kc * KEYS + loc) * 64 + w;
                vh = kh32[gi];
                vl = kl32[gi];
            }
            *(uint32_t*)(smem + OFF_KH + j * QROW + w * 4) = vh;
            *(uint32_t*)(smem + OFF_KL + j * QROW + w * 4) = vl;
        }
        // ---- stage V^T chunk (128 d-rows x 32 keys, hi/lo) ----
        for (int idx = tid; idx < 128 * 16; idx += 256) {
            int d = idx >> 4, w = idx & 15;
            int loc = ch * 32 + 2 * w;
            uint32_t vh = 0, vl = 0;
            if (loc < KEYS) {
                int g = kc * KEYS + loc;
                int n = g / PPIX, pix = g - n * PPIX;
                int gi = (n * DDIM + d) * 98 + (pix >> 1);
                vh = vh32[gi];
                vl = vl32[gi];
            }
            *(uint32_t*)(smem + OFF_VH + d * EROW + w * 4) = vh;
            *(uint32_t*)(smem + OFF_VL + d * EROW + w * 4) = vl;
        }
        __syncthreads();

        // ---- S = Qh.Kh^T + Qh.Kl^T + Ql.Kh^T  (16m x 16j per warp) ----
        float sc[2][4];
#pragma unroll
        for (int n = 0; n < 2; n++)
#pragma unroll
            for (int q = 0; q < 4; q++) sc[n][q] = 0.f;

#pragma unroll
        for (int k = 0; k < 8; k++) {
            const int kb = k * 32;
            uint32_t ah[4], al[4], bh[4], bl[4];
            uint32_t ra = sb + OFF_QH + (m0 + a_row) * QROW + kb + a_off;
            ldsm4(ra, ah);
            ldsm4(ra + (OFF_QL - OFF_QH), al);
            uint32_t rb = sb + OFF_KH + (j0 + b_row) * QROW + kb + b_off;
            ldsm4(rb, bh);
            ldsm4(rb + (OFF_KL - OFF_KH), bl);
#pragma unroll
            for (int n = 0; n < 2; n++) {
                mma16816(sc[n], ah, bh[n * 2], bh[n * 2 + 1]);
                mma16816(sc[n], ah, bl[n * 2], bl[n * 2 + 1]);
                mma16816(sc[n], al, bh[n * 2], bh[n * 2 + 1]);
            }
        }

        // ---- exp + exact pad mask; E hi/lo -> smem; row-sum partials ----
        {
            float rs0 = 0.f, rs1 = 0.f;
            const int r = m0 + (lane >> 2);
#pragma unroll
            for (int n = 0; n < 2; n++) {
                int jl = j0 + n * 8 + 2 * (lane & 3);
                int jg = ch * 32 + jl;
                float e0 = (jg     < KEYS) ? __expf(sc[n][0]) : 0.f;
                float e1 = (jg + 1 < KEYS) ? __expf(sc[n][1]) : 0.f;
                float e2 = (jg     < KEYS) ? __expf(sc[n][2]) : 0.f;
                float e3 = (jg + 1 < KEYS) ? __expf(sc[n][3]) : 0.f;
                rs0 += e0 + e1;
                rs1 += e2 + e3;
                float h0 = __bfloat162float(__float2bfloat16(e0));
                float h1 = __bfloat162float(__float2bfloat16(e1));
                float h2 = __bfloat162float(__float2bfloat16(e2));
                float h3 = __bfloat162float(__float2bfloat16(e3));
                *(uint32_t*)(smem + OFF_EH + r * EROW + jl * 2)       = packbf(h0, h1);
                *(uint32_t*)(smem + OFF_EH + (r + 8) * EROW + jl * 2) = packbf(h2, h3);
                *(uint32_t*)(smem + OFF_EL + r * EROW + jl * 2)       = packbf(e0 - h0, e1 - h1);
                *(uint32_t*)(smem + OFF_EL + (r + 8) * EROW + jl * 2) = packbf(e2 - h2, e3 - h3);
            }
            rs0 += __shfl_xor_sync(0xFFFFFFFFu, rs0, 1);
            rs0 += __shfl_xor_sync(0xFFFFFFFFu, rs0, 2);
            rs1 += __shfl_xor_sync(0xFFFFFFFFu, rs1, 1);
            rs1 += __shfl_xor_sync(0xFFFFFFFFu, rs1, 2);
            if ((lane & 3) == 0) {
                atomicAdd(&dsumf[r], rs0);
                atomicAdd(&dsumf[r + 8], rs1);
            }
        }
        __syncthreads();   // E visible to all warps

        // ---- O += Eh.Vh + Eh.Vl + El.Vh  (16m x 64d per warp) ----
#pragma unroll
        for (int kj = 0; kj < 2; kj++) {
            const int kb = kj * 32;
            uint32_t eh[4], el[4], vvh[4][4], vvl[4][4];
            uint32_t ra = sb + OFF_EH + (m0 + a_row) * EROW + kb + a_off;
            ldsm4(ra, eh);
            ldsm4(ra + (OFF_EL - OFF_EH), el);
#pragma unroll
            for (int nd = 0; nd < 4; nd++) {
                uint32_t rb = sb + OFF_VH + (d0 + nd * 16 + b_row) * EROW + kb + b_off;
                ldsm4(rb, vvh[nd]);
                ldsm4(rb + (OFF_VL - OFF_VH), vvl[nd]);
            }
#pragma unroll
            for (int n = 0; n < 8; n++) {
                uint32_t vh0 = vvh[n >> 1][(n & 1) * 2], vh1 = vvh[n >> 1][(n & 1) * 2 + 1];
                uint32_t vl0 = vvl[n >> 1][(n & 1) * 2], vl1 = vvl[n >> 1][(n & 1) * 2 + 1];
                mma16816(oc[n], eh, vh0, vh1);
                mma16816(oc[n], eh, vl0, vl1);
                mma16816(oc[n], el, vh0, vh1);
            }
        }
    }

    // ---- epilogue: O frags -> smem (pad 133) -> normalized coalesced out ----
    __syncthreads();
    float* Osm = (float*)smem;   // [64][133] f32, reuses Q region (34 KB)
    {
        const int r = m0 + (lane >> 2);
#pragma unroll
        for (int n = 0; n < 8; n++) {
            int d = d0 + n * 8 + 2 * (lane & 3);
            Osm[r * 133 + d]           = oc[n][0];
            Osm[r * 133 + d + 1]       = oc[n][1];
            Osm[(r + 8) * 133 + d]     = oc[n][2];
            Osm[(r + 8) * 133 + d + 1] = oc[n][3];
        }
    }
    __syncthreads();

    float* ob = out + ((b * KCLS + kc) * DDIM) * PPIX + mt * 49;
    for (int idx = tid; idx < 128 * 49; idx += 256) {
        int d = idx / 49, m = idx - d * 49;
        ob[d * PPIX + m] = Osm[m * 133 + d] / dsumf[m];
    }
}

// ---------------------------------------------------------------------------
// kernel_launch
// ---------------------------------------------------------------------------
extern "C" void kernel_launch(void* const* d_in, const int* in_sizes, int n_in,
                              void* d_out, int out_size)
{
    const float* supp = (const float*)d_in[0];
    const float* qry  = (const float*)d_in[1];
    const float* Wqk  = (const float*)d_in[3];
    const float* Wv   = (const float*)d_in[4];
    float* out = (float*)d_out;

    cudaFuncSetAttribute(attn_kernel,
                         cudaFuncAttributeMaxDynamicSharedMemorySize, ATT_SMEM);

    proj_kernel<<<dim3(7, NSUP + BQ), 256>>>(supp, qry, Wqk, Wv, out + OUT1);
    attn_kernel<<<dim3(4, KCLS, BQ), 256, ATT_SMEM>>>(out);
}

// round 7
// speedup vs baseline: 3.0359x; 1.2601x over previous
#include <cuda_runtime.h>
#include <cuda_bf16.h>
#include <cstdint>
#include <math.h>

// ---------------------------------------------------------------------------
// Problem constants
// ---------------------------------------------------------------------------
#define BQ 32
#define NSUP 25
#define KCLS 5
#define CIN 512
#define PPIX 196
#define DDIM 128
#define KEYS 980
#define OUT1 (BQ * KCLS * DDIM * PPIX)
#define MTOT (BQ * PPIX)          // 6272 flattened queries
#define NTILE 98                  // 6272 / 64 dense m-tiles

// bf16 hi/lo split scratch (device globals — no allocation allowed)
__device__ __align__(16) __nv_bfloat16 g_qh[MTOT * DDIM];         // [g][d]
__device__ __align__(16) __nv_bfloat16 g_ql[MTOT * DDIM];
__device__ __align__(16) __nv_bfloat16 g_kh[NSUP * PPIX * DDIM];  // [gkey][d]
__device__ __align__(16) __nv_bfloat16 g_kl[NSUP * PPIX * DDIM];
__device__ __align__(16) __nv_bfloat16 g_vh[NSUP * DDIM * PPIX];  // [n][d][pix]
__device__ __align__(16) __nv_bfloat16 g_vl[NSUP * DDIM * PPIX];

// ---------------------------------------------------------------------------
// mma.sync / ldmatrix helpers (baseline PTX, legal on plain sm_103)
// ---------------------------------------------------------------------------
__device__ __forceinline__ void ldsm4(uint32_t addr, uint32_t r[4]) {
    asm volatile("ldmatrix.sync.aligned.m8n8.x4.shared.b16 {%0,%1,%2,%3}, [%4];"
                 : "=r"(r[0]), "=r"(r[1]), "=r"(r[2]), "=r"(r[3]) : "r"(addr));
}
__device__ __forceinline__ void mma16816(float c[4], const uint32_t a[4],
                                         uint32_t b0, uint32_t b1) {
    asm volatile("mma.sync.aligned.m16n8k16.row.col.f32.bf16.bf16.f32 "
                 "{%0,%1,%2,%3}, {%4,%5,%6,%7}, {%8,%9}, {%0,%1,%2,%3};"
                 : "+f"(c[0]), "+f"(c[1]), "+f"(c[2]), "+f"(c[3])
                 : "r"(a[0]), "r"(a[1]), "r"(a[2]), "r"(a[3]), "r"(b0), "r"(b1));
}
__device__ __forceinline__ uint32_t smem_u32(const void* p) {
    uint32_t a;
    asm("{ .reg .u64 t; cvta.to.shared.u64 t, %1; cvt.u32.u64 %0, t; }"
        : "=r"(a) : "l"(p));
    return a;
}
__device__ __forceinline__ uint32_t packbf(float e0, float e1) {
    uint32_t r;   // lower half = e0
    asm("cvt.rn.bf16x2.f32 %0, %1, %2;" : "=r"(r) : "f"(e1), "f"(e0));
    return r;
}

// ---------------------------------------------------------------------------
// Projection: channel-mixing GEMM + bf16 hi/lo split emission.
// grid = (7 pixel-tiles of 28, 57 images). block = 256 = 128 d x 2 halves.
// ---------------------------------------------------------------------------
__global__ __launch_bounds__(256) void proj_kernel(
    const float* __restrict__ supp, const float* __restrict__ qry,
    const float* __restrict__ Wq, const float* __restrict__ Wv,
    float* __restrict__ outv_ext)
{
    __shared__ float Wqs[32][129];
    __shared__ float Wvs[32][129];
    __shared__ float xs[32][28];

    const int tid = threadIdx.x;
    const int d = tid & 127;
    const int half = tid >> 7;
    const int img = blockIdx.y;
    const bool is_supp = img < NSUP;
    const float* x = is_supp ? supp + img * (CIN * PPIX)
                             : qry + (img - NSUP) * (CIN * PPIX);
    const int p0 = blockIdx.x * 28;
    const int pp = p0 + half * 14;

    float accq[14], accv[14];
#pragma unroll
    for (int i = 0; i < 14; i++) { accq[i] = 0.f; accv[i] = 0.f; }

    for (int c0 = 0; c0 < CIN; c0 += 32) {
        __syncthreads();
        for (int idx = tid; idx < 32 * 128; idx += 256) {
            int dd = idx >> 5, c = idx & 31;
            Wqs[c][dd] = Wq[dd * CIN + c0 + c];
            Wvs[c][dd] = Wv[dd * CIN + c0 + c];
        }
        for (int idx = tid; idx < 32 * 28; idx += 256) {
            int c = idx / 28, i = idx - c * 28;
            xs[c][i] = x[(c0 + c) * PPIX + p0 + i];
        }
        __syncthreads();
#pragma unroll 8
        for (int c = 0; c < 32; c++) {
            float wq = Wqs[c][d];
            float wv = Wvs[c][d];
#pragma unroll
            for (int i = 0; i < 14; i++) {
                float xi = xs[c][half * 14 + i];
                accq[i] = fmaf(xi, wq, accq[i]);
                accv[i] = fmaf(xi, wv, accv[i]);
            }
        }
    }

    if (is_supp) {
#pragma unroll
        for (int i = 0; i < 14; i++) {
            float q = accq[i];
            __nv_bfloat16 qh = __float2bfloat16(q);
            int kidx = (img * PPIX + pp + i) * DDIM + d;
            g_kh[kidx] = qh;
            g_kl[kidx] = __float2bfloat16(q - __bfloat162float(qh));
            float v = accv[i];
            __nv_bfloat16 vh = __float2bfloat16(v);
            int vidx = (img * DDIM + d) * PPIX + pp + i;
            g_vh[vidx] = vh;
            g_vl[vidx] = __float2bfloat16(v - __bfloat162float(vh));
        }
    } else {
        int qi = img - NSUP;
        float* ov = outv_ext + qi * (DDIM * PPIX) + d * PPIX + pp;
#pragma unroll
        for (int i = 0; i < 14; i++) {
            float q = accq[i];
            __nv_bfloat16 qh = __float2bfloat16(q);
            int qidx = (qi * PPIX + pp + i) * DDIM + d;
            g_qh[qidx] = qh;
            g_ql[qidx] = __float2bfloat16(q - __bfloat162float(qh));
            ov[i] = accv[i];
        }
    }
}

// ---------------------------------------------------------------------------
// mma.sync attention, DENSE m-packing: all 32*196 = 6272 queries per class
// flattened into 98 fully-dense tiles of 64 (rows may span two b images —
// only the output mapping cares). grid = (98, 5) = 490 CTAs, block 256,
// 2 CTAs/SM. 31 chunks x 32 keys (980 valid; key-pads masked exactly).
// S warps: 4m(16) x 2j(16).  PV warps: 2m(32) x 4d(32), O held in regs.
// ---------------------------------------------------------------------------
#define NCHUNK 31
#define QROW 272            // 128 bf16 + 16B pad (conflict-free ldmatrix)
#define EROW 80             // 32 bf16 + 16B pad
#define OFF_QH 0
#define OFF_QL 17408
#define OFF_KH 34816
#define OFF_KL 43520
#define OFF_VH 52224
#define OFF_VL 62464
#define OFF_EH 72704
#define OFF_EL 77824
#define OFF_DS 82944
#define ATT_SMEM (OFF_DS + 256)

__global__ __launch_bounds__(256, 2) void attn_kernel(float* __restrict__ out)
{
    extern __shared__ char smem[];
    const uint32_t sb = smem_u32(smem);
    float* dsumf = (float*)(smem + OFF_DS);

    const int tid = threadIdx.x;
    const int lane = tid & 31;
    const int warp = tid >> 5;
    const int tile = blockIdx.x, kc = blockIdx.y;

    const int m0 = (warp & 3) * 16;      // S warp m base
    const int j0 = (warp >> 2) * 16;     // S warp j base
    const int pm0 = (warp & 1) * 32;     // PV warp m base
    const int pd0 = (warp >> 1) * 32;    // PV warp d base

    // ldmatrix lane addressing
    const int a_row = lane & 15;
    const int a_off = (lane >> 4) << 4;
    const int b_row = (lane & 7) | ((lane >> 4) << 3);
    const int b_off = ((lane >> 3) & 1) << 4;

    const uint32_t* qh32 = (const uint32_t*)g_qh;
    const uint32_t* ql32 = (const uint32_t*)g_ql;
    const uint32_t* kh32 = (const uint32_t*)g_kh;
    const uint32_t* kl32 = (const uint32_t*)g_kl;
    const uint32_t* vh32 = (const uint32_t*)g_vh;
    const uint32_t* vl32 = (const uint32_t*)g_vl;

    // ---- stage Q (hi/lo): 64 dense rows, flat index tile*64 + r ----
    for (int idx = tid; idx < 64 * 64; idx += 256) {
        int r = idx >> 6, w = idx & 63;
        int gi = (tile * 64 + r) * 64 + w;
        *(uint32_t*)(smem + OFF_QH + r * QROW + w * 4) = qh32[gi];
        *(uint32_t*)(smem + OFF_QL + r * QROW + w * 4) = ql32[gi];
    }
    if (tid < 64) dsumf[tid] = 0.f;

    // PV accumulators (persist across chunks): O[32m x 32d] per warp
    float oc[2][4][4];
#pragma unroll
    for (int mi = 0; mi < 2; mi++)
#pragma unroll
        for (int n = 0; n < 4; n++)
#pragma unroll
            for (int q = 0; q < 4; q++) oc[mi][n][q] = 0.f;

    for (int ch = 0; ch < NCHUNK; ch++) {
        __syncthreads();   // prior chunk's reads of K/V/E done before restage

        // ---- stage K chunk (32 key-rows, hi/lo) ----
        for (int idx = tid; idx < 32 * 64; idx += 256) {
            int j = idx >> 6, w = idx & 63;
            int loc = ch * 32 + j;
            uint32_t vh = 0, vl = 0;
            if (loc < KEYS) {
                int gi = (kc * KEYS + loc) * 64 + w;
                vh = kh32[gi];
                vl = kl32[gi];
            }
            *(uint32_t*)(smem + OFF_KH + j * QROW + w * 4) = vh;
            *(uint32_t*)(smem + OFF_KL + j * QROW + w * 4) = vl;
        }
        // ---- stage V^T chunk (128 d-rows x 32 keys, hi/lo) ----
        for (int idx = tid; idx < 128 * 16; idx += 256) {
            int d = idx >> 4, w = idx & 15;
            int loc = ch * 32 + 2 * w;
            uint32_t vh = 0, vl = 0;
            if (loc < KEYS) {
                int g = kc * KEYS + loc;
                int n = g / PPIX, pix = g - n * PPIX;
                int gi = (n * DDIM + d) * 98 + (pix >> 1);
                vh = vh32[gi];
                vl = vl32[gi];
            }
            *(uint32_t*)(smem + OFF_VH + d * EROW + w * 4) = vh;
            *(uint32_t*)(smem + OFF_VL + d * EROW + w * 4) = vl;
        }
        __syncthreads();

        // ---- S = Qh.Kh^T + Qh.Kl^T + Ql.Kh^T  (16m x 16j per warp) ----
        float sc[2][4];
#pragma unroll
        for (int n = 0; n < 2; n++)
#pragma unroll
            for (int q = 0; q < 4; q++) sc[n][q] = 0.f;

#pragma unroll
        for (int k = 0; k < 8; k++) {
            const int kb = k * 32;
            uint32_t ah[4], al[4], bh[4], bl[4];
            uint32_t ra = sb + OFF_QH + (m0 + a_row) * QROW + kb + a_off;
            ldsm4(ra, ah);
            ldsm4(ra + (OFF_QL - OFF_QH), al);
            uint32_t rb = sb + OFF_KH + (j0 + b_row) * QROW + kb + b_off;
            ldsm4(rb, bh);
            ldsm4(rb + (OFF_KL - OFF_KH), bl);
#pragma unroll
            for (int n = 0; n < 2; n++) {
                mma16816(sc[n], ah, bh[n * 2], bh[n * 2 + 1]);
                mma16816(sc[n], ah, bl[n * 2], bl[n * 2 + 1]);
                mma16816(sc[n], al, bh[n * 2], bh[n * 2 + 1]);
            }
        }

        // ---- exp + exact key-pad mask; E hi/lo -> smem; row sums ----
        {
            float rs0 = 0.f, rs1 = 0.f;
            const int r = m0 + (lane >> 2);
#pragma unroll
            for (int n = 0; n < 2; n++) {
                int jl = j0 + n * 8 + 2 * (lane & 3);
                int jg = ch * 32 + jl;
                float e0 = (jg     < KEYS) ? __expf(sc[n][0]) : 0.f;
                float e1 = (jg + 1 < KEYS) ? __expf(sc[n][1]) : 0.f;
                float e2 = (jg     < KEYS) ? __expf(sc[n][2]) : 0.f;
                float e3 = (jg + 1 < KEYS) ? __expf(sc[n][3]) : 0.f;
                rs0 += e0 + e1;
                rs1 += e2 + e3;
                float h0 = __bfloat162float(__float2bfloat16(e0));
                float h1 = __bfloat162float(__float2bfloat16(e1));
                float h2 = __bfloat162float(__float2bfloat16(e2));
                float h3 = __bfloat162float(__float2bfloat16(e3));
                *(uint32_t*)(smem + OFF_EH + r * EROW + jl * 2)       = packbf(h0, h1);
                *(uint32_t*)(smem + OFF_EH + (r + 8) * EROW + jl * 2) = packbf(h2, h3);
                *(uint32_t*)(smem + OFF_EL + r * EROW + jl * 2)       = packbf(e0 - h0, e1 - h1);
                *(uint32_t*)(smem + OFF_EL + (r + 8) * EROW + jl * 2) = packbf(e2 - h2, e3 - h3);
            }
            rs0 += __shfl_xor_sync(0xFFFFFFFFu, rs0, 1);
            rs0 += __shfl_xor_sync(0xFFFFFFFFu, rs0, 2);
            rs1 += __shfl_xor_sync(0xFFFFFFFFu, rs1, 1);
            rs1 += __shfl_xor_sync(0xFFFFFFFFu, rs1, 2);
            if ((lane & 3) == 0) {
                atomicAdd(&dsumf[r], rs0);
                atomicAdd(&dsumf[r + 8], rs1);
            }
        }
        __syncthreads();   // E visible to all warps

        // ---- O += Eh.Vh + Eh.Vl + El.Vh  (32m x 32d per warp) ----
#pragma unroll
        for (int kj = 0; kj < 2; kj++) {
            const int kb = kj * 32;    // 16 keys
            uint32_t eh[2][4], el[2][4], vvh[2][4], vvl[2][4];
#pragma unroll
            for (int mi = 0; mi < 2; mi++) {
                uint32_t ra = sb + OFF_EH + (pm0 + mi * 16 + a_row) * EROW + kb + a_off;
                ldsm4(ra, eh[mi]);
                ldsm4(ra + (OFF_EL - OFF_EH), el[mi]);
            }
#pragma unroll
            for (int nd = 0; nd < 2; nd++) {
                uint32_t rb = sb + OFF_VH + (pd0 + nd * 16 + b_row) * EROW + kb + b_off;
                ldsm4(rb, vvh[nd]);
                ldsm4(rb + (OFF_VL - OFF_VH), vvl[nd]);
            }
#pragma unroll
            for (int mi = 0; mi < 2; mi++)
#pragma unroll
                for (int n = 0; n < 4; n++) {
                    uint32_t h0 = vvh[n >> 1][(n & 1) * 2], h1 = vvh[n >> 1][(n & 1) * 2 + 1];
                    uint32_t l0 = vvl[n >> 1][(n & 1) * 2], l1 = vvl[n >> 1][(n & 1) * 2 + 1];
                    mma16816(oc[mi][n], eh[mi], h0, h1);
                    mma16816(oc[mi][n], eh[mi], l0, l1);
                    mma16816(oc[mi][n], el[mi], h0, h1);
                }
        }
    }

    // ---- epilogue: O frags -> smem (pad 133) -> normalized coalesced out ----
    __syncthreads();
    float* Osm = (float*)smem;   // [64][133] f32, reuses Q region (34 KB)
#pragma unroll
    for (int mi = 0; mi < 2; mi++) {
        const int r = pm0 + mi * 16 + (lane >> 2);
#pragma unroll
        for (int n = 0; n < 4; n++) {
            int d = pd0 + n * 8 + 2 * (lane & 3);
            Osm[r * 133 + d]           = oc[mi][n][0];
            Osm[r * 133 + d + 1]       = oc[mi][n][1];
            Osm[(r + 8) * 133 + d]     = oc[mi][n][2];
            Osm[(r + 8) * 133 + d + 1] = oc[mi][n][3];
        }
    }
    __syncthreads();

    // row m -> global query g = tile*64 + m -> (b, p); out[b][kc][d*196+p]
    for (int idx = tid; idx < 128 * 64; idx += 256) {
        int d = idx >> 6, m = idx & 63;
        int g = tile * 64 + m;
        int bb = g / PPIX, p = g - bb * PPIX;
        out[((bb * KCLS + kc) * DDIM + d) * PPIX + p] = Osm[m * 133 + d] / dsumf[m];
    }
}

// ---------------------------------------------------------------------------
// kernel_launch
// ---------------------------------------------------------------------------
extern "C" void kernel_launch(void* const* d_in, const int* in_sizes, int n_in,
                              void* d_out, int out_size)
{
    const float* supp = (const float*)d_in[0];
    const float* qry  = (const float*)d_in[1];
    const float* Wqk  = (const float*)d_in[3];
    const float* Wv   = (const float*)d_in[4];
    float* out = (float*)d_out;

    cudaFuncSetAttribute(attn_kernel,
                         cudaFuncAttributeMaxDynamicSharedMemorySize, ATT_SMEM);

    proj_kernel<<<dim3(7, NSUP + BQ), 256>>>(supp, qry, Wqk, Wv, out + OUT1);
    attn_kernel<<<dim3(NTILE, KCLS), 256, ATT_SMEM>>>(out);
}

// round 8
// speedup vs baseline: 3.7580x; 1.2378x over previous
#include <cuda_runtime.h>
#include <cuda_bf16.h>
#include <cstdint>
#include <math.h>

// ---------------------------------------------------------------------------
// Problem constants
// ---------------------------------------------------------------------------
#define BQ 32
#define NSUP 25
#define KCLS 5
#define CIN 512
#define PPIX 196
#define DDIM 128
#define KEYS 980
#define OUT1 (BQ * KCLS * DDIM * PPIX)
#define MTOT (BQ * PPIX)          // 6272 flattened queries
#define NTILE 98                  // 6272 / 64 dense m-tiles
#define KROWS (NSUP * PPIX + 64)  // K rows padded so last chunk never faults

// bf16 hi/lo split scratch (device globals — zero-initialized, no alloc)
__device__ __align__(16) __nv_bfloat16 g_qh[MTOT * DDIM];          // [g][d]
__device__ __align__(16) __nv_bfloat16 g_ql[MTOT * DDIM];
__device__ __align__(16) __nv_bfloat16 g_kh[KROWS * DDIM];         // [kc*980+loc][d]
__device__ __align__(16) __nv_bfloat16 g_kl[KROWS * DDIM];
__device__ __align__(16) __nv_bfloat16 g_vth[KCLS * DDIM * 1024];  // [kc][d][slot]
__device__ __align__(16) __nv_bfloat16 g_vtl[KCLS * DDIM * 1024];  // pads stay 0

// ---------------------------------------------------------------------------
// PTX helpers (baseline PTX, legal on plain sm_103)
// ---------------------------------------------------------------------------
__device__ __forceinline__ void ldsm4(uint32_t addr, uint32_t r[4]) {
    asm volatile("ldmatrix.sync.aligned.m8n8.x4.shared.b16 {%0,%1,%2,%3}, [%4];"
                 : "=r"(r[0]), "=r"(r[1]), "=r"(r[2]), "=r"(r[3]) : "r"(addr));
}
__device__ __forceinline__ void mma16816(float c[4], const uint32_t a[4],
                                         uint32_t b0, uint32_t b1) {
    asm volatile("mma.sync.aligned.m16n8k16.row.col.f32.bf16.bf16.f32 "
                 "{%0,%1,%2,%3}, {%4,%5,%6,%7}, {%8,%9}, {%0,%1,%2,%3};"
                 : "+f"(c[0]), "+f"(c[1]), "+f"(c[2]), "+f"(c[3])
                 : "r"(a[0]), "r"(a[1]), "r"(a[2]), "r"(a[3]), "r"(b0), "r"(b1));
}
__device__ __forceinline__ uint32_t smem_u32(const void* p) {
    uint32_t a;
    asm("{ .reg .u64 t; cvta.to.shared.u64 t, %1; cvt.u32.u64 %0, t; }"
        : "=r"(a) : "l"(p));
    return a;
}
__device__ __forceinline__ uint32_t packbf(float e0, float e1) {
    uint32_t r;   // lower half = e0
    asm("cvt.rn.bf16x2.f32 %0, %1, %2;" : "=r"(r) : "f"(e1), "f"(e0));
    return r;
}
#define CPA16(dst, src) \
    asm volatile("cp.async.ca.shared.global [%0], [%1], 16;" \
                 :: "r"(dst), "l"(src))
#define CPA_COMMIT() asm volatile("cp.async.commit_group;" ::: "memory")
#define CPA_WAIT0()  asm volatile("cp.async.wait_group 0;" ::: "memory")

// ---------------------------------------------------------------------------
// Projection: channel-mixing GEMM + bf16 hi/lo split emission.
// grid = (7 pixel-tiles of 28, 57 images). block = 256 = 128 d x 2 halves.
// ---------------------------------------------------------------------------
__global__ __launch_bounds__(256) void proj_kernel(
    const float* __restrict__ supp, const float* __restrict__ qry,
    const float* __restrict__ Wq, const float* __restrict__ Wv,
    float* __restrict__ outv_ext)
{
    __shared__ float Wqs[32][129];
    __shared__ float Wvs[32][129];
    __shared__ float xs[32][28];

    const int tid = threadIdx.x;
    const int d = tid & 127;
    const int half = tid >> 7;
    const int img = blockIdx.y;
    const bool is_supp = img < NSUP;
    const float* x = is_supp ? supp + img * (CIN * PPIX)
                             : qry + (img - NSUP) * (CIN * PPIX);
    const int p0 = blockIdx.x * 28;
    const int pp = p0 + half * 14;

    float accq[14], accv[14];
#pragma unroll
    for (int i = 0; i < 14; i++) { accq[i] = 0.f; accv[i] = 0.f; }

    for (int c0 = 0; c0 < CIN; c0 += 32) {
        __syncthreads();
        for (int idx = tid; idx < 32 * 128; idx += 256) {
            int dd = idx >> 5, c = idx & 31;
            Wqs[c][dd] = Wq[dd * CIN + c0 + c];
            Wvs[c][dd] = Wv[dd * CIN + c0 + c];
        }
        for (int idx = tid; idx < 32 * 28; idx += 256) {
            int c = idx / 28, i = idx - c * 28;
            xs[c][i] = x[(c0 + c) * PPIX + p0 + i];
        }
        __syncthreads();
#pragma unroll 8
        for (int c = 0; c < 32; c++) {
            float wq = Wqs[c][d];
            float wv = Wvs[c][d];
#pragma unroll
            for (int i = 0; i < 14; i++) {
                float xi = xs[c][half * 14 + i];
                accq[i] = fmaf(xi, wq, accq[i]);
                accv[i] = fmaf(xi, wv, accv[i]);
            }
        }
    }

    if (is_supp) {
        const int cls = img / 5, s = img - cls * 5;
#pragma unroll
        for (int i = 0; i < 14; i++) {
            float q = accq[i];
            __nv_bfloat16 qh = __float2bfloat16(q);
            int kidx = (img * PPIX + pp + i) * DDIM + d;
            g_kh[kidx] = qh;
            g_kl[kidx] = __float2bfloat16(q - __bfloat162float(qh));
            float v = accv[i];
            __nv_bfloat16 vh = __float2bfloat16(v);
            int vidx = (cls * DDIM + d) * 1024 + s * PPIX + pp + i;
            g_vth[vidx] = vh;
            g_vtl[vidx] = __float2bfloat16(v - __bfloat162float(vh));
        }
    } else {
        int qi = img - NSUP;
        float* ov = outv_ext + qi * (DDIM * PPIX) + d * PPIX + pp;
#pragma unroll
        for (int i = 0; i < 14; i++) {
            float q = accq[i];
            __nv_bfloat16 qh = __float2bfloat16(q);
            int qidx = (qi * PPIX + pp + i) * DDIM + d;
            g_qh[qidx] = qh;
            g_ql[qidx] = __float2bfloat16(q - __bfloat162float(qh));
            ov[i] = accv[i];
        }
    }
}

// ---------------------------------------------------------------------------
// FlashAttention-style mma.sync attention: E stays in registers.
// grid = (98 dense m-tiles of 64, 5 classes). block = 256, 2 CTAs/SM.
// 16 chunks x 64 keys. Warp w: m-rows (w&3)*16, key-half (w>>2)*32.
// Per chunk: S[16m x 32j] C-frags -> exp -> bf16 hi/lo A-frags (registers)
// -> PV accumulates O[16m x 128d] per warp. Epilogue sums key-half partners.
// ---------------------------------------------------------------------------
#define NCHUNK 16
#define QROW 272            // 128 bf16 + 16B pad
#define VROW 144            // 64 bf16 + 16B pad
#define OFF_QH 0
#define OFF_QL 17408
#define OFF_KH 34816
#define OFF_KL 52224
#define OFF_VH 69632
#define OFF_VL 88064
#define OFF_DS 106496
#define ATT_SMEM (OFF_DS + 256)

__global__ __launch_bounds__(256, 2) void attn_kernel(float* __restrict__ out)
{
    extern __shared__ char smem[];
    const uint32_t sb = smem_u32(smem);
    float* dsumf = (float*)(smem + OFF_DS);

    const int tid = threadIdx.x;
    const int lane = tid & 31;
    const int warp = tid >> 5;
    const int tile = blockIdx.x, kc = blockIdx.y;

    const int m0 = (warp & 3) * 16;      // warp m base
    const int h32 = (warp >> 2) * 32;    // warp key-half base within chunk

    // ldmatrix lane addressing
    const int a_row = lane & 15;
    const int a_off = (lane >> 4) << 4;
    const int b_row = (lane & 7) | ((lane >> 4) << 3);
    const int b_off = ((lane >> 3) & 1) << 4;

    // ---- stage Q (hi/lo) via cp.async: 64 dense rows ----
    {
        const char* qh8 = (const char*)(g_qh + (size_t)tile * 64 * DDIM);
        const char* ql8 = (const char*)(g_ql + (size_t)tile * 64 * DDIM);
        for (int idx = tid; idx < 64 * 16; idx += 256) {
            int r = idx >> 4, seg = idx & 15;
            CPA16(sb + OFF_QH + r * QROW + seg * 16, qh8 + r * 256 + seg * 16);
            CPA16(sb + OFF_QL + r * QROW + seg * 16, ql8 + r * 256 + seg * 16);
        }
    }
    if (tid < 64) dsumf[tid] = 0.f;

    // O accumulators: [16m x 128d] per warp (16 n-tiles x 4 regs)
    float oc[16][4];
#pragma unroll
    for (int n = 0; n < 16; n++)
#pragma unroll
        for (int q = 0; q < 4; q++) oc[n][q] = 0.f;

    const char* kh8 = (const char*)(g_kh + (size_t)kc * KEYS * DDIM);
    const char* kl8 = (const char*)(g_kl + (size_t)kc * KEYS * DDIM);
    const char* vh8 = (const char*)(g_vth + (size_t)kc * DDIM * 1024);
    const char* vl8 = (const char*)(g_vtl + (size_t)kc * DDIM * 1024);

    for (int ch = 0; ch < NCHUNK; ch++) {
        __syncthreads();   // prior chunk's reads of K/V smem complete

        // ---- stage K chunk (64 rows x 128 bf16, hi/lo) via cp.async ----
        for (int idx = tid; idx < 64 * 16; idx += 256) {
            int j = idx >> 4, seg = idx & 15;
            const size_t so = (size_t)(ch * 64 + j) * 256 + seg * 16;
            CPA16(sb + OFF_KH + j * QROW + seg * 16, kh8 + so);
            CPA16(sb + OFF_KL + j * QROW + seg * 16, kl8 + so);
        }
        // ---- stage V^T chunk (128 d-rows x 64 keys, hi/lo) ----
        for (int idx = tid; idx < 128 * 8; idx += 256) {
            int d = idx >> 3, seg = idx & 7;
            const size_t so = (size_t)d * 2048 + ch * 128 + seg * 16;
            CPA16(sb + OFF_VH + d * VROW + seg * 16, vh8 + so);
            CPA16(sb + OFF_VL + d * VROW + seg * 16, vl8 + so);
        }
        CPA_COMMIT();
        CPA_WAIT0();
        __syncthreads();

        // ---- S = Qh.Kh^T + Qh.Kl^T + Ql.Kh^T  (16m x 32j per warp) ----
        float sc[4][4];
#pragma unroll
        for (int n = 0; n < 4; n++)
#pragma unroll
            for (int q = 0; q < 4; q++) sc[n][q] = 0.f;

#pragma unroll
        for (int k = 0; k < 8; k++) {
            const int kb = k * 32;
            uint32_t ah[4], al[4], bh0[4], bh1[4], bl0[4], bl1[4];
            uint32_t ra = sb + OFF_QH + (m0 + a_row) * QROW + kb + a_off;
            ldsm4(ra, ah);
            ldsm4(ra + (OFF_QL - OFF_QH), al);
            uint32_t rb = sb + OFF_KH + (h32 + b_row) * QROW + kb + b_off;
            ldsm4(rb, bh0);
            ldsm4(rb + 16 * QROW, bh1);
            ldsm4(rb + (OFF_KL - OFF_KH), bl0);
            ldsm4(rb + (OFF_KL - OFF_KH) + 16 * QROW, bl1);
#pragma unroll
            for (int n = 0; n < 4; n++) {
                uint32_t h0 = (n < 2) ? bh0[(n & 1) * 2] : bh1[(n & 1) * 2];
                uint32_t h1 = (n < 2) ? bh0[(n & 1) * 2 + 1] : bh1[(n & 1) * 2 + 1];
                uint32_t l0 = (n < 2) ? bl0[(n & 1) * 2] : bl1[(n & 1) * 2];
                uint32_t l1 = (n < 2) ? bl0[(n & 1) * 2 + 1] : bl1[(n & 1) * 2 + 1];
                mma16816(sc[n], ah, h0, h1);
                mma16816(sc[n], ah, l0, l1);
                mma16816(sc[n], al, h0, h1);
            }
        }

        // ---- exp (exact key mask) -> row sums -> E A-frags in registers ----
        uint32_t ehf[2][4], elf[2][4];
        {
            float rs0 = 0.f, rs1 = 0.f;
            const int r = m0 + (lane >> 2);
#pragma unroll
            for (int n = 0; n < 4; n++) {
                int jg = ch * 64 + h32 + n * 8 + 2 * (lane & 3);
                float e0 = (jg     < KEYS) ? __expf(sc[n][0]) : 0.f;
                float e1 = (jg + 1 < KEYS) ? __expf(sc[n][1]) : 0.f;
                float e2 = (jg     < KEYS) ? __expf(sc[n][2]) : 0.f;
                float e3 = (jg + 1 < KEYS) ? __expf(sc[n][3]) : 0.f;
                rs0 += e0 + e1;
                rs1 += e2 + e3;
                float h0 = __bfloat162float(__float2bfloat16(e0));
                float h1 = __bfloat162float(__float2bfloat16(e1));
                float h2 = __bfloat162float(__float2bfloat16(e2));
                float h3 = __bfloat162float(__float2bfloat16(e3));
                // C(m16n8) tile n -> A(m16k16) frag [n/2], regs (n&1)*2 .. +1
                ehf[n >> 1][(n & 1) * 2]     = packbf(h0, h1);
                ehf[n >> 1][(n & 1) * 2 + 1] = packbf(h2, h3);
                elf[n >> 1][(n & 1) * 2]     = packbf(e0 - h0, e1 - h1);
                elf[n >> 1][(n & 1) * 2 + 1] = packbf(e2 - h2, e3 - h3);
            }
            rs0 += __shfl_xor_sync(0xFFFFFFFFu, rs0, 1);
            rs0 += __shfl_xor_sync(0xFFFFFFFFu, rs0, 2);
            rs1 += __shfl_xor_sync(0xFFFFFFFFu, rs1, 1);
            rs1 += __shfl_xor_sync(0xFFFFFFFFu, rs1, 2);
            if ((lane & 3) == 0) {
                atomicAdd(&dsumf[r], rs0);
                atomicAdd(&dsumf[r + 8], rs1);
            }
        }

        // ---- O += Eh.Vh + El.Vh + Eh.Vl  (16m x 128d, E from registers) ----
#pragma unroll
        for (int kk = 0; kk < 2; kk++) {
            const int kcol = (h32 + kk * 16) * 2;   // byte col of this k-step
#pragma unroll
            for (int dh = 0; dh < 2; dh++) {
                uint32_t vv[4][4];
#pragma unroll
                for (int nd = 0; nd < 4; nd++)
                    ldsm4(sb + OFF_VH + (dh * 64 + nd * 16 + b_row) * VROW + kcol + b_off,
                          vv[nd]);
#pragma unroll
                for (int nd = 0; nd < 4; nd++)
#pragma unroll
                    for (int t = 0; t < 2; t++) {
                        float* o = oc[dh * 8 + nd * 2 + t];
                        mma16816(o, ehf[kk], vv[nd][t * 2], vv[nd][t * 2 + 1]);
                        mma16816(o, elf[kk], vv[nd][t * 2], vv[nd][t * 2 + 1]);
                    }
#pragma unroll
                for (int nd = 0; nd < 4; nd++)
                    ldsm4(sb + OFF_VL + (dh * 64 + nd * 16 + b_row) * VROW + kcol + b_off,
                          vv[nd]);
#pragma unroll
                for (int nd = 0; nd < 4; nd++)
#pragma unroll
                    for (int t = 0; t < 2; t++)
                        mma16816(oc[dh * 8 + nd * 2 + t], ehf[kk],
                                 vv[nd][t * 2], vv[nd][t * 2 + 1]);
            }
        }
    }

    // ---- epilogue: sum key-half partners via smem, normalize, write ----
    __syncthreads();
    float* Osm = (float*)smem;   // [64][133] f32, reuses Q/K region
    const int r = m0 + (lane >> 2);
    if (warp < 4) {
#pragma unroll
        for (int n = 0; n < 16; n++) {
            int d = n * 8 + 2 * (lane & 3);
            Osm[r * 133 + d]           = oc[n][0];
            Osm[r * 133 + d + 1]       = oc[n][1];
            Osm[(r + 8) * 133 + d]     = oc[n][2];
            Osm[(r + 8) * 133 + d + 1] = oc[n][3];
        }
    }
    __syncthreads();
    if (warp >= 4) {
#pragma unroll
        for (int n = 0; n < 16; n++) {
            int d = n * 8 + 2 * (lane & 3);
            Osm[r * 133 + d]           += oc[n][0];
            Osm[r * 133 + d + 1]       += oc[n][1];
            Osm[(r + 8) * 133 + d]     += oc[n][2];
            Osm[(r + 8) * 133 + d + 1] += oc[n][3];
        }
    }
    __syncthreads();

    // row m -> global query g = tile*64 + m -> (b, p); out[b][kc][d*196+p]
    for (int idx = tid; idx < 128 * 64; idx += 256) {
        int d = idx >> 6, m = idx & 63;
        int g = tile * 64 + m;
        int bb = g / PPIX, p = g - bb * PPIX;
        out[((bb * KCLS + kc) * DDIM + d) * PPIX + p] = Osm[m * 133 + d] / dsumf[m];
    }
}

// ---------------------------------------------------------------------------
// kernel_launch
// ---------------------------------------------------------------------------
extern "C" void kernel_launch(void* const* d_in, const int* in_sizes, int n_in,
                              void* d_out, int out_size)
{
    const float* supp = (const float*)d_in[0];
    const float* qry  = (const float*)d_in[1];
    const float* Wqk  = (const float*)d_in[3];
    const float* Wv   = (const float*)d_in[4];
    float* out = (float*)d_out;

    cudaFuncSetAttribute(attn_kernel,
                         cudaFuncAttributeMaxDynamicSharedMemorySize, ATT_SMEM);

    proj_kernel<<<dim3(7, NSUP + BQ), 256>>>(supp, qry, Wqk, Wv, out + OUT1);
    attn_kernel<<<dim3(NTILE, KCLS), 256, ATT_SMEM>>>(out);
}

// round 9
// speedup vs baseline: 4.7916x; 1.2750x over previous
#include <cuda_runtime.h>
#include <cuda_bf16.h>
#include <cstdint>
#include <math.h>

// ---------------------------------------------------------------------------
// Problem constants
// ---------------------------------------------------------------------------
#define BQ 32
#define NSUP 25
#define KCLS 5
#define CIN 512
#define PPIX 196
#define DDIM 128
#define KEYS 980
#define OUT1 (BQ * KCLS * DDIM * PPIX)
#define MTOT (BQ * PPIX)          // 6272 flattened queries
#define NTILE 98                  // 6272 / 64 dense m-tiles
#define KROWS (NSUP * PPIX + 64)  // K rows padded so last chunk never faults
#define GROWS 11200               // 175 x 64 dense proj rows (28 dead in middle)
#define GQBASE 4928               // queries start row (supports [0,4900))
#define NMT 175

// bf16 hi/lo split scratch (device globals — zero-initialized, no alloc)
__device__ __align__(16) __nv_bfloat16 g_xh[GROWS * CIN];          // [g][c]
__device__ __align__(16) __nv_bfloat16 g_xl[GROWS * CIN];
__device__ __align__(16) __nv_bfloat16 g_wh[2 * DDIM * CIN];       // [qv][d][c]
__device__ __align__(16) __nv_bfloat16 g_wl[2 * DDIM * CIN];
__device__ __align__(16) __nv_bfloat16 g_qh[MTOT * DDIM];          // [g][d]
__device__ __align__(16) __nv_bfloat16 g_ql[MTOT * DDIM];
__device__ __align__(16) __nv_bfloat16 g_kh[KROWS * DDIM];         // [gkey][d]
__device__ __align__(16) __nv_bfloat16 g_kl[KROWS * DDIM];
__device__ __align__(16) __nv_bfloat16 g_vth[KCLS * DDIM * 1024];  // [kc][d][slot]
__device__ __align__(16) __nv_bfloat16 g_vtl[KCLS * DDIM * 1024];  // pads stay 0

// ---------------------------------------------------------------------------
// PTX helpers (baseline PTX, legal on plain sm_103)
// ---------------------------------------------------------------------------
__device__ __forceinline__ void ldsm4(uint32_t addr, uint32_t r[4]) {
    asm volatile("ldmatrix.sync.aligned.m8n8.x4.shared.b16 {%0,%1,%2,%3}, [%4];"
                 : "=r"(r[0]), "=r"(r[1]), "=r"(r[2]), "=r"(r[3]) : "r"(addr));
}
__device__ __forceinline__ void mma16816(float c[4], const uint32_t a[4],
                                         uint32_t b0, uint32_t b1) {
    asm volatile("mma.sync.aligned.m16n8k16.row.col.f32.bf16.bf16.f32 "
                 "{%0,%1,%2,%3}, {%4,%5,%6,%7}, {%8,%9}, {%0,%1,%2,%3};"
                 : "+f"(c[0]), "+f"(c[1]), "+f"(c[2]), "+f"(c[3])
                 : "r"(a[0]), "r"(a[1]), "r"(a[2]), "r"(a[3]), "r"(b0), "r"(b1));
}
__device__ __forceinline__ uint32_t smem_u32(const void* p) {
    uint32_t a;
    asm("{ .reg .u64 t; cvta.to.shared.u64 t, %1; cvt.u32.u64 %0, t; }"
        : "=r"(a) : "l"(p));
    return a;
}
__device__ __forceinline__ uint32_t packbf(float e0, float e1) {
    uint32_t r;   // lower half = e0
    asm("cvt.rn.bf16x2.f32 %0, %1, %2;" : "=r"(r) : "f"(e1), "f"(e0));
    return r;
}
#define CPA16(dst, src) \
    asm volatile("cp.async.ca.shared.global [%0], [%1], 16;" \
                 :: "r"(dst), "l"(src))
#define CPA_COMMIT() asm volatile("cp.async.commit_group;" ::: "memory")
#define CPA_WAIT0()  asm volatile("cp.async.wait_group 0;" ::: "memory")

// ---------------------------------------------------------------------------
// xsplit: features [img][c][p] f32 -> dense transposed bf16 hi/lo [g][c].
// grid = (8 c-tiles of 64, 4 p-tiles of 49, 57 imgs). block = 256.
// ---------------------------------------------------------------------------
__global__ __launch_bounds__(256) void xsplit_kernel(
    const float* __restrict__ supp, const float* __restrict__ qry)
{
    __shared__ float xs[64][50];
    const int tid = threadIdx.x;
    const int img = blockIdx.z;
    const float* x = (img < NSUP) ? supp + (size_t)img * CIN * PPIX
                                  : qry + (size_t)(img - NSUP) * CIN * PPIX;
    const int c0 = blockIdx.x * 64, p0 = blockIdx.y * 49;

    for (int idx = tid; idx < 64 * 49; idx += 256) {
        int c = idx / 49, p = idx - c * 49;
        xs[c][p] = x[(c0 + c) * PPIX + p0 + p];
    }
    __syncthreads();

    const size_t gbase = (img < NSUP) ? (size_t)img * PPIX + p0
                                      : (size_t)GQBASE + (img - NSUP) * PPIX + p0;
    for (int idx = tid; idx < 49 * 64; idx += 256) {
        int p = idx / 64, c = idx - p * 64;
        float v = xs[c][p];
        __nv_bfloat16 h = __float2bfloat16(v);
        size_t o = (gbase + p) * CIN + c0 + c;
        g_xh[o] = h;
        g_xl[o] = __float2bfloat16(v - __bfloat162float(h));
    }
}

// ---------------------------------------------------------------------------
// wsplit: W_qk / W_v [128][512] f32 -> bf16 hi/lo. grid = (2, 16).
// ---------------------------------------------------------------------------
__global__ __launch_bounds__(256) void wsplit_kernel(
    const float* __restrict__ Wq, const float* __restrict__ Wv)
{
    const float* W = blockIdx.x ? Wv : Wq;
    const int base = blockIdx.y * 4096;
    for (int i = threadIdx.x; i < 4096; i += 256) {
        float v = W[base + i];
        __nv_bfloat16 h = __float2bfloat16(v);
        size_t o = (size_t)blockIdx.x * DDIM * CIN + base + i;
        g_wh[o] = h;
        g_wl[o] = __float2bfloat16(v - __bfloat162float(h));
    }
}

// ---------------------------------------------------------------------------
// projmma: out[g][d] = sum_c x[g][c] * W[d][c], 3-split bf16 HMMA.
// grid = (175 m-tiles of 64, 2 {qk,v}). block 256, 2 CTAs/SM.
// Warp w: m-rows (w&3)*16, d-cols (w>>2)*64. K = 512 in 8 chunks of 64.
// Epilogue qv=0: q/k bf16 splits straight from frags.
// Epilogue qv=1: smem transpose -> query_v fp32 out + support V^T splits.
// ---------------------------------------------------------------------------
#define AROW 144
#define P_AH 0
#define P_AL (64 * AROW)              // 9216
#define P_WH (2 * 64 * AROW)          // 18432
#define P_WL (P_WH + 128 * AROW)      // 36864
#define PROJ_SMEM (P_WL + 128 * AROW) // 55296

__global__ __launch_bounds__(256, 2) void projmma_kernel(float* __restrict__ outv)
{
    extern __shared__ char smem[];
    const uint32_t sb = smem_u32(smem);
    const int tid = threadIdx.x;
    const int lane = tid & 31;
    const int warp = tid >> 5;
    const int tile = blockIdx.x, qv = blockIdx.y;

    const int m0 = (warp & 3) * 16;
    const int n0 = (warp >> 2) * 64;

    const int a_row = lane & 15;
    const int a_off = (lane >> 4) << 4;
    const int b_row = (lane & 7) | ((lane >> 4) << 3);
    const int b_off = ((lane >> 3) & 1) << 4;

    float oc[8][4];
#pragma unroll
    for (int n = 0; n < 8; n++)
#pragma unroll
        for (int q = 0; q < 4; q++) oc[n][q] = 0.f;

    const char* xh8 = (const char*)(g_xh + (size_t)tile * 64 * CIN);
    const char* xl8 = (const char*)(g_xl + (size_t)tile * 64 * CIN);
    const char* wh8 = (const char*)(g_wh + (size_t)qv * DDIM * CIN);
    const char* wl8 = (const char*)(g_wl + (size_t)qv * DDIM * CIN);

    for (int ch = 0; ch < 8; ch++) {
        __syncthreads();
        for (int idx = tid; idx < 64 * 8; idx += 256) {
            int r = idx >> 3, seg = idx & 7;
            size_t so = (size_t)r * 1024 + ch * 128 + seg * 16;
            CPA16(sb + P_AH + r * AROW + seg * 16, xh8 + so);
            CPA16(sb + P_AL + r * AROW + seg * 16, xl8 + so);
        }
        for (int idx = tid; idx < 128 * 8; idx += 256) {
            int n = idx >> 3, seg = idx & 7;
            size_t so = (size_t)n * 1024 + ch * 128 + seg * 16;
            CPA16(sb + P_WH + n * AROW + seg * 16, wh8 + so);
            CPA16(sb + P_WL + n * AROW + seg * 16, wl8 + so);
        }
        CPA_COMMIT();
        CPA_WAIT0();
        __syncthreads();

#pragma unroll
        for (int ks = 0; ks < 4; ks++) {
            const int kb = ks * 32;
            uint32_t ah[4], al[4];
            uint32_t ra = sb + P_AH + (m0 + a_row) * AROW + kb + a_off;
            ldsm4(ra, ah);
            ldsm4(ra + (P_AL - P_AH), al);
#pragma unroll
            for (int nt = 0; nt < 4; nt++) {
                uint32_t bh[4], bl[4];
                uint32_t rb = sb + P_WH + (n0 + nt * 16 + b_row) * AROW + kb + b_off;
                ldsm4(rb, bh);
                ldsm4(rb + (P_WL - P_WH), bl);
#pragma unroll
                for (int t = 0; t < 2; t++) {
                    float* o = oc[nt * 2 + t];
                    mma16816(o, ah, bh[t * 2], bh[t * 2 + 1]);
                    mma16816(o, ah, bl[t * 2], bl[t * 2 + 1]);
                    mma16816(o, al, bh[t * 2], bh[t * 2 + 1]);
                }
            }
        }
    }

    const int gbase = tile * 64;
    if (qv == 0) {
        // q/k projection: split + packed 4B stores straight from frags
        uint32_t* kh32 = (uint32_t*)g_kh;
        uint32_t* kl32 = (uint32_t*)g_kl;
        uint32_t* qh32 = (uint32_t*)g_qh;
        uint32_t* ql32 = (uint32_t*)g_ql;
        const int r1 = m0 + (lane >> 2);
#pragma unroll
        for (int nt = 0; nt < 8; nt++) {
            const int d = n0 + nt * 8 + 2 * (lane & 3);
#pragma unroll
            for (int half = 0; half < 2; half++) {
                int g = gbase + r1 + half * 8;
                float c0 = oc[nt][half * 2], c1 = oc[nt][half * 2 + 1];
                float h0 = __bfloat162float(__float2bfloat16(c0));
                float h1 = __bfloat162float(__float2bfloat16(c1));
                uint32_t ph = packbf(h0, h1);
                uint32_t pl = packbf(c0 - h0, c1 - h1);
                if (g < NSUP * PPIX) {
                    int o = (g * DDIM + d) >> 1;
                    kh32[o] = ph;
                    kl32[o] = pl;
                } else if (g >= GQBASE) {
                    int o = ((g - GQBASE) * DDIM + d) >> 1;
                    qh32[o] = ph;
                    ql32[o] = pl;
                }
            }
        }
    } else {
        // v projection: transpose via smem, then query fp32 out / support splits
        __syncthreads();
        float* Osm = (float*)smem;   // [64][133]
        const int r = m0 + (lane >> 2);
#pragma unroll
        for (int nt = 0; nt < 8; nt++) {
            const int d = n0 + nt * 8 + 2 * (lane & 3);
            Osm[r * 133 + d]           = oc[nt][0];
            Osm[r * 133 + d + 1]       = oc[nt][1];
            Osm[(r + 8) * 133 + d]     = oc[nt][2];
            Osm[(r + 8) * 133 + d + 1] = oc[nt][3];
        }
        __syncthreads();
        for (int idx = tid; idx < 128 * 64; idx += 256) {
            int d = idx >> 6, m = idx & 63;
            int g = gbase + m;
            float v = Osm[m * 133 + d];
            if (g < NSUP * PPIX) {
                int img = g / PPIX, p = g - img * PPIX;
                int cls = img / 5, s = img - cls * 5;
                __nv_bfloat16 h = __float2bfloat16(v);
                size_t o = ((size_t)cls * DDIM + d) * 1024 + s * PPIX + p;
                g_vth[o] = h;
                g_vtl[o] = __float2bfloat16(v - __bfloat162float(h));
            } else if (g >= GQBASE) {
                int qi = g - GQBASE;
                int img = qi / PPIX, p = qi - img * PPIX;
                outv[((size_t)img * DDIM + d) * PPIX + p] = v;
            }
        }
    }
}

// ---------------------------------------------------------------------------
// FlashAttention-style mma.sync attention: E stays in registers.
// grid = (98 dense m-tiles of 64, 5 classes). block = 256, 2 CTAs/SM.
// 16 chunks x 64 keys. Warp w: m-rows (w&3)*16, key-half (w>>2)*32.
// ---------------------------------------------------------------------------
#define NCHUNK 16
#define QROW 272            // 128 bf16 + 16B pad
#define VROW 144            // 64 bf16 + 16B pad
#define OFF_QH 0
#define OFF_QL 17408
#define OFF_KH 34816
#define OFF_KL 52224
#define OFF_VH 69632
#define OFF_VL 88064
#define OFF_DS 106496
#define ATT_SMEM (OFF_DS + 256)

__global__ __launch_bounds__(256, 2) void attn_kernel(float* __restrict__ out)
{
    extern __shared__ char smem[];
    const uint32_t sb = smem_u32(smem);
    float* dsumf = (float*)(smem + OFF_DS);

    const int tid = threadIdx.x;
    const int lane = tid & 31;
    const int warp = tid >> 5;
    const int tile = blockIdx.x, kc = blockIdx.y;

    const int m0 = (warp & 3) * 16;
    const int h32 = (warp >> 2) * 32;

    const int a_row = lane & 15;
    const int a_off = (lane >> 4) << 4;
    const int b_row = (lane & 7) | ((lane >> 4) << 3);
    const int b_off = ((lane >> 3) & 1) << 4;

    {
        const char* qh8 = (const char*)(g_qh + (size_t)tile * 64 * DDIM);
        const char* ql8 = (const char*)(g_ql + (size_t)tile * 64 * DDIM);
        for (int idx = tid; idx < 64 * 16; idx += 256) {
            int r = idx >> 4, seg = idx & 15;
            CPA16(sb + OFF_QH + r * QROW + seg * 16, qh8 + r * 256 + seg * 16);
            CPA16(sb + OFF_QL + r * QROW + seg * 16, ql8 + r * 256 + seg * 16);
        }
    }
    if (tid < 64) dsumf[tid] = 0.f;

    float oc[16][4];
#pragma unroll
    for (int n = 0; n < 16; n++)
#pragma unroll
        for (int q = 0; q < 4; q++) oc[n][q] = 0.f;

    const char* kh8 = (const char*)(g_kh + (size_t)kc * KEYS * DDIM);
    const char* kl8 = (const char*)(g_kl + (size_t)kc * KEYS * DDIM);
    const char* vh8 = (const char*)(g_vth + (size_t)kc * DDIM * 1024);
    const char* vl8 = (const char*)(g_vtl + (size_t)kc * DDIM * 1024);

    for (int ch = 0; ch < NCHUNK; ch++) {
        __syncthreads();

        for (int idx = tid; idx < 64 * 16; idx += 256) {
            int j = idx >> 4, seg = idx & 15;
            const size_t so = (size_t)(ch * 64 + j) * 256 + seg * 16;
            CPA16(sb + OFF_KH + j * QROW + seg * 16, kh8 + so);
            CPA16(sb + OFF_KL + j * QROW + seg * 16, kl8 + so);
        }
        for (int idx = tid; idx < 128 * 8; idx += 256) {
            int d = idx >> 3, seg = idx & 7;
            const size_t so = (size_t)d * 2048 + ch * 128 + seg * 16;
            CPA16(sb + OFF_VH + d * VROW + seg * 16, vh8 + so);
            CPA16(sb + OFF_VL + d * VROW + seg * 16, vl8 + so);
        }
        CPA_COMMIT();
        CPA_WAIT0();
        __syncthreads();

        float sc[4][4];
#pragma unroll
        for (int n = 0; n < 4; n++)
#pragma unroll
            for (int q = 0; q < 4; q++) sc[n][q] = 0.f;

#pragma unroll
        for (int k = 0; k < 8; k++) {
            const int kb = k * 32;
            uint32_t ah[4], al[4], bh0[4], bh1[4], bl0[4], bl1[4];
            uint32_t ra = sb + OFF_QH + (m0 + a_row) * QROW + kb + a_off;
            ldsm4(ra, ah);
            ldsm4(ra + (OFF_QL - OFF_QH), al);
            uint32_t rb = sb + OFF_KH + (h32 + b_row) * QROW + kb + b_off;
            ldsm4(rb, bh0);
            ldsm4(rb + 16 * QROW, bh1);
            ldsm4(rb + (OFF_KL - OFF_KH), bl0);
            ldsm4(rb + (OFF_KL - OFF_KH) + 16 * QROW, bl1);
#pragma unroll
            for (int n = 0; n < 4; n++) {
                uint32_t h0 = (n < 2) ? bh0[(n & 1) * 2] : bh1[(n & 1) * 2];
                uint32_t h1 = (n < 2) ? bh0[(n & 1) * 2 + 1] : bh1[(n & 1) * 2 + 1];
                uint32_t l0 = (n < 2) ? bl0[(n & 1) * 2] : bl1[(n & 1) * 2];
                uint32_t l1 = (n < 2) ? bl0[(n & 1) * 2 + 1] : bl1[(n & 1) * 2 + 1];
                mma16816(sc[n], ah, h0, h1);
                mma16816(sc[n], ah, l0, l1);
                mma16816(sc[n], al, h0, h1);
            }
        }

        uint32_t ehf[2][4], elf[2][4];
        {
            float rs0 = 0.f, rs1 = 0.f;
            const int r = m0 + (lane >> 2);
#pragma unroll
            for (int n = 0; n < 4; n++) {
                int jg = ch * 64 + h32 + n * 8 + 2 * (lane & 3);
                float e0 = (jg     < KEYS) ? __expf(sc[n][0]) : 0.f;
                float e1 = (jg + 1 < KEYS) ? __expf(sc[n][1]) : 0.f;
                float e2 = (jg     < KEYS) ? __expf(sc[n][2]) : 0.f;
                float e3 = (jg + 1 < KEYS) ? __expf(sc[n][3]) : 0.f;
                rs0 += e0 + e1;
                rs1 += e2 + e3;
                float h0 = __bfloat162float(__float2bfloat16(e0));
                float h1 = __bfloat162float(__float2bfloat16(e1));
                float h2 = __bfloat162float(__float2bfloat16(e2));
                float h3 = __bfloat162float(__float2bfloat16(e3));
                ehf[n >> 1][(n & 1) * 2]     = packbf(h0, h1);
                ehf[n >> 1][(n & 1) * 2 + 1] = packbf(h2, h3);
                elf[n >> 1][(n & 1) * 2]     = packbf(e0 - h0, e1 - h1);
                elf[n >> 1][(n & 1) * 2 + 1] = packbf(e2 - h2, e3 - h3);
            }
            rs0 += __shfl_xor_sync(0xFFFFFFFFu, rs0, 1);
            rs0 += __shfl_xor_sync(0xFFFFFFFFu, rs0, 2);
            rs1 += __shfl_xor_sync(0xFFFFFFFFu, rs1, 1);
            rs1 += __shfl_xor_sync(0xFFFFFFFFu, rs1, 2);
            if ((lane & 3) == 0) {
                atomicAdd(&dsumf[r], rs0);
                atomicAdd(&dsumf[r + 8], rs1);
            }
        }

#pragma unroll
        for (int kk = 0; kk < 2; kk++) {
            const int kcol = (h32 + kk * 16) * 2;
#pragma unroll
            for (int dh = 0; dh < 2; dh++) {
                uint32_t vv[4][4];
#pragma unroll
                for (int nd = 0; nd < 4; nd++)
                    ldsm4(sb + OFF_VH + (dh * 64 + nd * 16 + b_row) * VROW + kcol + b_off,
                          vv[nd]);
#pragma unroll
                for (int nd = 0; nd < 4; nd++)
#pragma unroll
                    for (int t = 0; t < 2; t++) {
                        float* o = oc[dh * 8 + nd * 2 + t];
                        mma16816(o, ehf[kk], vv[nd][t * 2], vv[nd][t * 2 + 1]);
                        mma16816(o, elf[kk], vv[nd][t * 2], vv[nd][t * 2 + 1]);
                    }
#pragma unroll
                for (int nd = 0; nd < 4; nd++)
                    ldsm4(sb + OFF_VL + (dh * 64 + nd * 16 + b_row) * VROW + kcol + b_off,
                          vv[nd]);
#pragma unroll
                for (int nd = 0; nd < 4; nd++)
#pragma unroll
                    for (int t = 0; t < 2; t++)
                        mma16816(oc[dh * 8 + nd * 2 + t], ehf[kk],
                                 vv[nd][t * 2], vv[nd][t * 2 + 1]);
            }
        }
    }

    __syncthreads();
    float* Osm = (float*)smem;
    const int r = m0 + (lane >> 2);
    if (warp < 4) {
#pragma unroll
        for (int n = 0; n < 16; n++) {
            int d = n * 8 + 2 * (lane & 3);
            Osm[r * 133 + d]           = oc[n][0];
            Osm[r * 133 + d + 1]       = oc[n][1];
            Osm[(r + 8) * 133 + d]     = oc[n][2];
            Osm[(r + 8) * 133 + d + 1] = oc[n][3];
        }
    }
    __syncthreads();
    if (warp >= 4) {
#pragma unroll
        for (int n = 0; n < 16; n++) {
            int d = n * 8 + 2 * (lane & 3);
            Osm[r * 133 + d]           += oc[n][0];
            Osm[r * 133 + d + 1]       += oc[n][1];
            Osm[(r + 8) * 133 + d]     += oc[n][2];
            Osm[(r + 8) * 133 + d + 1] += oc[n][3];
        }
    }
    __syncthreads();

    for (int idx = tid; idx < 128 * 64; idx += 256) {
        int d = idx >> 6, m = idx & 63;
        int g = tile * 64 + m;
        int bb = g / PPIX, p = g - bb * PPIX;
        out[((bb * KCLS + kc) * DDIM + d) * PPIX + p] = Osm[m * 133 + d] / dsumf[m];
    }
}

// ---------------------------------------------------------------------------
// kernel_launch
// ---------------------------------------------------------------------------
extern "C" void kernel_launch(void* const* d_in, const int* in_sizes, int n_in,
                              void* d_out, int out_size)
{
    const float* supp = (const float*)d_in[0];
    const float* qry  = (const float*)d_in[1];
    const float* Wqk  = (const float*)d_in[3];
    const float* Wv   = (const float*)d_in[4];
    float* out = (float*)d_out;

    cudaFuncSetAttribute(projmma_kernel,
                         cudaFuncAttributeMaxDynamicSharedMemorySize, PROJ_SMEM);
    cudaFuncSetAttribute(attn_kernel,
                         cudaFuncAttributeMaxDynamicSharedMemorySize, ATT_SMEM);

    xsplit_kernel<<<dim3(8, 4, NSUP + BQ), 256>>>(supp, qry);
    wsplit_kernel<<<dim3(2, 16), 256>>>(Wqk, Wv);
    projmma_kernel<<<dim3(NMT, 2), 256, PROJ_SMEM>>>(out + OUT1);
    attn_kernel<<<dim3(NTILE, KCLS), 256, ATT_SMEM>>>(out);
}

// round 11
// speedup vs baseline: 4.9219x; 1.0272x over previous
#include <cuda_runtime.h>
#include <cuda_bf16.h>
#include <cstdint>
#include <math.h>

// ---------------------------------------------------------------------------
// Problem constants
// ---------------------------------------------------------------------------
#define BQ 32
#define NSUP 25
#define KCLS 5
#define CIN 512
#define PPIX 196
#define DDIM 128
#define KEYS 980
#define OUT1 (BQ * KCLS * DDIM * PPIX)
#define MTOT (BQ * PPIX)          // 6272 flattened queries
#define NTILE 49                  // 6272 / 128 dense m-tiles (attention)
#define KROWS (NSUP * PPIX + 64)  // K rows padded so last chunk never faults
#define GROWS 11200               // 175 x 64 dense proj rows (28 dead in middle)
#define GQBASE 4928               // queries start row (supports [0,4900))
#define NMT 175

// bf16 hi/lo split scratch (device globals — zero-initialized, no alloc)
__device__ __align__(16) __nv_bfloat16 g_xh[GROWS * CIN];          // [g][c]
__device__ __align__(16) __nv_bfloat16 g_xl[GROWS * CIN];
__device__ __align__(16) __nv_bfloat16 g_wh[2 * DDIM * CIN];       // [qv][d][c]
__device__ __align__(16) __nv_bfloat16 g_wl[2 * DDIM * CIN];
__device__ __align__(16) __nv_bfloat16 g_qh[MTOT * DDIM];          // [g][d]
__device__ __align__(16) __nv_bfloat16 g_ql[MTOT * DDIM];
__device__ __align__(16) __nv_bfloat16 g_kh[KROWS * DDIM];         // [gkey][d]
__device__ __align__(16) __nv_bfloat16 g_kl[KROWS * DDIM];
__device__ __align__(16) __nv_bfloat16 g_vth[KCLS * DDIM * 1024];  // [kc][d][slot]
__device__ __align__(16) __nv_bfloat16 g_vtl[KCLS * DDIM * 1024];  // pads stay 0

// ---------------------------------------------------------------------------
// PTX helpers (baseline PTX, legal on plain sm_103)
// ---------------------------------------------------------------------------
__device__ __forceinline__ void ldsm4(uint32_t addr, uint32_t r[4]) {
    asm volatile("ldmatrix.sync.aligned.m8n8.x4.shared.b16 {%0,%1,%2,%3}, [%4];"
                 : "=r"(r[0]), "=r"(r[1]), "=r"(r[2]), "=r"(r[3]) : "r"(addr));
}
__device__ __forceinline__ void mma16816(float c[4], const uint32_t a[4],
                                         uint32_t b0, uint32_t b1) {
    asm volatile("mma.sync.aligned.m16n8k16.row.col.f32.bf16.bf16.f32 "
                 "{%0,%1,%2,%3}, {%4,%5,%6,%7}, {%8,%9}, {%0,%1,%2,%3};"
                 : "+f"(c[0]), "+f"(c[1]), "+f"(c[2]), "+f"(c[3])
                 : "r"(a[0]), "r"(a[1]), "r"(a[2]), "r"(a[3]), "r"(b0), "r"(b1));
}
__device__ __forceinline__ uint32_t smem_u32(const void* p) {
    uint32_t a;
    asm("{ .reg .u64 t; cvta.to.shared.u64 t, %1; cvt.u32.u64 %0, t; }"
        : "=r"(a) : "l"(p));
    return a;
}
__device__ __forceinline__ uint32_t packbf(float e0, float e1) {
    uint32_t r;   // lower half = e0
    asm("cvt.rn.bf16x2.f32 %0, %1, %2;" : "=r"(r) : "f"(e1), "f"(e0));
    return r;
}
#define CPA16(dst, src) \
    asm volatile("cp.async.ca.shared.global [%0], [%1], 16;" \
                 :: "r"(dst), "l"(src))
#define CPA_COMMIT() asm volatile("cp.async.commit_group;" ::: "memory")
#define CPA_WAIT0()  asm volatile("cp.async.wait_group 0;" ::: "memory")

// ---------------------------------------------------------------------------
// xsplit: features [img][c][p] f32 -> dense transposed bf16 hi/lo [g][c].
// grid = (8 c-tiles of 64, 4 p-tiles of 49, 57 imgs). block = 256.
// ---------------------------------------------------------------------------
__global__ __launch_bounds__(256) void xsplit_kernel(
    const float* __restrict__ supp, const float* __restrict__ qry)
{
    __shared__ float xs[64][50];
    const int tid = threadIdx.x;
    const int img = blockIdx.z;
    const float* x = (img < NSUP) ? supp + (size_t)img * CIN * PPIX
                                  : qry + (size_t)(img - NSUP) * CIN * PPIX;
    const int c0 = blockIdx.x * 64, p0 = blockIdx.y * 49;

    for (int idx = tid; idx < 64 * 49; idx += 256) {
        int c = idx / 49, p = idx - c * 49;
        xs[c][p] = x[(c0 + c) * PPIX + p0 + p];
    }
    __syncthreads();

    const size_t gbase = (img < NSUP) ? (size_t)img * PPIX + p0
                                      : (size_t)GQBASE + (img - NSUP) * PPIX + p0;
    for (int idx = tid; idx < 49 * 64; idx += 256) {
        int p = idx / 64, c = idx - p * 64;
        float v = xs[c][p];
        __nv_bfloat16 h = __float2bfloat16(v);
        size_t o = (gbase + p) * CIN + c0 + c;
        g_xh[o] = h;
        g_xl[o] = __float2bfloat16(v - __bfloat162float(h));
    }
}

// ---------------------------------------------------------------------------
// wsplit: W_qk / W_v [128][512] f32 -> bf16 hi/lo. grid = (2, 16).
// ---------------------------------------------------------------------------
__global__ __launch_bounds__(256) void wsplit_kernel(
    const float* __restrict__ Wq, const float* __restrict__ Wv)
{
    const float* W = blockIdx.x ? Wv : Wq;
    const int base = blockIdx.y * 4096;
    for (int i = threadIdx.x; i < 4096; i += 256) {
        float v = W[base + i];
        __nv_bfloat16 h = __float2bfloat16(v);
        size_t o = (size_t)blockIdx.x * DDIM * CIN + base + i;
        g_wh[o] = h;
        g_wl[o] = __float2bfloat16(v - __bfloat162float(h));
    }
}

// ---------------------------------------------------------------------------
// projmma: out[g][d] = sum_c x[g][c] * W[d][c], 3-split bf16 HMMA.
// grid = (175 m-tiles of 64, 2 {qk,v}). block 256, 2 CTAs/SM.
// ---------------------------------------------------------------------------
#define AROW 144
#define P_AH 0
#define P_AL (64 * AROW)
#define P_WH (2 * 64 * AROW)
#define P_WL (P_WH + 128 * AROW)
#define PROJ_SMEM (P_WL + 128 * AROW)

__global__ __launch_bounds__(256, 2) void projmma_kernel(float* __restrict__ outv)
{
    extern __shared__ char smem[];
    const uint32_t sb = smem_u32(smem);
    const int tid = threadIdx.x;
    const int lane = tid & 31;
    const int warp = tid >> 5;
    const int tile = blockIdx.x, qv = blockIdx.y;

    const int m0 = (warp & 3) * 16;
    const int n0 = (warp >> 2) * 64;

    const int a_row = lane & 15;
    const int a_off = (lane >> 4) << 4;
    const int b_row = (lane & 7) | ((lane >> 4) << 3);
    const int b_off = ((lane >> 3) & 1) << 4;

    float oc[8][4];
#pragma unroll
    for (int n = 0; n < 8; n++)
#pragma unroll
        for (int q = 0; q < 4; q++) oc[n][q] = 0.f;

    const char* xh8 = (const char*)(g_xh + (size_t)tile * 64 * CIN);
    const char* xl8 = (const char*)(g_xl + (size_t)tile * 64 * CIN);
    const char* wh8 = (const char*)(g_wh + (size_t)qv * DDIM * CIN);
    const char* wl8 = (const char*)(g_wl + (size_t)qv * DDIM * CIN);

    for (int ch = 0; ch < 8; ch++) {
        __syncthreads();
        for (int idx = tid; idx < 64 * 8; idx += 256) {
            int r = idx >> 3, seg = idx & 7;
            size_t so = (size_t)r * 1024 + ch * 128 + seg * 16;
            CPA16(sb + P_AH + r * AROW + seg * 16, xh8 + so);
            CPA16(sb + P_AL + r * AROW + seg * 16, xl8 + so);
        }
        for (int idx = tid; idx < 128 * 8; idx += 256) {
            int n = idx >> 3, seg = idx & 7;
            size_t so = (size_t)n * 1024 + ch * 128 + seg * 16;
            CPA16(sb + P_WH + n * AROW + seg * 16, wh8 + so);
            CPA16(sb + P_WL + n * AROW + seg * 16, wl8 + so);
        }
        CPA_COMMIT();
        CPA_WAIT0();
        __syncthreads();

#pragma unroll
        for (int ks = 0; ks < 4; ks++) {
            const int kb = ks * 32;
            uint32_t ah[4], al[4];
            uint32_t ra = sb + P_AH + (m0 + a_row) * AROW + kb + a_off;
            ldsm4(ra, ah);
            ldsm4(ra + (P_AL - P_AH), al);
#pragma unroll
            for (int nt = 0; nt < 4; nt++) {
                uint32_t bh[4], bl[4];
                uint32_t rb = sb + P_WH + (n0 + nt * 16 + b_row) * AROW + kb + b_off;
                ldsm4(rb, bh);
                ldsm4(rb + (P_WL - P_WH), bl);
#pragma unroll
                for (int t = 0; t < 2; t++) {
                    float* o = oc[nt * 2 + t];
                    mma16816(o, ah, bh[t * 2], bh[t * 2 + 1]);
                    mma16816(o, ah, bl[t * 2], bl[t * 2 + 1]);
                    mma16816(o, al, bh[t * 2], bh[t * 2 + 1]);
                }
            }
        }
    }

    const int gbase = tile * 64;
    if (qv == 0) {
        uint32_t* kh32 = (uint32_t*)g_kh;
        uint32_t* kl32 = (uint32_t*)g_kl;
        uint32_t* qh32 = (uint32_t*)g_qh;
        uint32_t* ql32 = (uint32_t*)g_ql;
        const int r1 = m0 + (lane >> 2);
#pragma unroll
        for (int nt = 0; nt < 8; nt++) {
            const int d = n0 + nt * 8 + 2 * (lane & 3);
#pragma unroll
            for (int half = 0; half < 2; half++) {
                int g = gbase + r1 + half * 8;
                float c0 = oc[nt][half * 2], c1 = oc[nt][half * 2 + 1];
                float h0 = __bfloat162float(__float2bfloat16(c0));
                float h1 = __bfloat162float(__float2bfloat16(c1));
                uint32_t ph = packbf(h0, h1);
                uint32_t pl = packbf(c0 - h0, c1 - h1);
                if (g < NSUP * PPIX) {
                    int o = (g * DDIM + d) >> 1;
                    kh32[o] = ph;
                    kl32[o] = pl;
                } else if (g >= GQBASE) {
                    int o = ((g - GQBASE) * DDIM + d) >> 1;
                    qh32[o] = ph;
                    ql32[o] = pl;
                }
            }
        }
    } else {
        __syncthreads();
        float* Osm = (float*)smem;   // [64][133]
        const int r = m0 + (lane >> 2);
#pragma unroll
        for (int nt = 0; nt < 8; nt++) {
            const int d = n0 + nt * 8 + 2 * (lane & 3);
            Osm[r * 133 + d]           = oc[nt][0];
            Osm[r * 133 + d + 1]       = oc[nt][1];
            Osm[(r + 8) * 133 + d]     = oc[nt][2];
            Osm[(r + 8) * 133 + d + 1] = oc[nt][3];
        }
        __syncthreads();
        for (int idx = tid; idx < 128 * 64; idx += 256) {
            int d = idx >> 6, m = idx & 63;
            int g = gbase + m;
            float v = Osm[m * 133 + d];
            if (g < NSUP * PPIX) {
                int img = g / PPIX, p = g - img * PPIX;
                int cls = img / 5, s = img - cls * 5;
                __nv_bfloat16 h = __float2bfloat16(v);
                size_t o = ((size_t)cls * DDIM + d) * 1024 + s * PPIX + p;
                g_vth[o] = h;
                g_vtl[o] = __float2bfloat16(v - __bfloat162float(h));
            } else if (g >= GQBASE) {
                int qi = g - GQBASE;
                int img = qi / PPIX, p = qi - img * PPIX;
                outv[((size_t)img * DDIM + d) * PPIX + p] = v;
            }
        }
    }
}

// ---------------------------------------------------------------------------
// FlashAttention-style mma.sync attention, M=128 per CTA, 512 threads,
// 1 CTA/SM, SYNCHRONOUS single-buffer staging (proven R9 discipline).
// grid = (49 dense m-tiles of 128, 5 classes) = 245 CTAs.
// Warp w: m-rows (w&7)*16, key-half (w>>3)*32 of the 64-key chunk.
// ---------------------------------------------------------------------------
#define NCHUNK 16
#define QROW 272            // 128 bf16 + 16B pad
#define VROW 144            // 64 bf16 + 16B pad
#define OFF_QH 0
#define OFF_QL 34816
#define OFF_KH 69632
#define OFF_KL 87040
#define OFF_VH 104448
#define OFF_VL 122880
#define OFF_DS 141312
#define ATT_SMEM (OFF_DS + 512)   // 141824

__global__ __launch_bounds__(512, 1) void attn_kernel(float* __restrict__ out)
{
    extern __shared__ char smem[];
    const uint32_t sb = smem_u32(smem);
    float* dsumf = (float*)(smem + OFF_DS);

    const int tid = threadIdx.x;
    const int lane = tid & 31;
    const int warp = tid >> 5;
    const int tile = blockIdx.x, kc = blockIdx.y;

    const int m0 = (warp & 7) * 16;      // warp m base (0..112)
    const int h32 = (warp >> 3) * 32;    // warp key-half base within chunk

    const int a_row = lane & 15;
    const int a_off = (lane >> 4) << 4;
    const int b_row = (lane & 7) | ((lane >> 4) << 3);
    const int b_off = ((lane >> 3) & 1) << 4;

    const char* kh8 = (const char*)(g_kh + (size_t)kc * KEYS * DDIM);
    const char* kl8 = (const char*)(g_kl + (size_t)kc * KEYS * DDIM);
    const char* vh8 = (const char*)(g_vth + (size_t)kc * DDIM * 1024);
    const char* vl8 = (const char*)(g_vtl + (size_t)kc * DDIM * 1024);

    // ---- prologue: stage Q (128 rows); joins chunk 0's commit group ----
    {
        const char* qh8 = (const char*)(g_qh + (size_t)tile * 128 * DDIM);
        const char* ql8 = (const char*)(g_ql + (size_t)tile * 128 * DDIM);
        for (int idx = tid; idx < 128 * 16; idx += 512) {
            int r = idx >> 4, seg = idx & 15;
            CPA16(sb + OFF_QH + r * QROW + seg * 16, qh8 + r * 256 + seg * 16);
            CPA16(sb + OFF_QL + r * QROW + seg * 16, ql8 + r * 256 + seg * 16);
        }
    }
    if (tid < 128) dsumf[tid] = 0.f;

    // O accumulators: [16m x 128d] per warp (16 n-tiles x 4 regs)
    float oc[16][4];
#pragma unroll
    for (int n = 0; n < 16; n++)
#pragma unroll
        for (int q = 0; q < 4; q++) oc[n][q] = 0.f;

    for (int ch = 0; ch < NCHUNK; ch++) {
        __syncthreads();   // prior chunk's reads of K/V smem complete

        // ---- stage K chunk (64 rows x 128 bf16, hi/lo) ----
        for (int idx = tid; idx < 64 * 16; idx += 512) {
            int j = idx >> 4, seg = idx & 15;
            const size_t so = (size_t)(ch * 64 + j) * 256 + seg * 16;
            CPA16(sb + OFF_KH + j * QROW + seg * 16, kh8 + so);
            CPA16(sb + OFF_KL + j * QROW + seg * 16, kl8 + so);
        }
        // ---- stage V^T chunk (128 d-rows x 64 keys, hi/lo) ----
        for (int idx = tid; idx < 128 * 8; idx += 512) {
            int d = idx >> 3, seg = idx & 7;
            const size_t so = (size_t)d * 2048 + ch * 128 + seg * 16;
            CPA16(sb + OFF_VH + d * VROW + seg * 16, vh8 + so);
            CPA16(sb + OFF_VL + d * VROW + seg * 16, vl8 + so);
        }
        CPA_COMMIT();
        CPA_WAIT0();
        __syncthreads();

        // ---- S = Qh.Kh^T + Qh.Kl^T + Ql.Kh^T  (16m x 32j per warp) ----
        float sc[4][4];
#pragma unroll
        for (int n = 0; n < 4; n++)
#pragma unroll
            for (int q = 0; q < 4; q++) sc[n][q] = 0.f;

#pragma unroll
        for (int k = 0; k < 8; k++) {
            const int kb = k * 32;
            uint32_t ah[4], al[4], bh0[4], bh1[4], bl0[4], bl1[4];
            uint32_t ra = sb + OFF_QH + (m0 + a_row) * QROW + kb + a_off;
            ldsm4(ra, ah);
            ldsm4(ra + (OFF_QL - OFF_QH), al);
            uint32_t rb = sb + OFF_KH + (h32 + b_row) * QROW + kb + b_off;
            ldsm4(rb, bh0);
            ldsm4(rb + 16 * QROW, bh1);
            ldsm4(rb + (OFF_KL - OFF_KH), bl0);
            ldsm4(rb + (OFF_KL - OFF_KH) + 16 * QROW, bl1);
#pragma unroll
            for (int n = 0; n < 4; n++) {
                uint32_t h0 = (n < 2) ? bh0[(n & 1) * 2] : bh1[(n & 1) * 2];
                uint32_t h1 = (n < 2) ? bh0[(n & 1) * 2 + 1] : bh1[(n & 1) * 2 + 1];
                uint32_t l0 = (n < 2) ? bl0[(n & 1) * 2] : bl1[(n & 1) * 2];
                uint32_t l1 = (n < 2) ? bl0[(n & 1) * 2 + 1] : bl1[(n & 1) * 2 + 1];
                mma16816(sc[n], ah, h0, h1);
                mma16816(sc[n], ah, l0, l1);
                mma16816(sc[n], al, h0, h1);
            }
        }

        // ---- exp (exact key mask) -> row sums -> E A-frags in registers ----
        uint32_t ehf[2][4], elf[2][4];
        {
            float rs0 = 0.f, rs1 = 0.f;
            const int r = m0 + (lane >> 2);
#pragma unroll
            for (int n = 0; n < 4; n++) {
                int jg = ch * 64 + h32 + n * 8 + 2 * (lane & 3);
                float e0 = (jg     < KEYS) ? __expf(sc[n][0]) : 0.f;
                float e1 = (jg + 1 < KEYS) ? __expf(sc[n][1]) : 0.f;
                float e2 = (jg     < KEYS) ? __expf(sc[n][2]) : 0.f;
                float e3 = (jg + 1 < KEYS) ? __expf(sc[n][3]) : 0.f;
                rs0 += e0 + e1;
                rs1 += e2 + e3;
                float h0 = __bfloat162float(__float2bfloat16(e0));
                float h1 = __bfloat162float(__float2bfloat16(e1));
                float h2 = __bfloat162float(__float2bfloat16(e2));
                float h3 = __bfloat162float(__float2bfloat16(e3));
                ehf[n >> 1][(n & 1) * 2]     = packbf(h0, h1);
                ehf[n >> 1][(n & 1) * 2 + 1] = packbf(h2, h3);
                elf[n >> 1][(n & 1) * 2]     = packbf(e0 - h0, e1 - h1);
                elf[n >> 1][(n & 1) * 2 + 1] = packbf(e2 - h2, e3 - h3);
            }
            rs0 += __shfl_xor_sync(0xFFFFFFFFu, rs0, 1);
            rs0 += __shfl_xor_sync(0xFFFFFFFFu, rs0, 2);
            rs1 += __shfl_xor_sync(0xFFFFFFFFu, rs1, 1);
            rs1 += __shfl_xor_sync(0xFFFFFFFFu, rs1, 2);
            if ((lane & 3) == 0) {
                atomicAdd(&dsumf[r], rs0);
                atomicAdd(&dsumf[r + 8], rs1);
            }
        }

        // ---- O += Eh.Vh + El.Vh + Eh.Vl  (16m x 128d, E from registers) ----
#pragma unroll
        for (int kk = 0; kk < 2; kk++) {
            const int kcol = (h32 + kk * 16) * 2;
#pragma unroll
            for (int dh = 0; dh < 2; dh++) {
                uint32_t vv[4][4];
#pragma unroll
                for (int nd = 0; nd < 4; nd++)
                    ldsm4(sb + OFF_VH + (dh * 64 + nd * 16 + b_row) * VROW + kcol + b_off,
                          vv[nd]);
#pragma unroll
                for (int nd = 0; nd < 4; nd++)
#pragma unroll
                    for (int t = 0; t < 2; t++) {
                        float* o = oc[dh * 8 + nd * 2 + t];
                        mma16816(o, ehf[kk], vv[nd][t * 2], vv[nd][t * 2 + 1]);
                        mma16816(o, elf[kk], vv[nd][t * 2], vv[nd][t * 2 + 1]);
                    }
#pragma unroll
                for (int nd = 0; nd < 4; nd++)
                    ldsm4(sb + OFF_VL + (dh * 64 + nd * 16 + b_row) * VROW + kcol + b_off,
                          vv[nd]);
#pragma unroll
                for (int nd = 0; nd < 4; nd++)
#pragma unroll
                    for (int t = 0; t < 2; t++)
                        mma16816(oc[dh * 8 + nd * 2 + t], ehf[kk],
                                 vv[nd][t * 2], vv[nd][t * 2 + 1]);
            }
        }
    }

    // ---- epilogue: sum key-half partners via smem, normalize, write ----
    __syncthreads();
    float* Osm = (float*)smem;   // [128][133] f32 = 68,096 B, reuses Q region
    const int r = m0 + (lane >> 2);
    if (warp < 8) {
#pragma unroll
        for (int n = 0; n < 16; n++) {
            int d = n * 8 + 2 * (lane & 3);
            Osm[r * 133 + d]           = oc[n][0];
            Osm[r * 133 + d + 1]       = oc[n][1];
            Osm[(r + 8) * 133 + d]     = oc[n][2];
            Osm[(r + 8) * 133 + d + 1] = oc[n][3];
        }
    }
    __syncthreads();
    if (warp >= 8) {
#pragma unroll
        for (int n = 0; n < 16; n++) {
            int d = n * 8 + 2 * (lane & 3);
            Osm[r * 133 + d]           += oc[n][0];
            Osm[r * 133 + d + 1]       += oc[n][1];
            Osm[(r + 8) * 133 + d]     += oc[n][2];
            Osm[(r + 8) * 133 + d + 1] += oc[n][3];
        }
    }
    __syncthreads();

    // row m -> global query g = tile*128 + m -> (b, p); out[b][kc][d*196+p]
    for (int idx = tid; idx < 128 * 128; idx += 512) {
        int d = idx >> 7, m = idx & 127;
        int g = tile * 128 + m;
        int bb = g / PPIX, p = g - bb * PPIX;
        out[((bb * KCLS + kc) * DDIM + d) * PPIX + p] = Osm[m * 133 + d] / dsumf[m];
    }
}

// ---------------------------------------------------------------------------
// kernel_launch
// ---------------------------------------------------------------------------
extern "C" void kernel_launch(void* const* d_in, const int* in_sizes, int n_in,
                              void* d_out, int out_size)
{
    const float* supp = (const float*)d_in[0];
    const float* qry  = (const float*)d_in[1];
    const float* Wqk  = (const float*)d_in[3];
    const float* Wv   = (const float*)d_in[4];
    float* out = (float*)d_out;

    cudaFuncSetAttribute(projmma_kernel,
                         cudaFuncAttributeMaxDynamicSharedMemorySize, PROJ_SMEM);
    cudaFuncSetAttribute(attn_kernel,
                         cudaFuncAttributeMaxDynamicSharedMemorySize, ATT_SMEM);

    xsplit_kernel<<<dim3(8, 4, NSUP + BQ), 256>>>(supp, qry);
    wsplit_kernel<<<dim3(2, 16), 256>>>(Wqk, Wv);
    projmma_kernel<<<dim3(NMT, 2), 256, PROJ_SMEM>>>(out + OUT1);
    attn_kernel<<<dim3(NTILE, KCLS), 512, ATT_SMEM>>>(out);
}

// round 14
// speedup vs baseline: 4.9742x; 1.0106x over previous
#include <cuda_runtime.h>
#include <cuda_bf16.h>
#include <cstdint>
#include <math.h>

// ---------------------------------------------------------------------------
// Problem constants
// ---------------------------------------------------------------------------
#define BQ 32
#define NSUP 25
#define KCLS 5
#define CIN 512
#define PPIX 196
#define DDIM 128
#define KEYS 980
#define OUT1 (BQ * KCLS * DDIM * PPIX)
#define MTOT (BQ * PPIX)          // 6272 flattened queries
#define NTILE 49                  // 6272 / 128 dense m-tiles (attention)
#define KROWS (NSUP * PPIX + 64)  // K rows padded so last chunk never faults
#define GROWS 11200               // 175 x 64 dense proj rows (28 dead in middle)
#define GQBASE 4928               // queries start row (supports [0,4900))
#define NMT 175

// bf16 hi/lo split scratch (device globals — zero-initialized, no alloc)
__device__ __align__(16) __nv_bfloat16 g_xh[GROWS * CIN];          // [g][c]
__device__ __align__(16) __nv_bfloat16 g_xl[GROWS * CIN];
__device__ __align__(16) __nv_bfloat16 g_wh[2 * DDIM * CIN];       // [qv][d][c]
__device__ __align__(16) __nv_bfloat16 g_wl[2 * DDIM * CIN];
__device__ __align__(16) __nv_bfloat16 g_qh[MTOT * DDIM];          // [g][d]
__device__ __align__(16) __nv_bfloat16 g_ql[MTOT * DDIM];
__device__ __align__(16) __nv_bfloat16 g_kh[KROWS * DDIM];         // [gkey][d]
__device__ __align__(16) __nv_bfloat16 g_kl[KROWS * DDIM];
__device__ __align__(16) __nv_bfloat16 g_vth[KCLS * DDIM * 1024];  // [kc][d][slot]
__device__ __align__(16) __nv_bfloat16 g_vtl[KCLS * DDIM * 1024];  // pads stay 0

// ---------------------------------------------------------------------------
// PTX helpers (baseline PTX, legal on plain sm_103)
// ---------------------------------------------------------------------------
__device__ __forceinline__ void ldsm4(uint32_t addr, uint32_t r[4]) {
    asm volatile("ldmatrix.sync.aligned.m8n8.x4.shared.b16 {%0,%1,%2,%3}, [%4];"
                 : "=r"(r[0]), "=r"(r[1]), "=r"(r[2]), "=r"(r[3]) : "r"(addr));
}
__device__ __forceinline__ void mma16816(float c[4], const uint32_t a[4],
                                         uint32_t b0, uint32_t b1) {
    asm volatile("mma.sync.aligned.m16n8k16.row.col.f32.bf16.bf16.f32 "
                 "{%0,%1,%2,%3}, {%4,%5,%6,%7}, {%8,%9}, {%0,%1,%2,%3};"
                 : "+f"(c[0]), "+f"(c[1]), "+f"(c[2]), "+f"(c[3])
                 : "r"(a[0]), "r"(a[1]), "r"(a[2]), "r"(a[3]), "r"(b0), "r"(b1));
}
__device__ __forceinline__ uint32_t smem_u32(const void* p) {
    uint32_t a;
    asm("{ .reg .u64 t; cvta.to.shared.u64 t, %1; cvt.u32.u64 %0, t; }"
        : "=r"(a) : "l"(p));
    return a;
}
__device__ __forceinline__ uint32_t packbf(float e0, float e1) {
    uint32_t r;   // lower half = e0
    asm("cvt.rn.bf16x2.f32 %0, %1, %2;" : "=r"(r) : "f"(e1), "f"(e0));
    return r;
}
#define CPA16(dst, src) \
    asm volatile("cp.async.ca.shared.global [%0], [%1], 16;" \
                 :: "r"(dst), "l"(src))
#define CPA_COMMIT() asm volatile("cp.async.commit_group;" ::: "memory")
#define CPA_WAIT0()  asm volatile("cp.async.wait_group 0;" ::: "memory")

// ---------------------------------------------------------------------------
// xsplit: features [img][c][p] f32 -> dense transposed bf16 hi/lo [g][c].
// grid = (8 c-tiles of 64, 4 p-tiles of 49, 57 imgs). block = 256.
// ---------------------------------------------------------------------------
__global__ __launch_bounds__(256) void xsplit_kernel(
    const float* __restrict__ supp, const float* __restrict__ qry)
{
    __shared__ float xs[64][50];
    const int tid = threadIdx.x;
    const int img = blockIdx.z;
    const float* x = (img < NSUP) ? supp + (size_t)img * CIN * PPIX
                                  : qry + (size_t)(img - NSUP) * CIN * PPIX;
    const int c0 = blockIdx.x * 64, p0 = blockIdx.y * 49;

    for (int idx = tid; idx < 64 * 49; idx += 256) {
        int c = idx / 49, p = idx - c * 49;
        xs[c][p] = x[(c0 + c) * PPIX + p0 + p];
    }
    __syncthreads();

    const size_t gbase = (img < NSUP) ? (size_t)img * PPIX + p0
                                      : (size_t)GQBASE + (img - NSUP) * PPIX + p0;
    for (int idx = tid; idx < 49 * 64; idx += 256) {
        int p = idx / 64, c = idx - p * 64;
        float v = xs[c][p];
        __nv_bfloat16 h = __float2bfloat16(v);
        size_t o = (gbase + p) * CIN + c0 + c;
        g_xh[o] = h;
        g_xl[o] = __float2bfloat16(v - __bfloat162float(h));
    }
}

// ---------------------------------------------------------------------------
// wsplit: W_qk / W_v [128][512] f32 -> bf16 hi/lo. grid = (2, 16).
// ---------------------------------------------------------------------------
__global__ __launch_bounds__(256) void wsplit_kernel(
    const float* __restrict__ Wq, const float* __restrict__ Wv)
{
    const float* W = blockIdx.x ? Wv : Wq;
    const int base = blockIdx.y * 4096;
    for (int i = threadIdx.x; i < 4096; i += 256) {
        float v = W[base + i];
        __nv_bfloat16 h = __float2bfloat16(v);
        size_t o = (size_t)blockIdx.x * DDIM * CIN + base + i;
        g_wh[o] = h;
        g_wl[o] = __float2bfloat16(v - __bfloat162float(h));
    }
}

// ---------------------------------------------------------------------------
// projmma: out[g][d] = sum_c x[g][c] * W[d][c], 3-split bf16 HMMA.
// grid = (175 m-tiles of 64, 2 {qk,v}). block 256, 2 CTAs/SM.
// ---------------------------------------------------------------------------
#define AROW 144
#define P_AH 0
#define P_AL (64 * AROW)
#define P_WH (2 * 64 * AROW)
#define P_WL (P_WH + 128 * AROW)
#define PROJ_SMEM (P_WL + 128 * AROW)

__global__ __launch_bounds__(256, 2) void projmma_kernel(float* __restrict__ outv)
{
    extern __shared__ char smem[];
    const uint32_t sb = smem_u32(smem);
    const int tid = threadIdx.x;
    const int lane = tid & 31;
    const int warp = tid >> 5;
    const int tile = blockIdx.x, qv = blockIdx.y;

    const int m0 = (warp & 3) * 16;
    const int n0 = (warp >> 2) * 64;

    const int a_row = lane & 15;
    const int a_off = (lane >> 4) << 4;
    const int b_row = (lane & 7) | ((lane >> 4) << 3);
    const int b_off = ((lane >> 3) & 1) << 4;

    float oc[8][4];
#pragma unroll
    for (int n = 0; n < 8; n++)
#pragma unroll
        for (int q = 0; q < 4; q++) oc[n][q] = 0.f;

    const char* xh8 = (const char*)(g_xh + (size_t)tile * 64 * CIN);
    const char* xl8 = (const char*)(g_xl + (size_t)tile * 64 * CIN);
    const char* wh8 = (const char*)(g_wh + (size_t)qv * DDIM * CIN);
    const char* wl8 = (const char*)(g_wl + (size_t)qv * DDIM * CIN);

    for (int ch = 0; ch < 8; ch++) {
        __syncthreads();
        for (int idx = tid; idx < 64 * 8; idx += 256) {
            int r = idx >> 3, seg = idx & 7;
            size_t so = (size_t)r * 1024 + ch * 128 + seg * 16;
            CPA16(sb + P_AH + r * AROW + seg * 16, xh8 + so);
            CPA16(sb + P_AL + r * AROW + seg * 16, xl8 + so);
        }
        for (int idx = tid; idx < 128 * 8; idx += 256) {
            int n = idx >> 3, seg = idx & 7;
            size_t so = (size_t)n * 1024 + ch * 128 + seg * 16;
            CPA16(sb + P_WH + n * AROW + seg * 16, wh8 + so);
            CPA16(sb + P_WL + n * AROW + seg * 16, wl8 + so);
        }
        CPA_COMMIT();
        CPA_WAIT0();
        __syncthreads();

#pragma unroll
        for (int ks = 0; ks < 4; ks++) {
            const int kb = ks * 32;
            uint32_t ah[4], al[4];
            uint32_t ra = sb + P_AH + (m0 + a_row) * AROW + kb + a_off;
            ldsm4(ra, ah);
            ldsm4(ra + (P_AL - P_AH), al);
#pragma unroll
            for (int nt = 0; nt < 4; nt++) {
                uint32_t bh[4], bl[4];
                uint32_t rb = sb + P_WH + (n0 + nt * 16 + b_row) * AROW + kb + b_off;
                ldsm4(rb, bh);
                ldsm4(rb + (P_WL - P_WH), bl);
#pragma unroll
                for (int t = 0; t < 2; t++) {
                    float* o = oc[nt * 2 + t];
                    mma16816(o, ah, bh[t * 2], bh[t * 2 + 1]);
                    mma16816(o, ah, bl[t * 2], bl[t * 2 + 1]);
                    mma16816(o, al, bh[t * 2], bh[t * 2 + 1]);
                }
            }
        }
    }

    const int gbase = tile * 64;
    if (qv == 0) {
        uint32_t* kh32 = (uint32_t*)g_kh;
        uint32_t* kl32 = (uint32_t*)g_kl;
        uint32_t* qh32 = (uint32_t*)g_qh;
        uint32_t* ql32 = (uint32_t*)g_ql;
        const int r1 = m0 + (lane >> 2);
#pragma unroll
        for (int nt = 0; nt < 8; nt++) {
            const int d = n0 + nt * 8 + 2 * (lane & 3);
#pragma unroll
            for (int half = 0; half < 2; half++) {
                int g = gbase + r1 + half * 8;
                float c0 = oc[nt][half * 2], c1 = oc[nt][half * 2 + 1];
                float h0 = __bfloat162float(__float2bfloat16(c0));
                float h1 = __bfloat162float(__float2bfloat16(c1));
                uint32_t ph = packbf(h0, h1);
                uint32_t pl = packbf(c0 - h0, c1 - h1);
                if (g < NSUP * PPIX) {
                    int o = (g * DDIM + d) >> 1;
                    kh32[o] = ph;
                    kl32[o] = pl;
                } else if (g >= GQBASE) {
                    int o = ((g - GQBASE) * DDIM + d) >> 1;
                    qh32[o] = ph;
                    ql32[o] = pl;
                }
            }
        }
    } else {
        __syncthreads();
        float* Osm = (float*)smem;   // [64][133]
        const int r = m0 + (lane >> 2);
#pragma unroll
        for (int nt = 0; nt < 8; nt++) {
            const int d = n0 + nt * 8 + 2 * (lane & 3);
            Osm[r * 133 + d]           = oc[nt][0];
            Osm[r * 133 + d + 1]       = oc[nt][1];
            Osm[(r + 8) * 133 + d]     = oc[nt][2];
            Osm[(r + 8) * 133 + d + 1] = oc[nt][3];
        }
        __syncthreads();
        for (int idx = tid; idx < 128 * 64; idx += 256) {
            int d = idx >> 6, m = idx & 63;
            int g = gbase + m;
            float v = Osm[m * 133 + d];
            if (g < NSUP * PPIX) {
                int img = g / PPIX, p = g - img * PPIX;
                int cls = img / 5, s = img - cls * 5;
                __nv_bfloat16 h = __float2bfloat16(v);
                size_t o = ((size_t)cls * DDIM + d) * 1024 + s * PPIX + p;
                g_vth[o] = h;
                g_vtl[o] = __float2bfloat16(v - __bfloat162float(h));
            } else if (g >= GQBASE) {
                int qi = g - GQBASE;
                int img = qi / PPIX, p = qi - img * PPIX;
                outv[((size_t)img * DDIM + d) * PPIX + p] = v;
            }
        }
    }
}

// ---------------------------------------------------------------------------
// FlashAttention-style mma.sync attention, M=128 per CTA, 512 threads,
// 1 CTA/SM, K/V double-buffered with mid-iteration prefetch:
//   loop: wait0; sync; S; exp; [prefetch ch+1 -> other buf; commit]; PV
// Buffer (ch+1)&1 is written only after the top-of-iter barrier that
// postdates all of iter ch-1's reads of it; wait0 keeps group logic trivial.
// FIX vs R10/R12/R13: cp.async destinations include the smem base (sb +).
// grid = (49 dense m-tiles of 128, 5 classes) = 245 CTAs.
// ---------------------------------------------------------------------------
#define NCHUNK 16
#define QROW 272            // 128 bf16 + 16B pad
#define VROW 144            // 64 bf16 + 16B pad
#define OFF_QH 0
#define OFF_QL 34816
#define OFF_BUF0 69632      // double-buffered region: [KH KL VH VL] x 2
#define BUFSTR 71680
#define B_KH 0
#define B_KL 17408
#define B_VH 34816
#define B_VL 53248
#define OFF_DS (OFF_BUF0 + 2 * BUFSTR + 128)   // 213120 (pad vs buffer end)
#define ATT_SMEM (OFF_DS + 512)                // 213632

__global__ __launch_bounds__(512, 1) void attn_kernel(float* __restrict__ out)
{
    extern __shared__ char smem[];
    const uint32_t sb = smem_u32(smem);
    float* dsumf = (float*)(smem + OFF_DS);

    const int tid = threadIdx.x;
    const int lane = tid & 31;
    const int warp = tid >> 5;
    const int tile = blockIdx.x, kc = blockIdx.y;

    const int m0 = (warp & 7) * 16;      // warp m base (0..112)
    const int h32 = (warp >> 3) * 32;    // warp key-half base within chunk

    const int a_row = lane & 15;
    const int a_off = (lane >> 4) << 4;
    const int b_row = (lane & 7) | ((lane >> 4) << 3);
    const int b_off = ((lane >> 3) & 1) << 4;

    const char* kh8 = (const char*)(g_kh + (size_t)kc * KEYS * DDIM);
    const char* kl8 = (const char*)(g_kl + (size_t)kc * KEYS * DDIM);
    const char* vh8 = (const char*)(g_vth + (size_t)kc * DDIM * 1024);
    const char* vl8 = (const char*)(g_vtl + (size_t)kc * DDIM * 1024);

    // ---- prologue: stage Q + chunk 0 K/V into buf0 (one group) ----
    {
        const char* qh8 = (const char*)(g_qh + (size_t)tile * 128 * DDIM);
        const char* ql8 = (const char*)(g_ql + (size_t)tile * 128 * DDIM);
        for (int idx = tid; idx < 128 * 16; idx += 512) {
            int r = idx >> 4, seg = idx & 15;
            CPA16(sb + OFF_QH + r * QROW + seg * 16, qh8 + r * 256 + seg * 16);
            CPA16(sb + OFF_QL + r * QROW + seg * 16, ql8 + r * 256 + seg * 16);
        }
        for (int idx = tid; idx < 64 * 16; idx += 512) {
            int j = idx >> 4, seg = idx & 15;
            const size_t so = (size_t)j * 256 + seg * 16;
            CPA16(sb + OFF_BUF0 + B_KH + j * QROW + seg * 16, kh8 + so);
            CPA16(sb + OFF_BUF0 + B_KL + j * QROW + seg * 16, kl8 + so);
        }
        for (int idx = tid; idx < 128 * 8; idx += 512) {
            int d = idx >> 3, seg = idx & 7;
            const size_t so = (size_t)d * 2048 + seg * 16;
            CPA16(sb + OFF_BUF0 + B_VH + d * VROW + seg * 16, vh8 + so);
            CPA16(sb + OFF_BUF0 + B_VL + d * VROW + seg * 16, vl8 + so);
        }
        CPA_COMMIT();
    }
    if (tid < 128) dsumf[tid] = 0.f;

    // O accumulators: [16m x 128d] per warp (16 n-tiles x 4 regs)
    float oc[16][4];
#pragma unroll
    for (int n = 0; n < 16; n++)
#pragma unroll
        for (int q = 0; q < 4; q++) oc[n][q] = 0.f;

    for (int ch = 0; ch < NCHUNK; ch++) {
        CPA_WAIT0();       // all staged data (incl. this chunk's) complete
        __syncthreads();   // visible to all; prior chunk's reads also done

        const uint32_t kb0 = OFF_BUF0 + (ch & 1) * BUFSTR;

        // ---- S = Qh.Kh^T + Qh.Kl^T + Ql.Kh^T  (16m x 32j per warp) ----
        float sc[4][4];
#pragma unroll
        for (int n = 0; n < 4; n++)
#pragma unroll
            for (int q = 0; q < 4; q++) sc[n][q] = 0.f;

#pragma unroll
        for (int k = 0; k < 8; k++) {
            const int kb = k * 32;
            uint32_t ah[4], al[4], bh0[4], bh1[4], bl0[4], bl1[4];
            uint32_t ra = sb + OFF_QH + (m0 + a_row) * QROW + kb + a_off;
            ldsm4(ra, ah);
            ldsm4(ra + (OFF_QL - OFF_QH), al);
            uint32_t rb = sb + kb0 + B_KH + (h32 + b_row) * QROW + kb + b_off;
            ldsm4(rb, bh0);
            ldsm4(rb + 16 * QROW, bh1);
            ldsm4(rb + (B_KL - B_KH), bl0);
            ldsm4(rb + (B_KL - B_KH) + 16 * QROW, bl1);
#pragma unroll
            for (int n = 0; n < 4; n++) {
                uint32_t h0 = (n < 2) ? bh0[(n & 1) * 2] : bh1[(n & 1) * 2];
                uint32_t h1 = (n < 2) ? bh0[(n & 1) * 2 + 1] : bh1[(n & 1) * 2 + 1];
                uint32_t l0 = (n < 2) ? bl0[(n & 1) * 2] : bl1[(n & 1) * 2];
                uint32_t l1 = (n < 2) ? bl0[(n & 1) * 2 + 1] : bl1[(n & 1) * 2 + 1];
                mma16816(sc[n], ah, h0, h1);
                mma16816(sc[n], ah, l0, l1);
                mma16816(sc[n], al, h0, h1);
            }
        }

        // ---- exp (exact key mask) -> row sums -> E A-frags in registers ----
        uint32_t ehf[2][4], elf[2][4];
        {
            float rs0 = 0.f, rs1 = 0.f;
            const int r = m0 + (lane >> 2);
#pragma unroll
            for (int n = 0; n < 4; n++) {
                int jg = ch * 64 + h32 + n * 8 + 2 * (lane & 3);
                float e0 = (jg     < KEYS) ? __expf(sc[n][0]) : 0.f;
                float e1 = (jg + 1 < KEYS) ? __expf(sc[n][1]) : 0.f;
                float e2 = (jg     < KEYS) ? __expf(sc[n][2]) : 0.f;
                float e3 = (jg + 1 < KEYS) ? __expf(sc[n][3]) : 0.f;
                rs0 += e0 + e1;
                rs1 += e2 + e3;
                float h0 = __bfloat162float(__float2bfloat16(e0));
                float h1 = __bfloat162float(__float2bfloat16(e1));
                float h2 = __bfloat162float(__float2bfloat16(e2));
                float h3 = __bfloat162float(__float2bfloat16(e3));
                ehf[n >> 1][(n & 1) * 2]     = packbf(h0, h1);
                ehf[n >> 1][(n & 1) * 2 + 1] = packbf(h2, h3);
                elf[n >> 1][(n & 1) * 2]     = packbf(e0 - h0, e1 - h1);
                elf[n >> 1][(n & 1) * 2 + 1] = packbf(e2 - h2, e3 - h3);
            }
            rs0 += __shfl_xor_sync(0xFFFFFFFFu, rs0, 1);
            rs0 += __shfl_xor_sync(0xFFFFFFFFu, rs0, 2);
            rs1 += __shfl_xor_sync(0xFFFFFFFFu, rs1, 1);
            rs1 += __shfl_xor_sync(0xFFFFFFFFu, rs1, 2);
            if ((lane & 3) == 0) {
                atomicAdd(&dsumf[r], rs0);
                atomicAdd(&dsumf[r + 8], rs1);
            }
        }

        // ---- prefetch chunk ch+1 into the other buffer (overlaps PV) ----
        if (ch + 1 < NCHUNK) {
            const uint32_t nb = sb + OFF_BUF0 + ((ch + 1) & 1) * BUFSTR;
            for (int idx = tid; idx < 64 * 16; idx += 512) {
                int j = idx >> 4, seg = idx & 15;
                const size_t so = (size_t)((ch + 1) * 64 + j) * 256 + seg * 16;
                CPA16(nb + B_KH + j * QROW + seg * 16, kh8 + so);
                CPA16(nb + B_KL + j * QROW + seg * 16, kl8 + so);
            }
            for (int idx = tid; idx < 128 * 8; idx += 512) {
                int d = idx >> 3, seg = idx & 7;
                const size_t so = (size_t)d * 2048 + (ch + 1) * 128 + seg * 16;
                CPA16(nb + B_VH + d * VROW + seg * 16, vh8 + so);
                CPA16(nb + B_VL + d * VROW + seg * 16, vl8 + so);
            }
            CPA_COMMIT();
        }

        // ---- O += Eh.Vh + El.Vh + Eh.Vl  (16m x 128d, E from registers) ----
#pragma unroll
        for (int kk = 0; kk < 2; kk++) {
            const int kcol = (h32 + kk * 16) * 2;
#pragma unroll
            for (int dh = 0; dh < 2; dh++) {
                uint32_t vv[4][4];
#pragma unroll
                for (int nd = 0; nd < 4; nd++)
                    ldsm4(sb + kb0 + B_VH + (dh * 64 + nd * 16 + b_row) * VROW + kcol + b_off,
                          vv[nd]);
#pragma unroll
                for (int nd = 0; nd < 4; nd++)
#pragma unroll
                    for (int t = 0; t < 2; t++) {
                        float* o = oc[dh * 8 + nd * 2 + t];
                        mma16816(o, ehf[kk], vv[nd][t * 2], vv[nd][t * 2 + 1]);
                        mma16816(o, elf[kk], vv[nd][t * 2], vv[nd][t * 2 + 1]);
                    }
#pragma unroll
                for (int nd = 0; nd < 4; nd++)
                    ldsm4(sb + kb0 + B_VL + (dh * 64 + nd * 16 + b_row) * VROW + kcol + b_off,
                          vv[nd]);
#pragma unroll
                for (int nd = 0; nd < 4; nd++)
#pragma unroll
                    for (int t = 0; t < 2; t++)
                        mma16816(oc[dh * 8 + nd * 2 + t], ehf[kk],
                                 vv[nd][t * 2], vv[nd][t * 2 + 1]);
            }
        }
    }

    // ---- epilogue: sum key-half partners via smem, normalize, write ----
    __syncthreads();
    float* Osm = (float*)smem;   // [128][133] f32 = 68,096 B, reuses Q region
    const int r = m0 + (lane >> 2);
    if (warp < 8) {
#pragma unroll
        for (int n = 0; n < 16; n++) {
            int d = n * 8 + 2 * (lane & 3);
            Osm[r * 133 + d]           = oc[n][0];
            Osm[r * 133 + d + 1]       = oc[n][1];
            Osm[(r + 8) * 133 + d]     = oc[n][2];
            Osm[(r + 8) * 133 + d + 1] = oc[n][3];
        }
    }
    __syncthreads();
    if (warp >= 8) {
#pragma unroll
        for (int n = 0; n < 16; n++) {
            int d = n * 8 + 2 * (lane & 3);
            Osm[r * 133 + d]           += oc[n][0];
            Osm[r * 133 + d + 1]       += oc[n][1];
            Osm[(r + 8) * 133 + d]     += oc[n][2];
            Osm[(r + 8) * 133 + d + 1] += oc[n][3];
        }
    }
    __syncthreads();

    // row m -> global query g = tile*128 + m -> (b, p); out[b][kc][d*196+p]
    for (int idx = tid; idx < 128 * 128; idx += 512) {
        int d = idx >> 7, m = idx & 127;
        int g = tile * 128 + m;
        int bb = g / PPIX, p = g - bb * PPIX;
        out[((bb * KCLS + kc) * DDIM + d) * PPIX + p] = Osm[m * 133 + d] / dsumf[m];
    }
}

// ---------------------------------------------------------------------------
// kernel_launch
// ---------------------------------------------------------------------------
extern "C" void kernel_launch(void* const* d_in, const int* in_sizes, int n_in,
                              void* d_out, int out_size)
{
    const float* supp = (const float*)d_in[0];
    const float* qry  = (const float*)d_in[1];
    const float* Wqk  = (const float*)d_in[3];
    const float* Wv   = (const float*)d_in[4];
    float* out = (float*)d_out;

    cudaFuncSetAttribute(projmma_kernel,
                         cudaFuncAttributeMaxDynamicSharedMemorySize, PROJ_SMEM);
    cudaFuncSetAttribute(attn_kernel,
                         cudaFuncAttributeMaxDynamicSharedMemorySize, ATT_SMEM);

    xsplit_kernel<<<dim3(8, 4, NSUP + BQ), 256>>>(supp, qry);
    wsplit_kernel<<<dim3(2, 16), 256>>>(Wqk, Wv);
    projmma_kernel<<<dim3(NMT, 2), 256, PROJ_SMEM>>>(out + OUT1);
    attn_kernel<<<dim3(NTILE, KCLS), 512, ATT_SMEM>>>(out);
}

// round 15
// speedup vs baseline: 5.0594x; 1.0171x over previous
#include <cuda_runtime.h>
#include <cuda_bf16.h>
#include <cstdint>
#include <math.h>

// ---------------------------------------------------------------------------
// Problem constants
// ---------------------------------------------------------------------------
#define BQ 32
#define NSUP 25
#define KCLS 5
#define CIN 512
#define PPIX 196
#define DDIM 128
#define KEYS 980
#define OUT1 (BQ * KCLS * DDIM * PPIX)
#define MTOT (BQ * PPIX)          // 6272 flattened queries
#define NTILE 49                  // 6272 / 128 dense m-tiles (attention)
#define KROWS (NSUP * PPIX + 64)  // K rows padded so last chunk never faults
#define GROWS 11200               // 175 x 64 dense proj rows (28 dead in middle)
#define GQBASE 4928               // queries start row (supports [0,4900))
#define NMT 175

// bf16 hi/lo split scratch (device globals — zero-initialized, no alloc)
__device__ __align__(16) __nv_bfloat16 g_xh[GROWS * CIN];          // [g][c]
__device__ __align__(16) __nv_bfloat16 g_xl[GROWS * CIN];
__device__ __align__(16) __nv_bfloat16 g_wh[2 * DDIM * CIN];       // [qv][d][c]
__device__ __align__(16) __nv_bfloat16 g_wl[2 * DDIM * CIN];
__device__ __align__(16) __nv_bfloat16 g_qh[MTOT * DDIM];          // [g][d]
__device__ __align__(16) __nv_bfloat16 g_ql[MTOT * DDIM];
__device__ __align__(16) __nv_bfloat16 g_kh[KROWS * DDIM];         // [gkey][d]
__device__ __align__(16) __nv_bfloat16 g_kl[KROWS * DDIM];
__device__ __align__(16) __nv_bfloat16 g_vth[KCLS * DDIM * 1024];  // [kc][d][slot]
__device__ __align__(16) __nv_bfloat16 g_vtl[KCLS * DDIM * 1024];  // pads stay 0

// ---------------------------------------------------------------------------
// PTX helpers (baseline PTX, legal on plain sm_103)
// ---------------------------------------------------------------------------
__device__ __forceinline__ void ldsm4(uint32_t addr, uint32_t r[4]) {
    asm volatile("ldmatrix.sync.aligned.m8n8.x4.shared.b16 {%0,%1,%2,%3}, [%4];"
                 : "=r"(r[0]), "=r"(r[1]), "=r"(r[2]), "=r"(r[3]) : "r"(addr));
}
__device__ __forceinline__ void mma16816(float c[4], const uint32_t a[4],
                                         uint32_t b0, uint32_t b1) {
    asm volatile("mma.sync.aligned.m16n8k16.row.col.f32.bf16.bf16.f32 "
                 "{%0,%1,%2,%3}, {%4,%5,%6,%7}, {%8,%9}, {%0,%1,%2,%3};"
                 : "+f"(c[0]), "+f"(c[1]), "+f"(c[2]), "+f"(c[3])
                 : "r"(a[0]), "r"(a[1]), "r"(a[2]), "r"(a[3]), "r"(b0), "r"(b1));
}
__device__ __forceinline__ uint32_t smem_u32(const void* p) {
    uint32_t a;
    asm("{ .reg .u64 t; cvta.to.shared.u64 t, %1; cvt.u32.u64 %0, t; }"
        : "=r"(a) : "l"(p));
    return a;
}
__device__ __forceinline__ uint32_t packbf(float e0, float e1) {
    uint32_t r;   // lower half = e0
    asm("cvt.rn.bf16x2.f32 %0, %1, %2;" : "=r"(r) : "f"(e1), "f"(e0));
    return r;
}
#define CPA16(dst, src) \
    asm volatile("cp.async.ca.shared.global [%0], [%1], 16;" \
                 :: "r"(dst), "l"(src))
#define CPA_COMMIT() asm volatile("cp.async.commit_group;" ::: "memory")
#define CPA_WAIT0()  asm volatile("cp.async.wait_group 0;" ::: "memory")

// ---------------------------------------------------------------------------
// xsplit (+ folded wsplit): features [img][c][p] f32 -> dense transposed
// bf16 hi/lo [g][c]; z-slice 57 splits W_qk/W_v instead.
// grid = (8 c-tiles of 64, 4 p-tiles of 49, 58). block = 256.
// ---------------------------------------------------------------------------
__global__ __launch_bounds__(256) void xsplit_kernel(
    const float* __restrict__ supp, const float* __restrict__ qry,
    const float* __restrict__ Wq, const float* __restrict__ Wv)
{
    __shared__ float xs[64][50];
    const int tid = threadIdx.x;
    const int img = blockIdx.z;

    if (img == NSUP + BQ) {
        // W split: 2 x 128 x 512 elements over 32 blocks x 256 threads
        const int blk = blockIdx.x * 4 + blockIdx.y;   // 0..31
        const int base = blk * 4096;                   // of 131072 total
        for (int i = tid; i < 4096; i += 256) {
            int e = base + i;                          // [qv][d][c] flat
            int qv = e >> 16;
            int rem = e & 65535;
            float v = (qv ? Wv : Wq)[rem];
            __nv_bfloat16 h = __float2bfloat16(v);
            g_wh[e] = h;
            g_wl[e] = __float2bfloat16(v - __bfloat162float(h));
        }
        return;
    }

    const float* x = (img < NSUP) ? supp + (size_t)img * CIN * PPIX
                                  : qry + (size_t)(img - NSUP) * CIN * PPIX;
    const int c0 = blockIdx.x * 64, p0 = blockIdx.y * 49;

    for (int idx = tid; idx < 64 * 49; idx += 256) {
        int c = idx / 49, p = idx - c * 49;
        xs[c][p] = x[(c0 + c) * PPIX + p0 + p];
    }
    __syncthreads();

    const size_t gbase = (img < NSUP) ? (size_t)img * PPIX + p0
                                      : (size_t)GQBASE + (img - NSUP) * PPIX + p0;
    for (int idx = tid; idx < 49 * 64; idx += 256) {
        int p = idx / 64, c = idx - p * 64;
        float v = xs[c][p];
        __nv_bfloat16 h = __float2bfloat16(v);
        size_t o = (gbase + p) * CIN + c0 + c;
        g_xh[o] = h;
        g_xl[o] = __float2bfloat16(v - __bfloat162float(h));
    }
}

// ---------------------------------------------------------------------------
// projmma: out[g][d] = sum_c x[g][c] * W[d][c], 3-split bf16 HMMA,
// DOUBLE-BUFFERED staging (same invariant as attn: top-of-iter wait0+sync;
// prefetch next chunk into other buffer before MMA; commit).
// grid = (175 m-tiles of 64, 2 {qk,v}). block 256, 2 CTAs/SM (221 KB/SM).
// ---------------------------------------------------------------------------
#define AROW 144
#define P_AH 0
#define P_AL (64 * AROW)              // 9216
#define P_WH (2 * 64 * AROW)          // 18432
#define P_WL (P_WH + 128 * AROW)      // 36864
#define PBUFSTR (P_WL + 128 * AROW)   // 55296 per buffer
#define PROJ_SMEM (2 * PBUFSTR)       // 110592

__global__ __launch_bounds__(256, 2) void projmma_kernel(float* __restrict__ outv)
{
    extern __shared__ char smem[];
    const uint32_t sb = smem_u32(smem);
    const int tid = threadIdx.x;
    const int lane = tid & 31;
    const int warp = tid >> 5;
    const int tile = blockIdx.x, qv = blockIdx.y;

    const int m0 = (warp & 3) * 16;
    const int n0 = (warp >> 2) * 64;

    const int a_row = lane & 15;
    const int a_off = (lane >> 4) << 4;
    const int b_row = (lane & 7) | ((lane >> 4) << 3);
    const int b_off = ((lane >> 3) & 1) << 4;

    float oc[8][4];
#pragma unroll
    for (int n = 0; n < 8; n++)
#pragma unroll
        for (int q = 0; q < 4; q++) oc[n][q] = 0.f;

    const char* xh8 = (const char*)(g_xh + (size_t)tile * 64 * CIN);
    const char* xl8 = (const char*)(g_xl + (size_t)tile * 64 * CIN);
    const char* wh8 = (const char*)(g_wh + (size_t)qv * DDIM * CIN);
    const char* wl8 = (const char*)(g_wl + (size_t)qv * DDIM * CIN);

    // prologue: stage chunk 0 into buf0
    for (int idx = tid; idx < 64 * 8; idx += 256) {
        int r = idx >> 3, seg = idx & 7;
        size_t so = (size_t)r * 1024 + seg * 16;
        CPA16(sb + P_AH + r * AROW + seg * 16, xh8 + so);
        CPA16(sb + P_AL + r * AROW + seg * 16, xl8 + so);
    }
    for (int idx = tid; idx < 128 * 8; idx += 256) {
        int n = idx >> 3, seg = idx & 7;
        size_t so = (size_t)n * 1024 + seg * 16;
        CPA16(sb + P_WH + n * AROW + seg * 16, wh8 + so);
        CPA16(sb + P_WL + n * AROW + seg * 16, wl8 + so);
    }
    CPA_COMMIT();

    for (int ch = 0; ch < 8; ch++) {
        CPA_WAIT0();
        __syncthreads();   // staged data visible; prior iter's reads done

        const uint32_t cb = sb + (uint32_t)(ch & 1) * PBUFSTR;

        // prefetch chunk ch+1 into other buffer (overlaps MMA below)
        if (ch + 1 < 8) {
            const uint32_t nb = sb + (uint32_t)((ch + 1) & 1) * PBUFSTR;
            for (int idx = tid; idx < 64 * 8; idx += 256) {
                int r = idx >> 3, seg = idx & 7;
                size_t so = (size_t)r * 1024 + (ch + 1) * 128 + seg * 16;
                CPA16(nb + P_AH + r * AROW + seg * 16, xh8 + so);
                CPA16(nb + P_AL + r * AROW + seg * 16, xl8 + so);
            }
            for (int idx = tid; idx < 128 * 8; idx += 256) {
                int n = idx >> 3, seg = idx & 7;
                size_t so = (size_t)n * 1024 + (ch + 1) * 128 + seg * 16;
                CPA16(nb + P_WH + n * AROW + seg * 16, wh8 + so);
                CPA16(nb + P_WL + n * AROW + seg * 16, wl8 + so);
            }
            CPA_COMMIT();
        }

#pragma unroll
        for (int ks = 0; ks < 4; ks++) {
            const int kb = ks * 32;
            uint32_t ah[4], al[4];
            uint32_t ra = cb + P_AH + (m0 + a_row) * AROW + kb + a_off;
            ldsm4(ra, ah);
            ldsm4(ra + (P_AL - P_AH), al);
#pragma unroll
            for (int nt = 0; nt < 4; nt++) {
                uint32_t bh[4], bl[4];
                uint32_t rb = cb + P_WH + (n0 + nt * 16 + b_row) * AROW + kb + b_off;
                ldsm4(rb, bh);
                ldsm4(rb + (P_WL - P_WH), bl);
#pragma unroll
                for (int t = 0; t < 2; t++) {
                    float* o = oc[nt * 2 + t];
                    mma16816(o, ah, bh[t * 2], bh[t * 2 + 1]);
                    mma16816(o, ah, bl[t * 2], bl[t * 2 + 1]);
                    mma16816(o, al, bh[t * 2], bh[t * 2 + 1]);
                }
            }
        }
    }

    const int gbase = tile * 64;
    if (qv == 0) {
        uint32_t* kh32 = (uint32_t*)g_kh;
        uint32_t* kl32 = (uint32_t*)g_kl;
        uint32_t* qh32 = (uint32_t*)g_qh;
        uint32_t* ql32 = (uint32_t*)g_ql;
        const int r1 = m0 + (lane >> 2);
#pragma unroll
        for (int nt = 0; nt < 8; nt++) {
            const int d = n0 + nt * 8 + 2 * (lane & 3);
#pragma unroll
            for (int half = 0; half < 2; half++) {
                int g = gbase + r1 + half * 8;
                float c0 = oc[nt][half * 2], c1 = oc[nt][half * 2 + 1];
                float h0 = __bfloat162float(__float2bfloat16(c0));
                float h1 = __bfloat162float(__float2bfloat16(c1));
                uint32_t ph = packbf(h0, h1);
                uint32_t pl = packbf(c0 - h0, c1 - h1);
                if (g < NSUP * PPIX) {
                    int o = (g * DDIM + d) >> 1;
                    kh32[o] = ph;
                    kl32[o] = pl;
                } else if (g >= GQBASE) {
                    int o = ((g - GQBASE) * DDIM + d) >> 1;
                    qh32[o] = ph;
                    ql32[o] = pl;
                }
            }
        }
    } else {
        __syncthreads();
        float* Osm = (float*)smem;   // [64][133]
        const int r = m0 + (lane >> 2);
#pragma unroll
        for (int nt = 0; nt < 8; nt++) {
            const int d = n0 + nt * 8 + 2 * (lane & 3);
            Osm[r * 133 + d]           = oc[nt][0];
            Osm[r * 133 + d + 1]       = oc[nt][1];
            Osm[(r + 8) * 133 + d]     = oc[nt][2];
            Osm[(r + 8) * 133 + d + 1] = oc[nt][3];
        }
        __syncthreads();
        for (int idx = tid; idx < 128 * 64; idx += 256) {
            int d = idx >> 6, m = idx & 63;
            int g = gbase + m;
            float v = Osm[m * 133 + d];
            if (g < NSUP * PPIX) {
                int img = g / PPIX, p = g - img * PPIX;
                int cls = img / 5, s = img - cls * 5;
                __nv_bfloat16 h = __float2bfloat16(v);
                size_t o = ((size_t)cls * DDIM + d) * 1024 + s * PPIX + p;
                g_vth[o] = h;
                g_vtl[o] = __float2bfloat16(v - __bfloat162float(h));
            } else if (g >= GQBASE) {
                int qi = g - GQBASE;
                int img = qi / PPIX, p = qi - img * PPIX;
                outv[((size_t)img * DDIM + d) * PPIX + p] = v;
            }
        }
    }
}

// ---------------------------------------------------------------------------
// FlashAttention-style mma.sync attention (UNCHANGED from R14 — proven).
// M=128 per CTA, 512 threads, 1 CTA/SM, K/V double-buffered.
// grid = (49 dense m-tiles of 128, 5 classes) = 245 CTAs.
// ---------------------------------------------------------------------------
#define NCHUNK 16
#define QROW 272            // 128 bf16 + 16B pad
#define VROW 144            // 64 bf16 + 16B pad
#define OFF_QH 0
#define OFF_QL 34816
#define OFF_BUF0 69632      // double-buffered region: [KH KL VH VL] x 2
#define BUFSTR 71680
#define B_KH 0
#define B_KL 17408
#define B_VH 34816
#define B_VL 53248
#define OFF_DS (OFF_BUF0 + 2 * BUFSTR + 128)   // 213120
#define ATT_SMEM (OFF_DS + 512)                // 213632

__global__ __launch_bounds__(512, 1) void attn_kernel(float* __restrict__ out)
{
    extern __shared__ char smem[];
    const uint32_t sb = smem_u32(smem);
    float* dsumf = (float*)(smem + OFF_DS);

    const int tid = threadIdx.x;
    const int lane = tid & 31;
    const int warp = tid >> 5;
    const int tile = blockIdx.x, kc = blockIdx.y;

    const int m0 = (warp & 7) * 16;      // warp m base (0..112)
    const int h32 = (warp >> 3) * 32;    // warp key-half base within chunk

    const int a_row = lane & 15;
    const int a_off = (lane >> 4) << 4;
    const int b_row = (lane & 7) | ((lane >> 4) << 3);
    const int b_off = ((lane >> 3) & 1) << 4;

    const char* kh8 = (const char*)(g_kh + (size_t)kc * KEYS * DDIM);
    const char* kl8 = (const char*)(g_kl + (size_t)kc * KEYS * DDIM);
    const char* vh8 = (const char*)(g_vth + (size_t)kc * DDIM * 1024);
    const char* vl8 = (const char*)(g_vtl + (size_t)kc * DDIM * 1024);

    // ---- prologue: stage Q + chunk 0 K/V into buf0 (one group) ----
    {
        const char* qh8 = (const char*)(g_qh + (size_t)tile * 128 * DDIM);
        const char* ql8 = (const char*)(g_ql + (size_t)tile * 128 * DDIM);
        for (int idx = tid; idx < 128 * 16; idx += 512) {
            int r = idx >> 4, seg = idx & 15;
            CPA16(sb + OFF_QH + r * QROW + seg * 16, qh8 + r * 256 + seg * 16);
            CPA16(sb + OFF_QL + r * QROW + seg * 16, ql8 + r * 256 + seg * 16);
        }
        for (int idx = tid; idx < 64 * 16; idx += 512) {
            int j = idx >> 4, seg = idx & 15;
            const size_t so = (size_t)j * 256 + seg * 16;
            CPA16(sb + OFF_BUF0 + B_KH + j * QROW + seg * 16, kh8 + so);
            CPA16(sb + OFF_BUF0 + B_KL + j * QROW + seg * 16, kl8 + so);
        }
        for (int idx = tid; idx < 128 * 8; idx += 512) {
            int d = idx >> 3, seg = idx & 7;
            const size_t so = (size_t)d * 2048 + seg * 16;
            CPA16(sb + OFF_BUF0 + B_VH + d * VROW + seg * 16, vh8 + so);
            CPA16(sb + OFF_BUF0 + B_VL + d * VROW + seg * 16, vl8 + so);
        }
        CPA_COMMIT();
    }
    if (tid < 128) dsumf[tid] = 0.f;

    // O accumulators: [16m x 128d] per warp (16 n-tiles x 4 regs)
    float oc[16][4];
#pragma unroll
    for (int n = 0; n < 16; n++)
#pragma unroll
        for (int q = 0; q < 4; q++) oc[n][q] = 0.f;

    for (int ch = 0; ch < NCHUNK; ch++) {
        CPA_WAIT0();       // all staged data (incl. this chunk's) complete
        __syncthreads();   // visible to all; prior chunk's reads also done

        const uint32_t kb0 = OFF_BUF0 + (ch & 1) * BUFSTR;

        // ---- S = Qh.Kh^T + Qh.Kl^T + Ql.Kh^T  (16m x 32j per warp) ----
        float sc[4][4];
#pragma unroll
        for (int n = 0; n < 4; n++)
#pragma unroll
            for (int q = 0; q < 4; q++) sc[n][q] = 0.f;

#pragma unroll
        for (int k = 0; k < 8; k++) {
            const int kb = k * 32;
            uint32_t ah[4], al[4], bh0[4], bh1[4], bl0[4], bl1[4];
            uint32_t ra = sb + OFF_QH + (m0 + a_row) * QROW + kb + a_off;
            ldsm4(ra, ah);
            ldsm4(ra + (OFF_QL - OFF_QH), al);
            uint32_t rb = sb + kb0 + B_KH + (h32 + b_row) * QROW + kb + b_off;
            ldsm4(rb, bh0);
            ldsm4(rb + 16 * QROW, bh1);
            ldsm4(rb + (B_KL - B_KH), bl0);
            ldsm4(rb + (B_KL - B_KH) + 16 * QROW, bl1);
#pragma unroll
            for (int n = 0; n < 4; n++) {
                uint32_t h0 = (n < 2) ? bh0[(n & 1) * 2] : bh1[(n & 1) * 2];
                uint32_t h1 = (n < 2) ? bh0[(n & 1) * 2 + 1] : bh1[(n & 1) * 2 + 1];
                uint32_t l0 = (n < 2) ? bl0[(n & 1) * 2] : bl1[(n & 1) * 2];
                uint32_t l1 = (n < 2) ? bl0[(n & 1) * 2 + 1] : bl1[(n & 1) * 2 + 1];
                mma16816(sc[n], ah, h0, h1);
                mma16816(sc[n], ah, l0, l1);
                mma16816(sc[n], al, h0, h1);
            }
        }

        // ---- exp (exact key mask) -> row sums -> E A-frags in registers ----
        uint32_t ehf[2][4], elf[2][4];
        {
            float rs0 = 0.f, rs1 = 0.f;
            const int r = m0 + (lane >> 2);
#pragma unroll
            for (int n = 0; n < 4; n++) {
                int jg = ch * 64 + h32 + n * 8 + 2 * (lane & 3);
                float e0 = (jg     < KEYS) ? __expf(sc[n][0]) : 0.f;
                float e1 = (jg + 1 < KEYS) ? __expf(sc[n][1]) : 0.f;
                float e2 = (jg     < KEYS) ? __expf(sc[n][2]) : 0.f;
                float e3 = (jg + 1 < KEYS) ? __expf(sc[n][3]) : 0.f;
                rs0 += e0 + e1;
                rs1 += e2 + e3;
                float h0 = __bfloat162float(__float2bfloat16(e0));
                float h1 = __bfloat162float(__float2bfloat16(e1));
                float h2 = __bfloat162float(__float2bfloat16(e2));
                float h3 = __bfloat162float(__float2bfloat16(e3));
                ehf[n >> 1][(n & 1) * 2]     = packbf(h0, h1);
                ehf[n >> 1][(n & 1) * 2 + 1] = packbf(h2, h3);
                elf[n >> 1][(n & 1) * 2]     = packbf(e0 - h0, e1 - h1);
                elf[n >> 1][(n & 1) * 2 + 1] = packbf(e2 - h2, e3 - h3);
            }
            rs0 += __shfl_xor_sync(0xFFFFFFFFu, rs0, 1);
            rs0 += __shfl_xor_sync(0xFFFFFFFFu, rs0, 2);
            rs1 += __shfl_xor_sync(0xFFFFFFFFu, rs1, 1);
            rs1 += __shfl_xor_sync(0xFFFFFFFFu, rs1, 2);
            if ((lane & 3) == 0) {
                atomicAdd(&dsumf[r], rs0);
                atomicAdd(&dsumf[r + 8], rs1);
            }
        }

        // ---- prefetch chunk ch+1 into the other buffer (overlaps PV) ----
        if (ch + 1 < NCHUNK) {
            const uint32_t nb = sb + OFF_BUF0 + ((ch + 1) & 1) * BUFSTR;
            for (int idx = tid; idx < 64 * 16; idx += 512) {
                int j = idx >> 4, seg = idx & 15;
                const size_t so = (size_t)((ch + 1) * 64 + j) * 256 + seg * 16;
                CPA16(nb + B_KH + j * QROW + seg * 16, kh8 + so);
                CPA16(nb + B_KL + j * QROW + seg * 16, kl8 + so);
            }
            for (int idx = tid; idx < 128 * 8; idx += 512) {
                int d = idx >> 3, seg = idx & 7;
                const size_t so = (size_t)d * 2048 + (ch + 1) * 128 + seg * 16;
                CPA16(nb + B_VH + d * VROW + seg * 16, vh8 + so);
                CPA16(nb + B_VL + d * VROW + seg * 16, vl8 + so);
            }
            CPA_COMMIT();
        }

        // ---- O += Eh.Vh + El.Vh + Eh.Vl  (16m x 128d, E from registers) ----
#pragma unroll
        for (int kk = 0; kk < 2; kk++) {
            const int kcol = (h32 + kk * 16) * 2;
#pragma unroll
            for (int dh = 0; dh < 2; dh++) {
                uint32_t vv[4][4];
#pragma unroll
                for (int nd = 0; nd < 4; nd++)
                    ldsm4(sb + kb0 + B_VH + (dh * 64 + nd * 16 + b_row) * VROW + kcol + b_off,
                          vv[nd]);
#pragma unroll
                for (int nd = 0; nd < 4; nd++)
#pragma unroll
                    for (int t = 0; t < 2; t++) {
                        float* o = oc[dh * 8 + nd * 2 + t];
                        mma16816(o, ehf[kk], vv[nd][t * 2], vv[nd][t * 2 + 1]);
                        mma16816(o, elf[kk], vv[nd][t * 2], vv[nd][t * 2 + 1]);
                    }
#pragma unroll
                for (int nd = 0; nd < 4; nd++)
                    ldsm4(sb + kb0 + B_VL + (dh * 64 + nd * 16 + b_row) * VROW + kcol + b_off,
                          vv[nd]);
#pragma unroll
                for (int nd = 0; nd < 4; nd++)
#pragma unroll
                    for (int t = 0; t < 2; t++)
                        mma16816(oc[dh * 8 + nd * 2 + t], ehf[kk],
                                 vv[nd][t * 2], vv[nd][t * 2 + 1]);
            }
        }
    }

    // ---- epilogue: sum key-half partners via smem, normalize, write ----
    __syncthreads();
    float* Osm = (float*)smem;   // [128][133] f32 = 68,096 B, reuses Q region
    const int r = m0 + (lane >> 2);
    if (warp < 8) {
#pragma unroll
        for (int n = 0; n < 16; n++) {
            int d = n * 8 + 2 * (lane & 3);
            Osm[r * 133 + d]           = oc[n][0];
            Osm[r * 133 + d + 1]       = oc[n][1];
            Osm[(r + 8) * 133 + d]     = oc[n][2];
            Osm[(r + 8) * 133 + d + 1] = oc[n][3];
        }
    }
    __syncthreads();
    if (warp >= 8) {
#pragma unroll
        for (int n = 0; n < 16; n++) {
            int d = n * 8 + 2 * (lane & 3);
            Osm[r * 133 + d]           += oc[n][0];
            Osm[r * 133 + d + 1]       += oc[n][1];
            Osm[(r + 8) * 133 + d]     += oc[n][2];
            Osm[(r + 8) * 133 + d + 1] += oc[n][3];
        }
    }
    __syncthreads();

    // row m -> global query g = tile*128 + m -> (b, p); out[b][kc][d*196+p]
    for (int idx = tid; idx < 128 * 128; idx += 512) {
        int d = idx >> 7, m = idx & 127;
        int g = tile * 128 + m;
        int bb = g / PPIX, p = g - bb * PPIX;
        out[((bb * KCLS + kc) * DDIM + d) * PPIX + p] = Osm[m * 133 + d] / dsumf[m];
    }
}

// ---------------------------------------------------------------------------
// kernel_launch
// ---------------------------------------------------------------------------
extern "C" void kernel_launch(void* const* d_in, const int* in_sizes, int n_in,
                              void* d_out, int out_size)
{
    const float* supp = (const float*)d_in[0];
    const float* qry  = (const float*)d_in[1];
    const float* Wqk  = (const float*)d_in[3];
    const float* Wv   = (const float*)d_in[4];
    float* out = (float*)d_out;

    cudaFuncSetAttribute(projmma_kernel,
                         cudaFuncAttributeMaxDynamicSharedMemorySize, PROJ_SMEM);
    cudaFuncSetAttribute(attn_kernel,
                         cudaFuncAttributeMaxDynamicSharedMemorySize, ATT_SMEM);

    xsplit_kernel<<<dim3(8, 4, NSUP + BQ + 1), 256>>>(supp, qry, Wqk, Wv);
    projmma_kernel<<<dim3(NMT, 2), 256, PROJ_SMEM>>>(out + OUT1);
    attn_kernel<<<dim3(NTILE, KCLS), 512, ATT_SMEM>>>(out);
}

// round 16
// speedup vs baseline: 5.0688x; 1.0019x over previous
#include <cuda_runtime.h>
#include <cuda_bf16.h>
#include <cstdint>
#include <math.h>

// ---------------------------------------------------------------------------
// Problem constants
// ---------------------------------------------------------------------------
#define BQ 32
#define NSUP 25
#define KCLS 5
#define CIN 512
#define PPIX 196
#define DDIM 128
#define KEYS 980
#define OUT1 (BQ * KCLS * DDIM * PPIX)
#define MTOT (BQ * PPIX)          // 6272 flattened queries
#define NTILE 49                  // 6272 / 128 dense m-tiles (attention)
#define KROWS (NSUP * PPIX + 64)  // K rows padded so last chunk never faults
#define GROWS 11200               // 175 x 64 dense proj rows (28 dead in middle)
#define GQBASE 4928               // queries start row (supports [0,4900))
#define NMT 175

// bf16 hi/lo split scratch (device globals — zero-initialized, no alloc)
__device__ __align__(16) __nv_bfloat16 g_xh[GROWS * CIN];          // [g][c]
__device__ __align__(16) __nv_bfloat16 g_xl[GROWS * CIN];
__device__ __align__(16) __nv_bfloat16 g_wh[2 * DDIM * CIN];       // [qv][d][c]
__device__ __align__(16) __nv_bfloat16 g_wl[2 * DDIM * CIN];
__device__ __align__(16) __nv_bfloat16 g_qh[MTOT * DDIM];          // [g][d]
__device__ __align__(16) __nv_bfloat16 g_ql[MTOT * DDIM];
__device__ __align__(16) __nv_bfloat16 g_kh[KROWS * DDIM];         // [gkey][d]
__device__ __align__(16) __nv_bfloat16 g_kl[KROWS * DDIM];
__device__ __align__(16) __nv_bfloat16 g_vth[KCLS * DDIM * 1024];  // [kc][d][slot]
__device__ __align__(16) __nv_bfloat16 g_vtl[KCLS * DDIM * 1024];  // pads stay 0

// ---------------------------------------------------------------------------
// PTX helpers (baseline PTX, legal on plain sm_103)
// ---------------------------------------------------------------------------
__device__ __forceinline__ void ldsm4(uint32_t addr, uint32_t r[4]) {
    asm volatile("ldmatrix.sync.aligned.m8n8.x4.shared.b16 {%0,%1,%2,%3}, [%4];"
                 : "=r"(r[0]), "=r"(r[1]), "=r"(r[2]), "=r"(r[3]) : "r"(addr));
}
__device__ __forceinline__ void mma16816(float c[4], const uint32_t a[4],
                                         uint32_t b0, uint32_t b1) {
    asm volatile("mma.sync.aligned.m16n8k16.row.col.f32.bf16.bf16.f32 "
                 "{%0,%1,%2,%3}, {%4,%5,%6,%7}, {%8,%9}, {%0,%1,%2,%3};"
                 : "+f"(c[0]), "+f"(c[1]), "+f"(c[2]), "+f"(c[3])
                 : "r"(a[0]), "r"(a[1]), "r"(a[2]), "r"(a[3]), "r"(b0), "r"(b1));
}
__device__ __forceinline__ uint32_t smem_u32(const void* p) {
    uint32_t a;
    asm("{ .reg .u64 t; cvta.to.shared.u64 t, %1; cvt.u32.u64 %0, t; }"
        : "=r"(a) : "l"(p));
    return a;
}
__device__ __forceinline__ uint32_t packbf(float e0, float e1) {
    uint32_t r;   // lower half = e0
    asm("cvt.rn.bf16x2.f32 %0, %1, %2;" : "=r"(r) : "f"(e1), "f"(e0));
    return r;
}
#define CPA16(dst, src) \
    asm volatile("cp.async.ca.shared.global [%0], [%1], 16;" \
                 :: "r"(dst), "l"(src))
#define CPA_COMMIT() asm volatile("cp.async.commit_group;" ::: "memory")
#define CPA_WAIT0()  asm volatile("cp.async.wait_group 0;" ::: "memory")

// ---------------------------------------------------------------------------
// xsplit (+ folded wsplit): features [img][c][p] f32 -> dense transposed
// bf16 hi/lo [g][c]. Vectorized: float4 global reads (p-tiles of 28 keep
// 16B alignment), packed bf16x2 stores (2 channels per 32-bit store).
// grid = (8 c-tiles of 64, 7 p-tiles of 28, 58); z=57 slices split W.
// ---------------------------------------------------------------------------
__global__ __launch_bounds__(256) void xsplit_kernel(
    const float* __restrict__ supp, const float* __restrict__ qry,
    const float* __restrict__ Wq, const float* __restrict__ Wv)
{
    __shared__ float xs[64][29];
    const int tid = threadIdx.x;
    const int img = blockIdx.z;

    if (img == NSUP + BQ) {
        // W split: 2 x 128 x 512 elements over the first 32 of 56 blocks
        const int blk = blockIdx.x * 7 + blockIdx.y;   // 0..55
        if (blk >= 32) return;
        const int base = blk * 4096;                   // of 131072 total
        for (int i = tid; i < 4096; i += 256) {
            int e = base + i;                          // [qv][d][c] flat
            int qv = e >> 16;
            int rem = e & 65535;
            float v = (qv ? Wv : Wq)[rem];
            __nv_bfloat16 h = __float2bfloat16(v);
            g_wh[e] = h;
            g_wl[e] = __float2bfloat16(v - __bfloat162float(h));
        }
        return;
    }

    const float* x = (img < NSUP) ? supp + (size_t)img * CIN * PPIX
                                  : qry + (size_t)(img - NSUP) * CIN * PPIX;
    const int c0 = blockIdx.x * 64, p0 = blockIdx.y * 28;

    // Phase 1: float4 loads, 64 rows x 7 float4 = 448 vectors
    for (int idx = tid; idx < 64 * 7; idx += 256) {
        int c = idx / 7, q4 = idx - c * 7;
        float4 v = *(const float4*)(x + (size_t)(c0 + c) * PPIX + p0 + q4 * 4);
        xs[c][q4 * 4]     = v.x;
        xs[c][q4 * 4 + 1] = v.y;
        xs[c][q4 * 4 + 2] = v.z;
        xs[c][q4 * 4 + 3] = v.w;
    }
    __syncthreads();

    // Phase 2: transpose + split + packed stores (2 channels / 32-bit word)
    const size_t gbase = (img < NSUP) ? (size_t)img * PPIX + p0
                                      : (size_t)GQBASE + (img - NSUP) * PPIX + p0;
    uint32_t* xh32 = (uint32_t*)g_xh;
    uint32_t* xl32 = (uint32_t*)g_xl;
    for (int idx = tid; idx < 28 * 32; idx += 256) {
        int p = idx >> 5, cp = idx & 31;       // cp = channel pair
        float v0 = xs[2 * cp][p];
        float v1 = xs[2 * cp + 1][p];
        float h0 = __bfloat162float(__float2bfloat16(v0));
        float h1 = __bfloat162float(__float2bfloat16(v1));
        size_t o = ((gbase + p) * CIN + c0) / 2 + cp;
        xh32[o] = packbf(h0, h1);
        xl32[o] = packbf(v0 - h0, v1 - h1);
    }
}

// ---------------------------------------------------------------------------
// projmma: out[g][d] = sum_c x[g][c] * W[d][c], 3-split bf16 HMMA,
// DOUBLE-BUFFERED staging (same invariant as attn: top-of-iter wait0+sync;
// prefetch next chunk into other buffer before MMA; commit).
// grid = (175 m-tiles of 64, 2 {qk,v}). block 256, 2 CTAs/SM (221 KB/SM).
// ---------------------------------------------------------------------------
#define AROW 144
#define P_AH 0
#define P_AL (64 * AROW)              // 9216
#define P_WH (2 * 64 * AROW)          // 18432
#define P_WL (P_WH + 128 * AROW)      // 36864
#define PBUFSTR (P_WL + 128 * AROW)   // 55296 per buffer
#define PROJ_SMEM (2 * PBUFSTR)       // 110592

__global__ __launch_bounds__(256, 2) void projmma_kernel(float* __restrict__ outv)
{
    extern __shared__ char smem[];
    const uint32_t sb = smem_u32(smem);
    const int tid = threadIdx.x;
    const int lane = tid & 31;
    const int warp = tid >> 5;
    const int tile = blockIdx.x, qv = blockIdx.y;

    const int m0 = (warp & 3) * 16;
    const int n0 = (warp >> 2) * 64;

    const int a_row = lane & 15;
    const int a_off = (lane >> 4) << 4;
    const int b_row = (lane & 7) | ((lane >> 4) << 3);
    const int b_off = ((lane >> 3) & 1) << 4;

    float oc[8][4];
#pragma unroll
    for (int n = 0; n < 8; n++)
#pragma unroll
        for (int q = 0; q < 4; q++) oc[n][q] = 0.f;

    const char* xh8 = (const char*)(g_xh + (size_t)tile * 64 * CIN);
    const char* xl8 = (const char*)(g_xl + (size_t)tile * 64 * CIN);
    const char* wh8 = (const char*)(g_wh + (size_t)qv * DDIM * CIN);
    const char* wl8 = (const char*)(g_wl + (size_t)qv * DDIM * CIN);

    // prologue: stage chunk 0 into buf0
    for (int idx = tid; idx < 64 * 8; idx += 256) {
        int r = idx >> 3, seg = idx & 7;
        size_t so = (size_t)r * 1024 + seg * 16;
        CPA16(sb + P_AH + r * AROW + seg * 16, xh8 + so);
        CPA16(sb + P_AL + r * AROW + seg * 16, xl8 + so);
    }
    for (int idx = tid; idx < 128 * 8; idx += 256) {
        int n = idx >> 3, seg = idx & 7;
        size_t so = (size_t)n * 1024 + seg * 16;
        CPA16(sb + P_WH + n * AROW + seg * 16, wh8 + so);
        CPA16(sb + P_WL + n * AROW + seg * 16, wl8 + so);
    }
    CPA_COMMIT();

    for (int ch = 0; ch < 8; ch++) {
        CPA_WAIT0();
        __syncthreads();   // staged data visible; prior iter's reads done

        const uint32_t cb = sb + (uint32_t)(ch & 1) * PBUFSTR;

        // prefetch chunk ch+1 into other buffer (overlaps MMA below)
        if (ch + 1 < 8) {
            const uint32_t nb = sb + (uint32_t)((ch + 1) & 1) * PBUFSTR;
            for (int idx = tid; idx < 64 * 8; idx += 256) {
                int r = idx >> 3, seg = idx & 7;
                size_t so = (size_t)r * 1024 + (ch + 1) * 128 + seg * 16;
                CPA16(nb + P_AH + r * AROW + seg * 16, xh8 + so);
                CPA16(nb + P_AL + r * AROW + seg * 16, xl8 + so);
            }
            for (int idx = tid; idx < 128 * 8; idx += 256) {
                int n = idx >> 3, seg = idx & 7;
                size_t so = (size_t)n * 1024 + (ch + 1) * 128 + seg * 16;
                CPA16(nb + P_WH + n * AROW + seg * 16, wh8 + so);
                CPA16(nb + P_WL + n * AROW + seg * 16, wl8 + so);
            }
            CPA_COMMIT();
        }

#pragma unroll
        for (int ks = 0; ks < 4; ks++) {
            const int kb = ks * 32;
            uint32_t ah[4], al[4];
            uint32_t ra = cb + P_AH + (m0 + a_row) * AROW + kb + a_off;
            ldsm4(ra, ah);
            ldsm4(ra + (P_AL - P_AH), al);
#pragma unroll
            for (int nt = 0; nt < 4; nt++) {
                uint32_t bh[4], bl[4];
                uint32_t rb = cb + P_WH + (n0 + nt * 16 + b_row) * AROW + kb + b_off;
                ldsm4(rb, bh);
                ldsm4(rb + (P_WL - P_WH), bl);
#pragma unroll
                for (int t = 0; t < 2; t++) {
                    float* o = oc[nt * 2 + t];
                    mma16816(o, ah, bh[t * 2], bh[t * 2 + 1]);
                    mma16816(o, ah, bl[t * 2], bl[t * 2 + 1]);
                    mma16816(o, al, bh[t * 2], bh[t * 2 + 1]);
                }
            }
        }
    }

    const int gbase = tile * 64;
    if (qv == 0) {
        uint32_t* kh32 = (uint32_t*)g_kh;
        uint32_t* kl32 = (uint32_t*)g_kl;
        uint32_t* qh32 = (uint32_t*)g_qh;
        uint32_t* ql32 = (uint32_t*)g_ql;
        const int r1 = m0 + (lane >> 2);
#pragma unroll
        for (int nt = 0; nt < 8; nt++) {
            const int d = n0 + nt * 8 + 2 * (lane & 3);
#pragma unroll
            for (int half = 0; half < 2; half++) {
                int g = gbase + r1 + half * 8;
                float c0 = oc[nt][half * 2], c1 = oc[nt][half * 2 + 1];
                float h0 = __bfloat162float(__float2bfloat16(c0));
                float h1 = __bfloat162float(__float2bfloat16(c1));
                uint32_t ph = packbf(h0, h1);
                uint32_t pl = packbf(c0 - h0, c1 - h1);
                if (g < NSUP * PPIX) {
                    int o = (g * DDIM + d) >> 1;
                    kh32[o] = ph;
                    kl32[o] = pl;
                } else if (g >= GQBASE) {
                    int o = ((g - GQBASE) * DDIM + d) >> 1;
                    qh32[o] = ph;
                    ql32[o] = pl;
                }
            }
        }
    } else {
        __syncthreads();
        float* Osm = (float*)smem;   // [64][133]
        const int r = m0 + (lane >> 2);
#pragma unroll
        for (int nt = 0; nt < 8; nt++) {
            const int d = n0 + nt * 8 + 2 * (lane & 3);
            Osm[r * 133 + d]           = oc[nt][0];
            Osm[r * 133 + d + 1]       = oc[nt][1];
            Osm[(r + 8) * 133 + d]     = oc[nt][2];
            Osm[(r + 8) * 133 + d + 1] = oc[nt][3];
        }
        __syncthreads();
        for (int idx = tid; idx < 128 * 64; idx += 256) {
            int d = idx >> 6, m = idx & 63;
            int g = gbase + m;
            float v = Osm[m * 133 + d];
            if (g < NSUP * PPIX) {
                int img = g / PPIX, p = g - img * PPIX;
                int cls = img / 5, s = img - cls * 5;
                __nv_bfloat16 h = __float2bfloat16(v);
                size_t o = ((size_t)cls * DDIM + d) * 1024 + s * PPIX + p;
                g_vth[o] = h;
                g_vtl[o] = __float2bfloat16(v - __bfloat162float(h));
            } else if (g >= GQBASE) {
                int qi = g - GQBASE;
                int img = qi / PPIX, p = qi - img * PPIX;
                outv[((size_t)img * DDIM + d) * PPIX + p] = v;
            }
        }
    }
}

// ---------------------------------------------------------------------------
// FlashAttention-style mma.sync attention (UNCHANGED from R14 — proven).
// M=128 per CTA, 512 threads, 1 CTA/SM, K/V double-buffered.
// grid = (49 dense m-tiles of 128, 5 classes) = 245 CTAs.
// ---------------------------------------------------------------------------
#define NCHUNK 16
#define QROW 272            // 128 bf16 + 16B pad
#define VROW 144            // 64 bf16 + 16B pad
#define OFF_QH 0
#define OFF_QL 34816
#define OFF_BUF0 69632      // double-buffered region: [KH KL VH VL] x 2
#define BUFSTR 71680
#define B_KH 0
#define B_KL 17408
#define B_VH 34816
#define B_VL 53248
#define OFF_DS (OFF_BUF0 + 2 * BUFSTR + 128)   // 213120
#define ATT_SMEM (OFF_DS + 512)                // 213632

__global__ __launch_bounds__(512, 1) void attn_kernel(float* __restrict__ out)
{
    extern __shared__ char smem[];
    const uint32_t sb = smem_u32(smem);
    float* dsumf = (float*)(smem + OFF_DS);

    const int tid = threadIdx.x;
    const int lane = tid & 31;
    const int warp = tid >> 5;
    const int tile = blockIdx.x, kc = blockIdx.y;

    const int m0 = (warp & 7) * 16;      // warp m base (0..112)
    const int h32 = (warp >> 3) * 32;    // warp key-half base within chunk

    const int a_row = lane & 15;
    const int a_off = (lane >> 4) << 4;
    const int b_row = (lane & 7) | ((lane >> 4) << 3);
    const int b_off = ((lane >> 3) & 1) << 4;

    const char* kh8 = (const char*)(g_kh + (size_t)kc * KEYS * DDIM);
    const char* kl8 = (const char*)(g_kl + (size_t)kc * KEYS * DDIM);
    const char* vh8 = (const char*)(g_vth + (size_t)kc * DDIM * 1024);
    const char* vl8 = (const char*)(g_vtl + (size_t)kc * DDIM * 1024);

    // ---- prologue: stage Q + chunk 0 K/V into buf0 (one group) ----
    {
        const char* qh8 = (const char*)(g_qh + (size_t)tile * 128 * DDIM);
        const char* ql8 = (const char*)(g_ql + (size_t)tile * 128 * DDIM);
        for (int idx = tid; idx < 128 * 16; idx += 512) {
            int r = idx >> 4, seg = idx & 15;
            CPA16(sb + OFF_QH + r * QROW + seg * 16, qh8 + r * 256 + seg * 16);
            CPA16(sb + OFF_QL + r * QROW + seg * 16, ql8 + r * 256 + seg * 16);
        }
        for (int idx = tid; idx < 64 * 16; idx += 512) {
            int j = idx >> 4, seg = idx & 15;
            const size_t so = (size_t)j * 256 + seg * 16;
            CPA16(sb + OFF_BUF0 + B_KH + j * QROW + seg * 16, kh8 + so);
            CPA16(sb + OFF_BUF0 + B_KL + j * QROW + seg * 16, kl8 + so);
        }
        for (int idx = tid; idx < 128 * 8; idx += 512) {
            int d = idx >> 3, seg = idx & 7;
            const size_t so = (size_t)d * 2048 + seg * 16;
            CPA16(sb + OFF_BUF0 + B_VH + d * VROW + seg * 16, vh8 + so);
            CPA16(sb + OFF_BUF0 + B_VL + d * VROW + seg * 16, vl8 + so);
        }
        CPA_COMMIT();
    }
    if (tid < 128) dsumf[tid] = 0.f;

    // O accumulators: [16m x 128d] per warp (16 n-tiles x 4 regs)
    float oc[16][4];
#pragma unroll
    for (int n = 0; n < 16; n++)
#pragma unroll
        for (int q = 0; q < 4; q++) oc[n][q] = 0.f;

    for (int ch = 0; ch < NCHUNK; ch++) {
        CPA_WAIT0();       // all staged data (incl. this chunk's) complete
        __syncthreads();   // visible to all; prior chunk's reads also done

        const uint32_t kb0 = OFF_BUF0 + (ch & 1) * BUFSTR;

        // ---- S = Qh.Kh^T + Qh.Kl^T + Ql.Kh^T  (16m x 32j per warp) ----
        float sc[4][4];
#pragma unroll
        for (int n = 0; n < 4; n++)
#pragma unroll
            for (int q = 0; q < 4; q++) sc[n][q] = 0.f;

#pragma unroll
        for (int k = 0; k < 8; k++) {
            const int kb = k * 32;
            uint32_t ah[4], al[4], bh0[4], bh1[4], bl0[4], bl1[4];
            uint32_t ra = sb + OFF_QH + (m0 + a_row) * QROW + kb + a_off;
            ldsm4(ra, ah);
            ldsm4(ra + (OFF_QL - OFF_QH), al);
            uint32_t rb = sb + kb0 + B_KH + (h32 + b_row) * QROW + kb + b_off;
            ldsm4(rb, bh0);
            ldsm4(rb + 16 * QROW, bh1);
            ldsm4(rb + (B_KL - B_KH), bl0);
            ldsm4(rb + (B_KL - B_KH) + 16 * QROW, bl1);
#pragma unroll
            for (int n = 0; n < 4; n++) {
                uint32_t h0 = (n < 2) ? bh0[(n & 1) * 2] : bh1[(n & 1) * 2];
                uint32_t h1 = (n < 2) ? bh0[(n & 1) * 2 + 1] : bh1[(n & 1) * 2 + 1];
                uint32_t l0 = (n < 2) ? bl0[(n & 1) * 2] : bl1[(n & 1) * 2];
                uint32_t l1 = (n < 2) ? bl0[(n & 1) * 2 + 1] : bl1[(n & 1) * 2 + 1];
                mma16816(sc[n], ah, h0, h1);
                mma16816(sc[n], ah, l0, l1);
                mma16816(sc[n], al, h0, h1);
            }
        }

        // ---- exp (exact key mask) -> row sums -> E A-frags in registers ----
        uint32_t ehf[2][4], elf[2][4];
        {
            float rs0 = 0.f, rs1 = 0.f;
            const int r = m0 + (lane >> 2);
#pragma unroll
            for (int n = 0; n < 4; n++) {
                int jg = ch * 64 + h32 + n * 8 + 2 * (lane & 3);
                float e0 = (jg     < KEYS) ? __expf(sc[n][0]) : 0.f;
                float e1 = (jg + 1 < KEYS) ? __expf(sc[n][1]) : 0.f;
                float e2 = (jg     < KEYS) ? __expf(sc[n][2]) : 0.f;
                float e3 = (jg + 1 < KEYS) ? __expf(sc[n][3]) : 0.f;
                rs0 += e0 + e1;
                rs1 += e2 + e3;
                float h0 = __bfloat162float(__float2bfloat16(e0));
                float h1 = __bfloat162float(__float2bfloat16(e1));
                float h2 = __bfloat162float(__float2bfloat16(e2));
                float h3 = __bfloat162float(__float2bfloat16(e3));
                ehf[n >> 1][(n & 1) * 2]     = packbf(h0, h1);
                ehf[n >> 1][(n & 1) * 2 + 1] = packbf(h2, h3);
                elf[n >> 1][(n & 1) * 2]     = packbf(e0 - h0, e1 - h1);
                elf[n >> 1][(n & 1) * 2 + 1] = packbf(e2 - h2, e3 - h3);
            }
            rs0 += __shfl_xor_sync(0xFFFFFFFFu, rs0, 1);
            rs0 += __shfl_xor_sync(0xFFFFFFFFu, rs0, 2);
            rs1 += __shfl_xor_sync(0xFFFFFFFFu, rs1, 1);
            rs1 += __shfl_xor_sync(0xFFFFFFFFu, rs1, 2);
            if ((lane & 3) == 0) {
                atomicAdd(&dsumf[r], rs0);
                atomicAdd(&dsumf[r + 8], rs1);
            }
        }

        // ---- prefetch chunk ch+1 into the other buffer (overlaps PV) ----
        if (ch + 1 < NCHUNK) {
            const uint32_t nb = sb + OFF_BUF0 + ((ch + 1) & 1) * BUFSTR;
            for (int idx = tid; idx < 64 * 16; idx += 512) {
                int j = idx >> 4, seg = idx & 15;
                const size_t so = (size_t)((ch + 1) * 64 + j) * 256 + seg * 16;
                CPA16(nb + B_KH + j * QROW + seg * 16, kh8 + so);
                CPA16(nb + B_KL + j * QROW + seg * 16, kl8 + so);
            }
            for (int idx = tid; idx < 128 * 8; idx += 512) {
                int d = idx >> 3, seg = idx & 7;
                const size_t so = (size_t)d * 2048 + (ch + 1) * 128 + seg * 16;
                CPA16(nb + B_VH + d * VROW + seg * 16, vh8 + so);
                CPA16(nb + B_VL + d * VROW + seg * 16, vl8 + so);
            }
            CPA_COMMIT();
        }

        // ---- O += Eh.Vh + El.Vh + Eh.Vl  (16m x 128d, E from registers) ----
#pragma unroll
        for (int kk = 0; kk < 2; kk++) {
            const int kcol = (h32 + kk * 16) * 2;
#pragma unroll
            for (int dh = 0; dh < 2; dh++) {
                uint32_t vv[4][4];
#pragma unroll
                for (int nd = 0; nd < 4; nd++)
                    ldsm4(sb + kb0 + B_VH + (dh * 64 + nd * 16 + b_row) * VROW + kcol + b_off,
                          vv[nd]);
#pragma unroll
                for (int nd = 0; nd < 4; nd++)
#pragma unroll
                    for (int t = 0; t < 2; t++) {
                        float* o = oc[dh * 8 + nd * 2 + t];
                        mma16816(o, ehf[kk], vv[nd][t * 2], vv[nd][t * 2 + 1]);
                        mma16816(o, elf[kk], vv[nd][t * 2], vv[nd][t * 2 + 1]);
                    }
#pragma unroll
                for (int nd = 0; nd < 4; nd++)
                    ldsm4(sb + kb0 + B_VL + (dh * 64 + nd * 16 + b_row) * VROW + kcol + b_off,
                          vv[nd]);
#pragma unroll
                for (int nd = 0; nd < 4; nd++)
#pragma unroll
                    for (int t = 0; t < 2; t++)
                        mma16816(oc[dh * 8 + nd * 2 + t], ehf[kk],
                                 vv[nd][t * 2], vv[nd][t * 2 + 1]);
            }
        }
    }

    // ---- epilogue: sum key-half partners via smem, normalize, write ----
    __syncthreads();
    float* Osm = (float*)smem;   // [128][133] f32 = 68,096 B, reuses Q region
    const int r = m0 + (lane >> 2);
    if (warp < 8) {
#pragma unroll
        for (int n = 0; n < 16; n++) {
            int d = n * 8 + 2 * (lane & 3);
            Osm[r * 133 + d]           = oc[n][0];
            Osm[r * 133 + d + 1]       = oc[n][1];
            Osm[(r + 8) * 133 + d]     = oc[n][2];
            Osm[(r + 8) * 133 + d + 1] = oc[n][3];
        }
    }
    __syncthreads();
    if (warp >= 8) {
#pragma unroll
        for (int n = 0; n < 16; n++) {
            int d = n * 8 + 2 * (lane & 3);
            Osm[r * 133 + d]           += oc[n][0];
            Osm[r * 133 + d + 1]       += oc[n][1];
            Osm[(r + 8) * 133 + d]     += oc[n][2];
            Osm[(r + 8) * 133 + d + 1] += oc[n][3];
        }
    }
    __syncthreads();

    // row m -> global query g = tile*128 + m -> (b, p); out[b][kc][d*196+p]
    for (int idx = tid; idx < 128 * 128; idx += 512) {
        int d = idx >> 7, m = idx & 127;
        int g = tile * 128 + m;
        int bb = g / PPIX, p = g - bb * PPIX;
        out[((bb * KCLS + kc) * DDIM + d) * PPIX + p] = Osm[m * 133 + d] / dsumf[m];
    }
}

// ---------------------------------------------------------------------------
// kernel_launch
// ---------------------------------------------------------------------------
extern "C" void kernel_launch(void* const* d_in, const int* in_sizes, int n_in,
                              void* d_out, int out_size)
{
    const float* supp = (const float*)d_in[0];
    const float* qry  = (const float*)d_in[1];
    const float* Wqk  = (const float*)d_in[3];
    const float* Wv   = (const float*)d_in[4];
    float* out = (float*)d_out;

    cudaFuncSetAttribute(projmma_kernel,
                         cudaFuncAttributeMaxDynamicSharedMemorySize, PROJ_SMEM);
    cudaFuncSetAttribute(attn_kernel,
                         cudaFuncAttributeMaxDynamicSharedMemorySize, ATT_SMEM);

    xsplit_kernel<<<dim3(8, 7, NSUP + BQ + 1), 256>>>(supp, qry, Wqk, Wv);
    projmma_kernel<<<dim3(NMT, 2), 256, PROJ_SMEM>>>(out + OUT1);
    attn_kernel<<<dim3(NTILE, KCLS), 512, ATT_SMEM>>>(out);
}

// round 17
// speedup vs baseline: 5.2651x; 1.0387x over previous
#include <cuda_runtime.h>
#include <cuda_bf16.h>
#include <cstdint>
#include <math.h>

// ---------------------------------------------------------------------------
// Problem constants
// ---------------------------------------------------------------------------
#define BQ 32
#define NSUP 25
#define KCLS 5
#define CIN 512
#define PPIX 196
#define DDIM 128
#define KEYS 980
#define OUT1 (BQ * KCLS * DDIM * PPIX)
#define MTOT (BQ * PPIX)          // 6272 flattened queries
#define NTILE 49                  // 6272 / 128 dense m-tiles (attention)
#define KROWS (NSUP * PPIX + 64)  // K rows padded so last chunk never faults
#define GROWS 11200               // 175 x 64 dense proj rows (28 dead in middle)
#define GQBASE 4928               // queries start row (supports [0,4900))
#define NMT 175

// bf16 hi/lo split scratch (device globals — zero-initialized, no alloc)
__device__ __align__(16) __nv_bfloat16 g_xh[GROWS * CIN];          // [g][c]
__device__ __align__(16) __nv_bfloat16 g_xl[GROWS * CIN];
__device__ __align__(16) __nv_bfloat16 g_wh[2 * DDIM * CIN];       // [qv][d][c]
__device__ __align__(16) __nv_bfloat16 g_wl[2 * DDIM * CIN];
__device__ __align__(16) __nv_bfloat16 g_qh[MTOT * DDIM];          // [g][d]
__device__ __align__(16) __nv_bfloat16 g_ql[MTOT * DDIM];
__device__ __align__(16) __nv_bfloat16 g_kh[KROWS * DDIM];         // [gkey][d]
__device__ __align__(16) __nv_bfloat16 g_kl[KROWS * DDIM];
__device__ __align__(16) __nv_bfloat16 g_vth[KCLS * DDIM * 1024];  // [kc][d][slot]
__device__ __align__(16) __nv_bfloat16 g_vtl[KCLS * DDIM * 1024];  // pads stay 0

// ---------------------------------------------------------------------------
// PTX helpers (baseline PTX, legal on plain sm_103)
// ---------------------------------------------------------------------------
__device__ __forceinline__ void ldsm4(uint32_t addr, uint32_t r[4]) {
    asm volatile("ldmatrix.sync.aligned.m8n8.x4.shared.b16 {%0,%1,%2,%3}, [%4];"
                 : "=r"(r[0]), "=r"(r[1]), "=r"(r[2]), "=r"(r[3]) : "r"(addr));
}
__device__ __forceinline__ void mma16816(float c[4], const uint32_t a[4],
                                         uint32_t b0, uint32_t b1) {
    asm volatile("mma.sync.aligned.m16n8k16.row.col.f32.bf16.bf16.f32 "
                 "{%0,%1,%2,%3}, {%4,%5,%6,%7}, {%8,%9}, {%0,%1,%2,%3};"
                 : "+f"(c[0]), "+f"(c[1]), "+f"(c[2]), "+f"(c[3])
                 : "r"(a[0]), "r"(a[1]), "r"(a[2]), "r"(a[3]), "r"(b0), "r"(b1));
}
__device__ __forceinline__ uint32_t smem_u32(const void* p) {
    uint32_t a;
    asm("{ .reg .u64 t; cvta.to.shared.u64 t, %1; cvt.u32.u64 %0, t; }"
        : "=r"(a) : "l"(p));
    return a;
}
__device__ __forceinline__ uint32_t packbf(float e0, float e1) {
    uint32_t r;   // lower half = e0
    asm("cvt.rn.bf16x2.f32 %0, %1, %2;" : "=r"(r) : "f"(e1), "f"(e0));
    return r;
}
#define CPA16(dst, src) \
    asm volatile("cp.async.ca.shared.global [%0], [%1], 16;" \
                 :: "r"(dst), "l"(src))
#define CPA_COMMIT() asm volatile("cp.async.commit_group;" ::: "memory")
#define CPA_WAIT0()  asm volatile("cp.async.wait_group 0;" ::: "memory")

// ---------------------------------------------------------------------------
// xsplit (+ folded wsplit): features [img][c][p] f32 -> dense transposed
// bf16 hi/lo [g][c]. Larger tiles (128 channels) for deeper per-thread MLP:
// grid = (4 c-tiles of 128, 7 p-tiles of 28, 58); z=57 slices split W.
// float4 global reads, packed bf16x2 stores.
// ---------------------------------------------------------------------------
__global__ __launch_bounds__(256) void xsplit_kernel(
    const float* __restrict__ supp, const float* __restrict__ qry,
    const float* __restrict__ Wq, const float* __restrict__ Wv)
{
    __shared__ float xs[128][29];
    const int tid = threadIdx.x;
    const int img = blockIdx.z;

    if (img == NSUP + BQ) {
        // W split: 2 x 128 x 512 = 131072 elements, grid-stride over 28 blocks
        const int blk = blockIdx.x * 7 + blockIdx.y;   // 0..27
        for (int e = blk * 256 + tid; e < 2 * DDIM * CIN; e += 28 * 256) {
            int qv = e >> 16;
            int rem = e & 65535;
            float v = (qv ? Wv : Wq)[rem];
            __nv_bfloat16 h = __float2bfloat16(v);
            g_wh[e] = h;
            g_wl[e] = __float2bfloat16(v - __bfloat162float(h));
        }
        return;
    }

    const float* x = (img < NSUP) ? supp + (size_t)img * CIN * PPIX
                                  : qry + (size_t)(img - NSUP) * CIN * PPIX;
    const int c0 = blockIdx.x * 128, p0 = blockIdx.y * 28;

    // Phase 1: float4 loads, 128 rows x 7 float4 = 896 vectors
    for (int idx = tid; idx < 128 * 7; idx += 256) {
        int c = idx / 7, q4 = idx - c * 7;
        float4 v = *(const float4*)(x + (size_t)(c0 + c) * PPIX + p0 + q4 * 4);
        xs[c][q4 * 4]     = v.x;
        xs[c][q4 * 4 + 1] = v.y;
        xs[c][q4 * 4 + 2] = v.z;
        xs[c][q4 * 4 + 3] = v.w;
    }
    __syncthreads();

    // Phase 2: transpose + split + packed stores (2 channels / 32-bit word)
    const size_t gbase = (img < NSUP) ? (size_t)img * PPIX + p0
                                      : (size_t)GQBASE + (img - NSUP) * PPIX + p0;
    uint32_t* xh32 = (uint32_t*)g_xh;
    uint32_t* xl32 = (uint32_t*)g_xl;
    for (int idx = tid; idx < 28 * 64; idx += 256) {
        int p = idx >> 6, cp = idx & 63;       // cp = channel pair (of 128)
        float v0 = xs[2 * cp][p];
        float v1 = xs[2 * cp + 1][p];
        float h0 = __bfloat162float(__float2bfloat16(v0));
        float h1 = __bfloat162float(__float2bfloat16(v1));
        size_t o = ((gbase + p) * CIN + c0) / 2 + cp;
        xh32[o] = packbf(h0, h1);
        xl32[o] = packbf(v0 - h0, v1 - h1);
    }
}

// ---------------------------------------------------------------------------
// projmma: out[g][d] = sum_c x[g][c] * W[d][c], 3-split bf16 HMMA.
// Single-buffered synchronous staging (proven R14 code), but 3 CTAs/SM:
// 350 CTAs / 444 resident slots = 0.79 waves — all CTAs resident, staging
// exposure hidden by co-resident CTAs, no tail quantization.
// grid = (175 m-tiles of 64, 2 {qk,v}). block 256.
// ---------------------------------------------------------------------------
#define AROW 144
#define P_AH 0
#define P_AL (64 * AROW)
#define P_WH (2 * 64 * AROW)
#define P_WL (P_WH + 128 * AROW)
#define PROJ_SMEM (P_WL + 128 * AROW)   // 55296

__global__ __launch_bounds__(256, 3) void projmma_kernel(float* __restrict__ outv)
{
    extern __shared__ char smem[];
    const uint32_t sb = smem_u32(smem);
    const int tid = threadIdx.x;
    const int lane = tid & 31;
    const int warp = tid >> 5;
    const int tile = blockIdx.x, qv = blockIdx.y;

    const int m0 = (warp & 3) * 16;
    const int n0 = (warp >> 2) * 64;

    const int a_row = lane & 15;
    const int a_off = (lane >> 4) << 4;
    const int b_row = (lane & 7) | ((lane >> 4) << 3);
    const int b_off = ((lane >> 3) & 1) << 4;

    float oc[8][4];
#pragma unroll
    for (int n = 0; n < 8; n++)
#pragma unroll
        for (int q = 0; q < 4; q++) oc[n][q] = 0.f;

    const char* xh8 = (const char*)(g_xh + (size_t)tile * 64 * CIN);
    const char* xl8 = (const char*)(g_xl + (size_t)tile * 64 * CIN);
    const char* wh8 = (const char*)(g_wh + (size_t)qv * DDIM * CIN);
    const char* wl8 = (const char*)(g_wl + (size_t)qv * DDIM * CIN);

    for (int ch = 0; ch < 8; ch++) {
        __syncthreads();
        for (int idx = tid; idx < 64 * 8; idx += 256) {
            int r = idx >> 3, seg = idx & 7;
            size_t so = (size_t)r * 1024 + ch * 128 + seg * 16;
            CPA16(sb + P_AH + r * AROW + seg * 16, xh8 + so);
            CPA16(sb + P_AL + r * AROW + seg * 16, xl8 + so);
        }
        for (int idx = tid; idx < 128 * 8; idx += 256) {
            int n = idx >> 3, seg = idx & 7;
            size_t so = (size_t)n * 1024 + ch * 128 + seg * 16;
            CPA16(sb + P_WH + n * AROW + seg * 16, wh8 + so);
            CPA16(sb + P_WL + n * AROW + seg * 16, wl8 + so);
        }
        CPA_COMMIT();
        CPA_WAIT0();
        __syncthreads();

#pragma unroll
        for (int ks = 0; ks < 4; ks++) {
            const int kb = ks * 32;
            uint32_t ah[4], al[4];
            uint32_t ra = sb + P_AH + (m0 + a_row) * AROW + kb + a_off;
            ldsm4(ra, ah);
            ldsm4(ra + (P_AL - P_AH), al);
#pragma unroll
            for (int nt = 0; nt < 4; nt++) {
                uint32_t bh[4], bl[4];
                uint32_t rb = sb + P_WH + (n0 + nt * 16 + b_row) * AROW + kb + b_off;
                ldsm4(rb, bh);
                ldsm4(rb + (P_WL - P_WH), bl);
#pragma unroll
                for (int t = 0; t < 2; t++) {
                    float* o = oc[nt * 2 + t];
                    mma16816(o, ah, bh[t * 2], bh[t * 2 + 1]);
                    mma16816(o, ah, bl[t * 2], bl[t * 2 + 1]);
                    mma16816(o, al, bh[t * 2], bh[t * 2 + 1]);
                }
            }
        }
    }

    const int gbase = tile * 64;
    if (qv == 0) {
        uint32_t* kh32 = (uint32_t*)g_kh;
        uint32_t* kl32 = (uint32_t*)g_kl;
        uint32_t* qh32 = (uint32_t*)g_qh;
        uint32_t* ql32 = (uint32_t*)g_ql;
        const int r1 = m0 + (lane >> 2);
#pragma unroll
        for (int nt = 0; nt < 8; nt++) {
            const int d = n0 + nt * 8 + 2 * (lane & 3);
#pragma unroll
            for (int half = 0; half < 2; half++) {
                int g = gbase + r1 + half * 8;
                float c0 = oc[nt][half * 2], c1 = oc[nt][half * 2 + 1];
                float h0 = __bfloat162float(__float2bfloat16(c0));
                float h1 = __bfloat162float(__float2bfloat16(c1));
                uint32_t ph = packbf(h0, h1);
                uint32_t pl = packbf(c0 - h0, c1 - h1);
                if (g < NSUP * PPIX) {
                    int o = (g * DDIM + d) >> 1;
                    kh32[o] = ph;
                    kl32[o] = pl;
                } else if (g >= GQBASE) {
                    int o = ((g - GQBASE) * DDIM + d) >> 1;
                    qh32[o] = ph;
                    ql32[o] = pl;
                }
            }
        }
    } else {
        __syncthreads();
        float* Osm = (float*)smem;   // [64][133]
        const int r = m0 + (lane >> 2);
#pragma unroll
        for (int nt = 0; nt < 8; nt++) {
            const int d = n0 + nt * 8 + 2 * (lane & 3);
            Osm[r * 133 + d]           = oc[nt][0];
            Osm[r * 133 + d + 1]       = oc[nt][1];
            Osm[(r + 8) * 133 + d]     = oc[nt][2];
            Osm[(r + 8) * 133 + d + 1] = oc[nt][3];
        }
        __syncthreads();
        for (int idx = tid; idx < 128 * 64; idx += 256) {
            int d = idx >> 6, m = idx & 63;
            int g = gbase + m;
            float v = Osm[m * 133 + d];
            if (g < NSUP * PPIX) {
                int img = g / PPIX, p = g - img * PPIX;
                int cls = img / 5, s = img - cls * 5;
                __nv_bfloat16 h = __float2bfloat16(v);
                size_t o = ((size_t)cls * DDIM + d) * 1024 + s * PPIX + p;
                g_vth[o] = h;
                g_vtl[o] = __float2bfloat16(v - __bfloat162float(h));
            } else if (g >= GQBASE) {
                int qi = g - GQBASE;
                int img = qi / PPIX, p = qi - img * PPIX;
                outv[((size_t)img * DDIM + d) * PPIX + p] = v;
            }
        }
    }
}

// ---------------------------------------------------------------------------
// FlashAttention-style mma.sync attention (UNCHANGED from R14 — proven).
// M=128 per CTA, 512 threads, 1 CTA/SM, K/V double-buffered.
// grid = (49 dense m-tiles of 128, 5 classes) = 245 CTAs.
// ---------------------------------------------------------------------------
#define NCHUNK 16
#define QROW 272            // 128 bf16 + 16B pad
#define VROW 144            // 64 bf16 + 16B pad
#define OFF_QH 0
#define OFF_QL 34816
#define OFF_BUF0 69632      // double-buffered region: [KH KL VH VL] x 2
#define BUFSTR 71680
#define B_KH 0
#define B_KL 17408
#define B_VH 34816
#define B_VL 53248
#define OFF_DS (OFF_BUF0 + 2 * BUFSTR + 128)   // 213120
#define ATT_SMEM (OFF_DS + 512)                // 213632

__global__ __launch_bounds__(512, 1) void attn_kernel(float* __restrict__ out)
{
    extern __shared__ char smem[];
    const uint32_t sb = smem_u32(smem);
    float* dsumf = (float*)(smem + OFF_DS);

    const int tid = threadIdx.x;
    const int lane = tid & 31;
    const int warp = tid >> 5;
    const int tile = blockIdx.x, kc = blockIdx.y;

    const int m0 = (warp & 7) * 16;      // warp m base (0..112)
    const int h32 = (warp >> 3) * 32;    // warp key-half base within chunk

    const int a_row = lane & 15;
    const int a_off = (lane >> 4) << 4;
    const int b_row = (lane & 7) | ((lane >> 4) << 3);
    const int b_off = ((lane >> 3) & 1) << 4;

    const char* kh8 = (const char*)(g_kh + (size_t)kc * KEYS * DDIM);
    const char* kl8 = (const char*)(g_kl + (size_t)kc * KEYS * DDIM);
    const char* vh8 = (const char*)(g_vth + (size_t)kc * DDIM * 1024);
    const char* vl8 = (const char*)(g_vtl + (size_t)kc * DDIM * 1024);

    // ---- prologue: stage Q + chunk 0 K/V into buf0 (one group) ----
    {
        const char* qh8 = (const char*)(g_qh + (size_t)tile * 128 * DDIM);
        const char* ql8 = (const char*)(g_ql + (size_t)tile * 128 * DDIM);
        for (int idx = tid; idx < 128 * 16; idx += 512) {
            int r = idx >> 4, seg = idx & 15;
            CPA16(sb + OFF_QH + r * QROW + seg * 16, qh8 + r * 256 + seg * 16);
            CPA16(sb + OFF_QL + r * QROW + seg * 16, ql8 + r * 256 + seg * 16);
        }
        for (int idx = tid; idx < 64 * 16; idx += 512) {
            int j = idx >> 4, seg = idx & 15;
            const size_t so = (size_t)j * 256 + seg * 16;
            CPA16(sb + OFF_BUF0 + B_KH + j * QROW + seg * 16, kh8 + so);
            CPA16(sb + OFF_BUF0 + B_KL + j * QROW + seg * 16, kl8 + so);
        }
        for (int idx = tid; idx < 128 * 8; idx += 512) {
            int d = idx >> 3, seg = idx & 7;
            const size_t so = (size_t)d * 2048 + seg * 16;
            CPA16(sb + OFF_BUF0 + B_VH + d * VROW + seg * 16, vh8 + so);
            CPA16(sb + OFF_BUF0 + B_VL + d * VROW + seg * 16, vl8 + so);
        }
        CPA_COMMIT();
    }
    if (tid < 128) dsumf[tid] = 0.f;

    // O accumulators: [16m x 128d] per warp (16 n-tiles x 4 regs)
    float oc[16][4];
#pragma unroll
    for (int n = 0; n < 16; n++)
#pragma unroll
        for (int q = 0; q < 4; q++) oc[n][q] = 0.f;

    for (int ch = 0; ch < NCHUNK; ch++) {
        CPA_WAIT0();       // all staged data (incl. this chunk's) complete
        __syncthreads();   // visible to all; prior chunk's reads also done

        const uint32_t kb0 = OFF_BUF0 + (ch & 1) * BUFSTR;

        // ---- S = Qh.Kh^T + Qh.Kl^T + Ql.Kh^T  (16m x 32j per warp) ----
        float sc[4][4];
#pragma unroll
        for (int n = 0; n < 4; n++)
#pragma unroll
            for (int q = 0; q < 4; q++) sc[n][q] = 0.f;

#pragma unroll
        for (int k = 0; k < 8; k++) {
            const int kb = k * 32;
            uint32_t ah[4], al[4], bh0[4], bh1[4], bl0[4], bl1[4];
            uint32_t ra = sb + OFF_QH + (m0 + a_row) * QROW + kb + a_off;
            ldsm4(ra, ah);
            ldsm4(ra + (OFF_QL - OFF_QH), al);
            uint32_t rb = sb + kb0 + B_KH + (h32 + b_row) * QROW + kb + b_off;
            ldsm4(rb, bh0);
            ldsm4(rb + 16 * QROW, bh1);
            ldsm4(rb + (B_KL - B_KH), bl0);
            ldsm4(rb + (B_KL - B_KH) + 16 * QROW, bl1);
#pragma unroll
            for (int n = 0; n < 4; n++) {
                uint32_t h0 = (n < 2) ? bh0[(n & 1) * 2] : bh1[(n & 1) * 2];
                uint32_t h1 = (n < 2) ? bh0[(n & 1) * 2 + 1] : bh1[(n & 1) * 2 + 1];
                uint32_t l0 = (n < 2) ? bl0[(n & 1) * 2] : bl1[(n & 1) * 2];
                uint32_t l1 = (n < 2) ? bl0[(n & 1) * 2 + 1] : bl1[(n & 1) * 2 + 1];
                mma16816(sc[n], ah, h0, h1);
                mma16816(sc[n], ah, l0, l1);
                mma16816(sc[n], al, h0, h1);
            }
        }

        // ---- exp (exact key mask) -> row sums -> E A-frags in registers ----
        uint32_t ehf[2][4], elf[2][4];
        {
            float rs0 = 0.f, rs1 = 0.f;
            const int r = m0 + (lane >> 2);
#pragma unroll
            for (int n = 0; n < 4; n++) {
                int jg = ch * 64 + h32 + n * 8 + 2 * (lane & 3);
                float e0 = (jg     < KEYS) ? __expf(sc[n][0]) : 0.f;
                float e1 = (jg + 1 < KEYS) ? __expf(sc[n][1]) : 0.f;
                float e2 = (jg     < KEYS) ? __expf(sc[n][2]) : 0.f;
                float e3 = (jg + 1 < KEYS) ? __expf(sc[n][3]) : 0.f;
                rs0 += e0 + e1;
                rs1 += e2 + e3;
                float h0 = __bfloat162float(__float2bfloat16(e0));
                float h1 = __bfloat162float(__float2bfloat16(e1));
                float h2 = __bfloat162float(__float2bfloat16(e2));
                float h3 = __bfloat162float(__float2bfloat16(e3));
                ehf[n >> 1][(n & 1) * 2]     = packbf(h0, h1);
                ehf[n >> 1][(n & 1) * 2 + 1] = packbf(h2, h3);
                elf[n >> 1][(n & 1) * 2]     = packbf(e0 - h0, e1 - h1);
                elf[n >> 1][(n & 1) * 2 + 1] = packbf(e2 - h2, e3 - h3);
            }
            rs0 += __shfl_xor_sync(0xFFFFFFFFu, rs0, 1);
            rs0 += __shfl_xor_sync(0xFFFFFFFFu, rs0, 2);
            rs1 += __shfl_xor_sync(0xFFFFFFFFu, rs1, 1);
            rs1 += __shfl_xor_sync(0xFFFFFFFFu, rs1, 2);
            if ((lane & 3) == 0) {
                atomicAdd(&dsumf[r], rs0);
                atomicAdd(&dsumf[r + 8], rs1);
            }
        }

        // ---- prefetch chunk ch+1 into the other buffer (overlaps PV) ----
        if (ch + 1 < NCHUNK) {
            const uint32_t nb = sb + OFF_BUF0 + ((ch + 1) & 1) * BUFSTR;
            for (int idx = tid; idx < 64 * 16; idx += 512) {
                int j = idx >> 4, seg = idx & 15;
                const size_t so = (size_t)((ch + 1) * 64 + j) * 256 + seg * 16;
                CPA16(nb + B_KH + j * QROW + seg * 16, kh8 + so);
                CPA16(nb + B_KL + j * QROW + seg * 16, kl8 + so);
            }
            for (int idx = tid; idx < 128 * 8; idx += 512) {
                int d = idx >> 3, seg = idx & 7;
                const size_t so = (size_t)d * 2048 + (ch + 1) * 128 + seg * 16;
                CPA16(nb + B_VH + d * VROW + seg * 16, vh8 + so);
                CPA16(nb + B_VL + d * VROW + seg * 16, vl8 + so);
            }
            CPA_COMMIT();
        }

        // ---- O += Eh.Vh + El.Vh + Eh.Vl  (16m x 128d, E from registers) ----
#pragma unroll
        for (int kk = 0; kk < 2; kk++) {
            const int kcol = (h32 + kk * 16) * 2;
#pragma unroll
            for (int dh = 0; dh < 2; dh++) {
                uint32_t vv[4][4];
#pragma unroll
                for (int nd = 0; nd < 4; nd++)
                    ldsm4(sb + kb0 + B_VH + (dh * 64 + nd * 16 + b_row) * VROW + kcol + b_off,
                          vv[nd]);
#pragma unroll
                for (int nd = 0; nd < 4; nd++)
#pragma unroll
                    for (int t = 0; t < 2; t++) {
                        float* o = oc[dh * 8 + nd * 2 + t];
                        mma16816(o, ehf[kk], vv[nd][t * 2], vv[nd][t * 2 + 1]);
                        mma16816(o, elf[kk], vv[nd][t * 2], vv[nd][t * 2 + 1]);
                    }
#pragma unroll
                for (int nd = 0; nd < 4; nd++)
                    ldsm4(sb + kb0 + B_VL + (dh * 64 + nd * 16 + b_row) * VROW + kcol + b_off,
                          vv[nd]);
#pragma unroll
                for (int nd = 0; nd < 4; nd++)
#pragma unroll
                    for (int t = 0; t < 2; t++)
                        mma16816(oc[dh * 8 + nd * 2 + t], ehf[kk],
                                 vv[nd][t * 2], vv[nd][t * 2 + 1]);
            }
        }
    }

    // ---- epilogue: sum key-half partners via smem, normalize, write ----
    __syncthreads();
    float* Osm = (float*)smem;   // [128][133] f32 = 68,096 B, reuses Q region
    const int r = m0 + (lane >> 2);
    if (warp < 8) {
#pragma unroll
        for (int n = 0; n < 16; n++) {
            int d = n * 8 + 2 * (lane & 3);
            Osm[r * 133 + d]           = oc[n][0];
            Osm[r * 133 + d + 1]       = oc[n][1];
            Osm[(r + 8) * 133 + d]     = oc[n][2];
            Osm[(r + 8) * 133 + d + 1] = oc[n][3];
        }
    }
    __syncthreads();
    if (warp >= 8) {
#pragma unroll
        for (int n = 0; n < 16; n++) {
            int d = n * 8 + 2 * (lane & 3);
            Osm[r * 133 + d]           += oc[n][0];
            Osm[r * 133 + d + 1]       += oc[n][1];
            Osm[(r + 8) * 133 + d]     += oc[n][2];
            Osm[(r + 8) * 133 + d + 1] += oc[n][3];
        }
    }
    __syncthreads();

    // row m -> global query g = tile*128 + m -> (b, p); out[b][kc][d*196+p]
    for (int idx = tid; idx < 128 * 128; idx += 512) {
        int d = idx >> 7, m = idx & 127;
        int g = tile * 128 + m;
        int bb = g / PPIX, p = g - bb * PPIX;
        out[((bb * KCLS + kc) * DDIM + d) * PPIX + p] = Osm[m * 133 + d] / dsumf[m];
    }
}

// ---------------------------------------------------------------------------
// kernel_launch
// ---------------------------------------------------------------------------
extern "C" void kernel_launch(void* const* d_in, const int* in_sizes, int n_in,
                              void* d_out, int out_size)
{
    const float* supp = (const float*)d_in[0];
    const float* qry  = (const float*)d_in[1];
    const float* Wqk  = (const float*)d_in[3];
    const float* Wv   = (const float*)d_in[4];
    float* out = (float*)d_out;

    cudaFuncSetAttribute(projmma_kernel,
                         cudaFuncAttributeMaxDynamicSharedMemorySize, PROJ_SMEM);
    cudaFuncSetAttribute(attn_kernel,
                         cudaFuncAttributeMaxDynamicSharedMemorySize, ATT_SMEM);

    xsplit_kernel<<<dim3(4, 7, NSUP + BQ + 1), 256>>>(supp, qry, Wqk, Wv);
    projmma_kernel<<<dim3(NMT, 2), 256, PROJ_SMEM>>>(out + OUT1);
    attn_kernel<<<dim3(NTILE, KCLS), 512, ATT_SMEM>>>(out);
}